// round 9
// baseline (speedup 1.0000x reference)
#include <cuda_runtime.h>
#include <cuda_bf16.h>
#include <math.h>
#include <cstdint>

// ---------------- problem constants ----------------
#define NTOK 32768
#define CDIM 256
#define NHD  8
#define HD   32
#define AGN  64
#define PVOL (34*34*34)
#define KCONV (27*256)

// ---------------- scratch (device globals) ----------------
__device__ float g_lin[NTOK * 768];
__device__ float g_A[AGN * CDIM];
__device__ float g_avpart[64 * NHD * AGN * HD];
__device__ float g_partl[64 * NHD * AGN];
__device__ float g_av[NHD * AGN * HD];
__device__ float g_mid[NTOK * CDIM];
__device__ float g_conv[NTOK * CDIM];
__device__ __nv_bfloat16 g_xhi[NTOK * CDIM], g_xlo[NTOK * CDIM];
__device__ __nv_bfloat16 g_vph[PVOL * CDIM], g_vpl[PVOL * CDIM];
__device__ __nv_bfloat16 g_wqh[768 * 256], g_wql[768 * 256];
__device__ __nv_bfloat16 g_wph[256 * 256], g_wpl[256 * 256];
__device__ __nv_bfloat16 g_wch[256 * KCONV], g_wcl[256 * KCONV];

// ---------------- fast exp ----------------
__device__ __forceinline__ float fexp(float x) {
    float t = x * 1.4426950408889634f;
    int e = __float2int_rn(t);
    float f = t - (float)e;
    float p = 1.3333558e-3f;
    p = fmaf(p, f, 9.6181291e-3f);
    p = fmaf(p, f, 5.5504109e-2f);
    p = fmaf(p, f, 2.4022651e-1f);
    p = fmaf(p, f, 6.9314718e-1f);
    p = fmaf(p, f, 1.0f);
    return __int_as_float(__float_as_int(p) + (e << 23));
}

// ---------------- asm helpers ----------------
__device__ __forceinline__ uint32_t smem_u32(const void* p) {
    uint32_t a;
    asm("{ .reg .u64 t; cvta.to.shared.u64 t, %1; cvt.u32.u64 %0, t; }" : "=r"(a) : "l"(p));
    return a;
}
#define CP16(dst, src) \
    asm volatile("cp.async.cg.shared.global [%0], [%1], 16;" :: "r"(dst), "l"(src))
#define CP_COMMIT() asm volatile("cp.async.commit_group;")
#define CP_WAIT1()  asm volatile("cp.async.wait_group 1;")
#define CP_WAIT0()  asm volatile("cp.async.wait_group 0;")

#define LDSM4(r, addr) \
    asm volatile("ldmatrix.sync.aligned.m8n8.x4.shared.b16 {%0,%1,%2,%3}, [%4];" \
        : "=r"((r)[0]), "=r"((r)[1]), "=r"((r)[2]), "=r"((r)[3]) : "r"(addr))

#define MMA16816(d, a, b0v, b1v) \
    asm volatile("mma.sync.aligned.m16n8k16.row.col.f32.bf16.bf16.f32 " \
        "{%0,%1,%2,%3}, {%4,%5,%6,%7}, {%8,%9}, {%0,%1,%2,%3};" \
        : "+f"((d)[0]), "+f"((d)[1]), "+f"((d)[2]), "+f"((d)[3]) \
        : "r"((a)[0]), "r"((a)[1]), "r"((a)[2]), "r"((a)[3]), "r"(b0v), "r"(b1v))

#define SW(o) ((o) ^ (((o) >> 3) & 0x70))

// ---------------- conversion kernels ----------------
__global__ void k_split(const float* __restrict__ x, __nv_bfloat16* __restrict__ hi,
                        __nv_bfloat16* __restrict__ lo, int n) {
    int i = blockIdx.x * 256 + threadIdx.x;
    if (i < n) {
        float v = x[i];
        __nv_bfloat16 h = __float2bfloat16(v);
        hi[i] = h;
        lo[i] = __float2bfloat16(v - __bfloat162float(h));
    }
}
__global__ void k_wconv(const float* __restrict__ w, __nv_bfloat16* __restrict__ hi,
                        __nv_bfloat16* __restrict__ lo) {
    int i = blockIdx.x * 256 + threadIdx.x;     // 27*256*256
    int co = i / KCONV;
    int rem = i - co * KCONV;
    int tap = rem >> 8, ci = rem & 255;
    float v = w[(co * 256 + ci) * 27 + tap];
    __nv_bfloat16 h = __float2bfloat16(v);
    hi[i] = h;
    lo[i] = __float2bfloat16(v - __bfloat162float(h));
}
__global__ void k_zero_b(uint32_t* __restrict__ p, int n) {
    int i = blockIdx.x * 256 + threadIdx.x;
    if (i < n) p[i] = 0u;
}
__global__ void k_vpadsplit(const float* __restrict__ lin, __nv_bfloat16* __restrict__ hi,
                            __nv_bfloat16* __restrict__ lo) {
    const int n = blockIdx.x;
    const int c4 = threadIdx.x;     // 64
    const int x = n >> 10, y = (n >> 5) & 31, z = n & 31;
    const int p = ((x + 1) * 34 + (y + 1)) * 34 + (z + 1);
    float4 v = *(const float4*)&lin[(size_t)n * 768 + 512 + c4 * 4];
    size_t o = (size_t)p * 256 + c4 * 4;
    float a[4] = {v.x, v.y, v.z, v.w};
#pragma unroll
    for (int j = 0; j < 4; j++) {
        __nv_bfloat16 h = __float2bfloat16(a[j]);
        hi[o + j] = h;
        lo[o + j] = __float2bfloat16(a[j] - __bfloat162float(h));
    }
}

// ---------------- HMMA split-bf16 GEMM: swizzled, 3-stage ----------------
#define TIL 8192
#define BUF 32768
#define SMEM_TOT (3 * BUF)

__global__ void __launch_bounds__(256, 2) gemm_mma(
    const __nv_bfloat16* __restrict__ Ahi, const __nv_bfloat16* __restrict__ Alo,
    const __nv_bfloat16* __restrict__ Bhi, const __nv_bfloat16* __restrict__ Blo,
    const float* __restrict__ bias, float* __restrict__ C,
    int K, int ldc, int mode)
{
    extern __shared__ char smem[];
    const uint32_t sb = smem_u32(smem);
    const int t = threadIdx.x;
    const int m0 = blockIdx.y * 128, n0 = blockIdx.x * 128;
    const int seg = t & 3, r0 = t >> 2;
    const int wid = t >> 5, lane = t & 31;
    const int wy = wid >> 1, wx = wid & 1;
    const int lA_r = lane & 15, lA_k8 = (lane >> 4) & 1;
    const int lB_n = (lane & 7) + ((lane >> 4) & 1) * 8, lB_k8 = (lane >> 3) & 1;
    const int NC = K >> 5;

    float acc[2][8][4];
#pragma unroll
    for (int i = 0; i < 2; i++)
#pragma unroll
        for (int j = 0; j < 8; j++)
#pragma unroll
            for (int q = 0; q < 4; q++) acc[i][j][q] = 0.0f;

    auto prefetch = [&](int c) {
        const uint32_t bb = sb + (c % 3) * BUF;
        const int kc = c * 32;
        int dx = 0, dy = 0, dz = 0;
        const int ci0 = kc & 255;
        if (mode) {
            const int tap = kc >> 8;
            dx = tap / 9 - 1; dy = (tap / 3) % 3 - 1; dz = tap % 3 - 1;
        }
#pragma unroll
        for (int i = 0; i < 2; i++) {
            const int r = r0 + i * 64;
            const uint32_t so = SW(r * 64 + seg * 16);
            size_t aoff;
            if (!mode) {
                aoff = (size_t)(m0 + r) * K + kc + seg * 8;
            } else {
                const int m = m0 + r;
                const int x = m >> 10, y = (m >> 5) & 31, z = m & 31;
                aoff = (size_t)(((x + 1 + dx) * 34 + (y + 1 + dy)) * 34 + (z + 1 + dz)) * 256
                       + ci0 + seg * 8;
            }
            CP16(bb + so, Ahi + aoff);
            CP16(bb + TIL + so, Alo + aoff);
            const size_t boff = (size_t)(n0 + r) * K + kc + seg * 8;
            CP16(bb + 2 * TIL + so, Bhi + boff);
            CP16(bb + 3 * TIL + so, Blo + boff);
        }
        CP_COMMIT();
    };

    prefetch(0);
    prefetch(1);
    for (int c = 0; c < NC; c++) {
        if (c + 1 < NC) CP_WAIT1(); else CP_WAIT0();
        __syncthreads();
        if (c + 2 < NC) prefetch(c + 2);
        const uint32_t bb = sb + (c % 3) * BUF;
#pragma unroll
        for (int ks = 0; ks < 2; ks++) {
            const int chunk = ks * 32 + lA_k8 * 16;
            uint32_t ah[2][4], al[2][4];
#pragma unroll
            for (int mt = 0; mt < 2; mt++) {
                const uint32_t aaddr = bb + SW((wy * 32 + mt * 16 + lA_r) * 64 + chunk);
                LDSM4(ah[mt], aaddr);
                LDSM4(al[mt], aaddr + TIL);
            }
            const int bchunk = ks * 32 + lB_k8 * 16;
            uint32_t bf[4][4];
#pragma unroll
            for (int np = 0; np < 4; np++) {
                const uint32_t baddr = bb + 2 * TIL + SW((wx * 64 + np * 16 + lB_n) * 64 + bchunk);
                LDSM4(bf[np], baddr);
            }
#pragma unroll
            for (int mt = 0; mt < 2; mt++)
#pragma unroll
                for (int nt = 0; nt < 8; nt++) {
                    const uint32_t* bp = &bf[nt >> 1][(nt & 1) * 2];
                    MMA16816(acc[mt][nt], ah[mt], bp[0], bp[1]);
                    MMA16816(acc[mt][nt], al[mt], bp[0], bp[1]);
                }
#pragma unroll
            for (int np = 0; np < 4; np++) {
                const uint32_t baddr = bb + 3 * TIL + SW((wx * 64 + np * 16 + lB_n) * 64 + bchunk);
                LDSM4(bf[np], baddr);
            }
#pragma unroll
            for (int mt = 0; mt < 2; mt++)
#pragma unroll
                for (int nt = 0; nt < 8; nt++) {
                    const uint32_t* bp = &bf[nt >> 1][(nt & 1) * 2];
                    MMA16816(acc[mt][nt], ah[mt], bp[0], bp[1]);
                }
        }
    }

    const int er = lane >> 2, ec = (lane & 3) * 2;
#pragma unroll
    for (int mt = 0; mt < 2; mt++) {
        const int row = m0 + wy * 32 + mt * 16 + er;
#pragma unroll
        for (int nt = 0; nt < 8; nt++) {
            const int col = n0 + wx * 64 + nt * 8 + ec;
            const float b0 = __ldg(&bias[col]), b1 = __ldg(&bias[col + 1]);
            float* cp0 = C + (size_t)row * ldc + col;
            float* cp1 = C + (size_t)(row + 8) * ldc + col;
            cp0[0] = acc[mt][nt][0] + b0;
            cp0[1] = acc[mt][nt][1] + b1;
            cp1[0] = acc[mt][nt][2] + b0;
            cp1[1] = acc[mt][nt][3] + b1;
        }
    }
}

// ---------------- proj GEMM: A = fp32 (mid + convout), split in-kernel ----------------
__global__ void __launch_bounds__(256, 2) gemm_proj(
    const float* __restrict__ A0, const float* __restrict__ A1,
    const __nv_bfloat16* __restrict__ Bhi, const __nv_bfloat16* __restrict__ Blo,
    const float* __restrict__ bias, float* __restrict__ C)
{
    extern __shared__ char smem[];
    const uint32_t sb = smem_u32(smem);
    const int t = threadIdx.x;
    const int m0 = blockIdx.y * 128, n0 = blockIdx.x * 128;
    const int seg = t & 3, r0 = t >> 2;
    const int wid = t >> 5, lane = t & 31;
    const int wy = wid >> 1, wx = wid & 1;
    const int lA_r = lane & 15, lA_k8 = (lane >> 4) & 1;
    const int lB_n = (lane & 7) + ((lane >> 4) & 1) * 8, lB_k8 = (lane >> 3) & 1;
    const int NC = 8;      // K = 256

    float acc[2][8][4];
#pragma unroll
    for (int i = 0; i < 2; i++)
#pragma unroll
        for (int j = 0; j < 8; j++)
#pragma unroll
            for (int q = 0; q < 4; q++) acc[i][j][q] = 0.0f;

    auto prefetch = [&](int c) {
        const uint32_t bb = sb + (c % 3) * BUF;
        const int kc = c * 32;
#pragma unroll
        for (int i = 0; i < 2; i++) {
            const int r = r0 + i * 64;
            const uint32_t so = SW(r * 64 + seg * 16);
            const size_t boff = (size_t)(n0 + r) * 256 + kc + seg * 8;
            CP16(bb + 2 * TIL + so, Bhi + boff);
            CP16(bb + 3 * TIL + so, Blo + boff);
            const size_t aoff = (size_t)(m0 + r) * 256 + kc + seg * 8;
            const float4 p0 = *(const float4*)(A0 + aoff);
            const float4 p1 = *(const float4*)(A1 + aoff);
            const float4 q0 = *(const float4*)(A0 + aoff + 4);
            const float4 q1 = *(const float4*)(A1 + aoff + 4);
            float v[8] = {p0.x + p1.x, p0.y + p1.y, p0.z + p1.z, p0.w + p1.w,
                          q0.x + q1.x, q0.y + q1.y, q0.z + q1.z, q0.w + q1.w};
            uint32_t hw[4], lw[4];
#pragma unroll
            for (int j = 0; j < 4; j++) {
                __nv_bfloat16 h0 = __float2bfloat16(v[2 * j]);
                __nv_bfloat16 h1 = __float2bfloat16(v[2 * j + 1]);
                __nv_bfloat162 hh = __halves2bfloat162(h0, h1);
                hw[j] = *(uint32_t*)&hh;
                __nv_bfloat16 l0 = __float2bfloat16(v[2 * j] - __bfloat162float(h0));
                __nv_bfloat16 l1 = __float2bfloat16(v[2 * j + 1] - __bfloat162float(h1));
                __nv_bfloat162 ll = __halves2bfloat162(l0, l1);
                lw[j] = *(uint32_t*)&ll;
            }
            *(uint4*)(smem + (bb - sb) + so) = make_uint4(hw[0], hw[1], hw[2], hw[3]);
            *(uint4*)(smem + (bb - sb) + TIL + so) = make_uint4(lw[0], lw[1], lw[2], lw[3]);
        }
        CP_COMMIT();
    };

    prefetch(0);
    prefetch(1);
    for (int c = 0; c < NC; c++) {
        if (c + 1 < NC) CP_WAIT1(); else CP_WAIT0();
        __syncthreads();
        if (c + 2 < NC) prefetch(c + 2);
        const uint32_t bb = sb + (c % 3) * BUF;
#pragma unroll
        for (int ks = 0; ks < 2; ks++) {
            const int chunk = ks * 32 + lA_k8 * 16;
            uint32_t ah[2][4], al[2][4];
#pragma unroll
            for (int mt = 0; mt < 2; mt++) {
                const uint32_t aaddr = bb + SW((wy * 32 + mt * 16 + lA_r) * 64 + chunk);
                LDSM4(ah[mt], aaddr);
                LDSM4(al[mt], aaddr + TIL);
            }
            const int bchunk = ks * 32 + lB_k8 * 16;
            uint32_t bf[4][4];
#pragma unroll
            for (int np = 0; np < 4; np++) {
                const uint32_t baddr = bb + 2 * TIL + SW((wx * 64 + np * 16 + lB_n) * 64 + bchunk);
                LDSM4(bf[np], baddr);
            }
#pragma unroll
            for (int mt = 0; mt < 2; mt++)
#pragma unroll
                for (int nt = 0; nt < 8; nt++) {
                    const uint32_t* bp = &bf[nt >> 1][(nt & 1) * 2];
                    MMA16816(acc[mt][nt], ah[mt], bp[0], bp[1]);
                    MMA16816(acc[mt][nt], al[mt], bp[0], bp[1]);
                }
#pragma unroll
            for (int np = 0; np < 4; np++) {
                const uint32_t baddr = bb + 3 * TIL + SW((wx * 64 + np * 16 + lB_n) * 64 + bchunk);
                LDSM4(bf[np], baddr);
            }
#pragma unroll
            for (int mt = 0; mt < 2; mt++)
#pragma unroll
                for (int nt = 0; nt < 8; nt++) {
                    const uint32_t* bp = &bf[nt >> 1][(nt & 1) * 2];
                    MMA16816(acc[mt][nt], ah[mt], bp[0], bp[1]);
                }
        }
    }

    const int er = lane >> 2, ec = (lane & 3) * 2;
#pragma unroll
    for (int mt = 0; mt < 2; mt++) {
        const int row = m0 + wy * 32 + mt * 16 + er;
#pragma unroll
        for (int nt = 0; nt < 8; nt++) {
            const int col = n0 + wx * 64 + nt * 8 + ec;
            const float b0 = __ldg(&bias[col]), b1 = __ldg(&bias[col + 1]);
            float* cp0 = C + (size_t)row * 256 + col;
            float* cp1 = C + (size_t)(row + 8) * 256 + col;
            cp0[0] = acc[mt][nt][0] + b0;
            cp0[1] = acc[mt][nt][1] + b1;
            cp1[0] = acc[mt][nt][2] + b0;
            cp1[1] = acc[mt][nt][3] + b1;
        }
    }
}

// ---------------- attention kernels ----------------
__global__ void k_pool(const float* __restrict__ lin, float* __restrict__ A) {
    const int a = blockIdx.x;
    const int c = threadIdx.x;
    const int p1 = a >> 4, p2 = (a >> 2) & 3, p3 = a & 3;
    const int csub = c >> 5;
    float s = 0.0f;
    for (int b1 = 0; b1 < 8; b1++) {
        const int f1 = p1 * 8 + b1;
        const int ch = (f1 >> 2) * 32 + (c & 31);
        const int nb1 = (f1 & 3) * 8192;
        for (int b2 = 0; b2 < 8; b2++) {
            const int nb2 = nb1 + (p2 * 8 + b2) * 256;
            for (int b3 = 0; b3 < 8; b3++) {
                const int n = nb2 + (p3 * 8 + b3) * 8 + csub;
                s += lin[(size_t)n * 768 + ch];
            }
        }
    }
    A[a * 256 + c] = s * (1.0f / 512.0f);
}

// fused stage 1: partial sumexp + exp(S)@V per 512-token chunk, S never materialized.
// Logits are provably tiny (A is a 512-mean; |s| << 1) so no max subtraction needed.
__global__ void __launch_bounds__(256) k_stage1(const float* __restrict__ lin,
                                                const float* __restrict__ Amat,
                                                float* __restrict__ part,
                                                float* __restrict__ partl) {
    const int h = blockIdx.y;
    const int chunk = blockIdx.x;
    const int n0 = chunk * 512;
    __shared__ float kt[64][40];
    __shared__ float vt[64][40];
    __shared__ float pt[64][65];
    const int tid = threadIdx.x;
    const int a = tid >> 2;
    const int sub4 = tid & 3;           // phase-1 token subgroup / phase-2 dim group
    const float scale = 0.17677669529663687f;

    // A row for this thread's agent -> registers (broadcast across the 4 dup threads)
    float4 Areg[8];
#pragma unroll
    for (int i = 0; i < 8; i++)
        Areg[i] = *(const float4*)&Amat[a * 256 + h * 32 + i * 4];

    float4 acc0 = {0, 0, 0, 0}, acc1 = {0, 0, 0, 0};
    float accl = 0.0f;

    for (int sb = 0; sb < 8; sb++) {
        const int nb = n0 + sb * 64;
        // load k/v tiles (64 tokens x 32 dims)
        for (int e = tid; e < 512; e += 256) {
            const int t = e >> 3, dq = e & 7;
            const float* base = lin + (size_t)(nb + t) * 768 + h * 32 + dq * 4;
            *(float4*)&kt[t][dq * 4] = *(const float4*)(base + 256);
            *(float4*)&vt[t][dq * 4] = *(const float4*)(base + 512);
        }
        __syncthreads();
        // phase 1: p[a][t] = exp(scale * A[a]·k[t]), each dot computed once
#pragma unroll 4
        for (int tt = 0; tt < 16; tt++) {
            const int t = tt * 4 + sub4;
            float s = 0.0f;
#pragma unroll
            for (int i = 0; i < 8; i++) {
                const float4 kv = *(const float4*)&kt[t][i * 4];
                s += Areg[i].x * kv.x + Areg[i].y * kv.y
                   + Areg[i].z * kv.z + Areg[i].w * kv.w;
            }
            pt[a][t] = fexp(s * scale);
        }
        __syncthreads();
        // phase 2: accumulate sum p and p*v
#pragma unroll 8
        for (int t = 0; t < 64; t++) {
            const float p = pt[a][t];
            accl += p;
            const float4 v0 = *(const float4*)&vt[t][sub4 * 8];
            const float4 v1 = *(const float4*)&vt[t][sub4 * 8 + 4];
            acc0.x += p * v0.x; acc0.y += p * v0.y; acc0.z += p * v0.z; acc0.w += p * v0.w;
            acc1.x += p * v1.x; acc1.y += p * v1.y; acc1.z += p * v1.z; acc1.w += p * v1.w;
        }
        __syncthreads();
    }
    float* pp = part + (size_t)((chunk * 8 + h) * 64 + a) * 32 + sub4 * 8;
    *(float4*)pp = acc0;
    *(float4*)(pp + 4) = acc1;
    if (sub4 == 0) partl[(chunk * 8 + h) * 64 + a] = accl;
}

__global__ void k_avreduce(const float* __restrict__ part, const float* __restrict__ partl,
                           float* __restrict__ av) {
    const int idx = blockIdx.x * 256 + threadIdx.x;      // 16384 = (h*64+a)*32+d
    const int row = idx >> 5;                            // h*64+a
    float s = 0.0f, lsum = 0.0f;
    for (int ch = 0; ch < 64; ch++) {
        s += part[(size_t)ch * 16384 + idx];
        lsum += partl[ch * 512 + row];
    }
    av[idx] = s / lsum;
}

__global__ void __launch_bounds__(256) k_stage2(const float* __restrict__ lin,
                                                const float* __restrict__ Amat,
                                                const float* __restrict__ av,
                                                float* __restrict__ mid) {
    const int h = blockIdx.y;
    const int n = blockIdx.x * 256 + threadIdx.x;
    __shared__ float4 As[64][8];
    __shared__ float4 Vs[64][8];
    for (int e = threadIdx.x; e < 512; e += 256) {
        int a = e >> 3, dq = e & 7;
        As[a][dq] = *(const float4*)&Amat[a * 256 + h * 32 + dq * 4];
        Vs[a][dq] = *(const float4*)&av[(size_t)(h * 64 + a) * 32 + dq * 4];
    }
    __syncthreads();
    float4 qv[8];
    const float* qp = lin + (size_t)n * 768 + h * 32;
#pragma unroll
    for (int i = 0; i < 8; i++) qv[i] = *(const float4*)&qp[i * 4];
    const float scale = 0.17677669529663687f;
    float lg[64];
    float mx = -1e30f;
#pragma unroll
    for (int a = 0; a < 64; a++) {
        float s = 0.0f;
#pragma unroll
        for (int i = 0; i < 8; i++) {
            const float4 v = As[a][i];
            s += qv[i].x * v.x + qv[i].y * v.y + qv[i].z * v.z + qv[i].w * v.w;
        }
        s *= scale;
        lg[a] = s;
        mx = fmaxf(mx, s);
    }
    float sum = 0.0f;
#pragma unroll
    for (int a = 0; a < 64; a++) {
        const float p = fexp(lg[a] - mx);
        lg[a] = p;
        sum += p;
    }
    float4 o[8];
#pragma unroll
    for (int i = 0; i < 8; i++) { o[i].x = 0; o[i].y = 0; o[i].z = 0; o[i].w = 0; }
#pragma unroll
    for (int a = 0; a < 64; a++) {
        const float p = lg[a];
#pragma unroll
        for (int i = 0; i < 8; i++) {
            const float4 v = Vs[a][i];
            o[i].x += p * v.x; o[i].y += p * v.y; o[i].z += p * v.z; o[i].w += p * v.w;
        }
    }
    const float inv = 1.0f / sum;
    float* mp = mid + (size_t)h * 1048576 + n;
#pragma unroll
    for (int i = 0; i < 8; i++) {
        mp[(size_t)(i * 4 + 0) * NTOK] = o[i].x * inv;
        mp[(size_t)(i * 4 + 1) * NTOK] = o[i].y * inv;
        mp[(size_t)(i * 4 + 2) * NTOK] = o[i].z * inv;
        mp[(size_t)(i * 4 + 3) * NTOK] = o[i].w * inv;
    }
}

// ---------------- launch ----------------
extern "C" void kernel_launch(void* const* d_in, const int* in_sizes, int n_in,
                              void* d_out, int out_size) {
    const float* x      = (const float*)d_in[0];
    const float* w_qkv  = (const float*)d_in[1];
    const float* b_qkv  = (const float*)d_in[2];
    const float* w_proj = (const float*)d_in[3];
    const float* b_proj = (const float*)d_in[4];
    const float* w_dwc  = (const float*)d_in[5];
    const float* b_dwc  = (const float*)d_in[6];
    float* out = (float*)d_out;

    float *lin, *A, *avpart, *partl, *av, *mid, *convout;
    __nv_bfloat16 *xhi, *xlo, *vph, *vpl, *wqh, *wql, *wph, *wpl, *wch, *wcl;
    cudaGetSymbolAddress((void**)&lin,     g_lin);
    cudaGetSymbolAddress((void**)&A,       g_A);
    cudaGetSymbolAddress((void**)&avpart,  g_avpart);
    cudaGetSymbolAddress((void**)&partl,   g_partl);
    cudaGetSymbolAddress((void**)&av,      g_av);
    cudaGetSymbolAddress((void**)&mid,     g_mid);
    cudaGetSymbolAddress((void**)&convout, g_conv);
    cudaGetSymbolAddress((void**)&xhi,     g_xhi);
    cudaGetSymbolAddress((void**)&xlo,     g_xlo);
    cudaGetSymbolAddress((void**)&vph,     g_vph);
    cudaGetSymbolAddress((void**)&vpl,     g_vpl);
    cudaGetSymbolAddress((void**)&wqh,     g_wqh);
    cudaGetSymbolAddress((void**)&wql,     g_wql);
    cudaGetSymbolAddress((void**)&wph,     g_wph);
    cudaGetSymbolAddress((void**)&wpl,     g_wpl);
    cudaGetSymbolAddress((void**)&wch,     g_wch);
    cudaGetSymbolAddress((void**)&wcl,     g_wcl);

    cudaFuncSetAttribute(gemm_mma,  cudaFuncAttributeMaxDynamicSharedMemorySize, SMEM_TOT);
    cudaFuncSetAttribute(gemm_proj, cudaFuncAttributeMaxDynamicSharedMemorySize, SMEM_TOT);

    cudaStream_t side;
    cudaStreamCreateWithFlags(&side, cudaStreamNonBlocking);
    cudaEvent_t evFork, evLin, evConv;
    cudaEventCreateWithFlags(&evFork, cudaEventDisableTiming);
    cudaEventCreateWithFlags(&evLin,  cudaEventDisableTiming);
    cudaEventCreateWithFlags(&evConv, cudaEventDisableTiming);

    // ---- main stream: splits + qkv ----
    k_split<<<(NTOK * CDIM + 255) / 256, 256>>>(x, xhi, xlo, NTOK * CDIM);
    k_split<<<(768 * 256 + 255) / 256, 256>>>(w_qkv, wqh, wql, 768 * 256);
    k_split<<<(256 * 256 + 255) / 256, 256>>>(w_proj, wph, wpl, 256 * 256);
    gemm_mma<<<dim3(6, 256), 256, SMEM_TOT>>>(xhi, xlo, wqh, wql, b_qkv, lin, 256, 768, 0);
    cudaEventRecord(evFork, 0);
    cudaEventRecord(evLin, 0);

    // ---- side stream: conv pipeline ----
    cudaStreamWaitEvent(side, evFork, 0);
    k_wconv<<<(27 * 256 * 256) / 256, 256, 0, side>>>(w_dwc, wch, wcl);
    k_zero_b<<<(PVOL * CDIM / 2 + 255) / 256, 256, 0, side>>>((uint32_t*)vph, PVOL * CDIM / 2);
    k_zero_b<<<(PVOL * CDIM / 2 + 255) / 256, 256, 0, side>>>((uint32_t*)vpl, PVOL * CDIM / 2);
    cudaStreamWaitEvent(side, evLin, 0);
    k_vpadsplit<<<NTOK, 64, 0, side>>>(lin, vph, vpl);
    gemm_mma<<<dim3(2, 256), 256, SMEM_TOT, side>>>(vph, vpl, wch, wcl, b_dwc, convout,
                                                    KCONV, 256, 1);
    cudaEventRecord(evConv, side);

    // ---- main stream: attention chain (concurrent with conv) ----
    k_pool<<<64, 256>>>(lin, A);
    k_stage1<<<dim3(64, 8), 256>>>(lin, A, avpart, partl);
    k_avreduce<<<64, 256>>>(avpart, partl, av);
    k_stage2<<<dim3(128, 8), 256>>>(lin, A, av, mid);

    // ---- join: proj GEMM reads mid + convout ----
    cudaStreamWaitEvent(0, evConv, 0);
    gemm_proj<<<dim3(2, 256), 256, SMEM_TOT>>>(mid, convout, wph, wpl, b_proj, out);
}

// round 10
// speedup vs baseline: 1.0553x; 1.0553x over previous
#include <cuda_runtime.h>
#include <cuda_bf16.h>
#include <math.h>
#include <cstdint>

// ---------------- problem constants ----------------
#define NTOK 32768
#define CDIM 256
#define NHD  8
#define HD   32
#define AGN  64
#define PVOL (34*34*34)
#define KCONV (27*256)

// ---------------- scratch (device globals) ----------------
__device__ float g_lin[NTOK * 768];
__device__ float g_S[NHD * AGN * NTOK];          // holds P = exp(scale*A.k)
__device__ float g_A[AGN * CDIM];
__device__ float g_avpart[64 * NHD * AGN * HD];
__device__ float g_partl[64 * NHD * AGN];
__device__ float g_av[NHD * AGN * HD];
__device__ float g_mid[NTOK * CDIM];
__device__ float g_conv[NTOK * CDIM];
__device__ __nv_bfloat16 g_xhi[NTOK * CDIM], g_xlo[NTOK * CDIM];
__device__ __nv_bfloat16 g_vph[PVOL * CDIM], g_vpl[PVOL * CDIM];
__device__ __nv_bfloat16 g_wqh[768 * 256], g_wql[768 * 256];
__device__ __nv_bfloat16 g_wph[256 * 256], g_wpl[256 * 256];
__device__ __nv_bfloat16 g_wch[256 * KCONV], g_wcl[256 * KCONV];

// ---------------- fast exp ----------------
__device__ __forceinline__ float fexp(float x) {
    float t = x * 1.4426950408889634f;
    int e = __float2int_rn(t);
    float f = t - (float)e;
    float p = 1.3333558e-3f;
    p = fmaf(p, f, 9.6181291e-3f);
    p = fmaf(p, f, 5.5504109e-2f);
    p = fmaf(p, f, 2.4022651e-1f);
    p = fmaf(p, f, 6.9314718e-1f);
    p = fmaf(p, f, 1.0f);
    return __int_as_float(__float_as_int(p) + (e << 23));
}

// ---------------- asm helpers ----------------
__device__ __forceinline__ uint32_t smem_u32(const void* p) {
    uint32_t a;
    asm("{ .reg .u64 t; cvta.to.shared.u64 t, %1; cvt.u32.u64 %0, t; }" : "=r"(a) : "l"(p));
    return a;
}
#define CP16(dst, src) \
    asm volatile("cp.async.cg.shared.global [%0], [%1], 16;" :: "r"(dst), "l"(src))
#define CP_COMMIT() asm volatile("cp.async.commit_group;")
#define CP_WAIT1()  asm volatile("cp.async.wait_group 1;")
#define CP_WAIT0()  asm volatile("cp.async.wait_group 0;")

#define LDSM4(r, addr) \
    asm volatile("ldmatrix.sync.aligned.m8n8.x4.shared.b16 {%0,%1,%2,%3}, [%4];" \
        : "=r"((r)[0]), "=r"((r)[1]), "=r"((r)[2]), "=r"((r)[3]) : "r"(addr))

#define MMA16816(d, a, b0v, b1v) \
    asm volatile("mma.sync.aligned.m16n8k16.row.col.f32.bf16.bf16.f32 " \
        "{%0,%1,%2,%3}, {%4,%5,%6,%7}, {%8,%9}, {%0,%1,%2,%3};" \
        : "+f"((d)[0]), "+f"((d)[1]), "+f"((d)[2]), "+f"((d)[3]) \
        : "r"((a)[0]), "r"((a)[1]), "r"((a)[2]), "r"((a)[3]), "r"(b0v), "r"(b1v))

#define SW(o) ((o) ^ (((o) >> 3) & 0x70))

// ---------------- conversion kernels ----------------
__global__ void k_split(const float* __restrict__ x, __nv_bfloat16* __restrict__ hi,
                        __nv_bfloat16* __restrict__ lo, int n) {
    int i = blockIdx.x * 256 + threadIdx.x;
    if (i < n) {
        float v = x[i];
        __nv_bfloat16 h = __float2bfloat16(v);
        hi[i] = h;
        lo[i] = __float2bfloat16(v - __bfloat162float(h));
    }
}
__global__ void k_wconv(const float* __restrict__ w, __nv_bfloat16* __restrict__ hi,
                        __nv_bfloat16* __restrict__ lo) {
    int i = blockIdx.x * 256 + threadIdx.x;     // 27*256*256
    int co = i / KCONV;
    int rem = i - co * KCONV;
    int tap = rem >> 8, ci = rem & 255;
    float v = w[(co * 256 + ci) * 27 + tap];
    __nv_bfloat16 h = __float2bfloat16(v);
    hi[i] = h;
    lo[i] = __float2bfloat16(v - __bfloat162float(h));
}
__global__ void k_zero_b(uint32_t* __restrict__ p, int n) {
    int i = blockIdx.x * 256 + threadIdx.x;
    if (i < n) p[i] = 0u;
}
__global__ void k_vpadsplit(const float* __restrict__ lin, __nv_bfloat16* __restrict__ hi,
                            __nv_bfloat16* __restrict__ lo) {
    const int n = blockIdx.x;
    const int c4 = threadIdx.x;     // 64
    const int x = n >> 10, y = (n >> 5) & 31, z = n & 31;
    const int p = ((x + 1) * 34 + (y + 1)) * 34 + (z + 1);
    float4 v = *(const float4*)&lin[(size_t)n * 768 + 512 + c4 * 4];
    size_t o = (size_t)p * 256 + c4 * 4;
    float a[4] = {v.x, v.y, v.z, v.w};
#pragma unroll
    for (int j = 0; j < 4; j++) {
        __nv_bfloat16 h = __float2bfloat16(a[j]);
        hi[o + j] = h;
        lo[o + j] = __float2bfloat16(a[j] - __bfloat162float(h));
    }
}

// ---------------- HMMA split-bf16 GEMM: swizzled, 3-stage ----------------
#define TIL 8192
#define BUF 32768
#define SMEM_TOT (3 * BUF)

__global__ void __launch_bounds__(256, 2) gemm_mma(
    const __nv_bfloat16* __restrict__ Ahi, const __nv_bfloat16* __restrict__ Alo,
    const __nv_bfloat16* __restrict__ Bhi, const __nv_bfloat16* __restrict__ Blo,
    const float* __restrict__ bias, float* __restrict__ C,
    int K, int ldc, int mode)
{
    extern __shared__ char smem[];
    const uint32_t sb = smem_u32(smem);
    const int t = threadIdx.x;
    const int m0 = blockIdx.y * 128, n0 = blockIdx.x * 128;
    const int seg = t & 3, r0 = t >> 2;
    const int wid = t >> 5, lane = t & 31;
    const int wy = wid >> 1, wx = wid & 1;
    const int lA_r = lane & 15, lA_k8 = (lane >> 4) & 1;
    const int lB_n = (lane & 7) + ((lane >> 4) & 1) * 8, lB_k8 = (lane >> 3) & 1;
    const int NC = K >> 5;

    float acc[2][8][4];
#pragma unroll
    for (int i = 0; i < 2; i++)
#pragma unroll
        for (int j = 0; j < 8; j++)
#pragma unroll
            for (int q = 0; q < 4; q++) acc[i][j][q] = 0.0f;

    auto prefetch = [&](int c) {
        const uint32_t bb = sb + (c % 3) * BUF;
        const int kc = c * 32;
        int dx = 0, dy = 0, dz = 0;
        const int ci0 = kc & 255;
        if (mode) {
            const int tap = kc >> 8;
            dx = tap / 9 - 1; dy = (tap / 3) % 3 - 1; dz = tap % 3 - 1;
        }
#pragma unroll
        for (int i = 0; i < 2; i++) {
            const int r = r0 + i * 64;
            const uint32_t so = SW(r * 64 + seg * 16);
            size_t aoff;
            if (!mode) {
                aoff = (size_t)(m0 + r) * K + kc + seg * 8;
            } else {
                const int m = m0 + r;
                const int x = m >> 10, y = (m >> 5) & 31, z = m & 31;
                aoff = (size_t)(((x + 1 + dx) * 34 + (y + 1 + dy)) * 34 + (z + 1 + dz)) * 256
                       + ci0 + seg * 8;
            }
            CP16(bb + so, Ahi + aoff);
            CP16(bb + TIL + so, Alo + aoff);
            const size_t boff = (size_t)(n0 + r) * K + kc + seg * 8;
            CP16(bb + 2 * TIL + so, Bhi + boff);
            CP16(bb + 3 * TIL + so, Blo + boff);
        }
        CP_COMMIT();
    };

    prefetch(0);
    prefetch(1);
    for (int c = 0; c < NC; c++) {
        if (c + 1 < NC) CP_WAIT1(); else CP_WAIT0();
        __syncthreads();
        if (c + 2 < NC) prefetch(c + 2);
        const uint32_t bb = sb + (c % 3) * BUF;
#pragma unroll
        for (int ks = 0; ks < 2; ks++) {
            const int chunk = ks * 32 + lA_k8 * 16;
            uint32_t ah[2][4], al[2][4];
#pragma unroll
            for (int mt = 0; mt < 2; mt++) {
                const uint32_t aaddr = bb + SW((wy * 32 + mt * 16 + lA_r) * 64 + chunk);
                LDSM4(ah[mt], aaddr);
                LDSM4(al[mt], aaddr + TIL);
            }
            const int bchunk = ks * 32 + lB_k8 * 16;
            uint32_t bf[4][4];
#pragma unroll
            for (int np = 0; np < 4; np++) {
                const uint32_t baddr = bb + 2 * TIL + SW((wx * 64 + np * 16 + lB_n) * 64 + bchunk);
                LDSM4(bf[np], baddr);
            }
#pragma unroll
            for (int mt = 0; mt < 2; mt++)
#pragma unroll
                for (int nt = 0; nt < 8; nt++) {
                    const uint32_t* bp = &bf[nt >> 1][(nt & 1) * 2];
                    MMA16816(acc[mt][nt], ah[mt], bp[0], bp[1]);
                    MMA16816(acc[mt][nt], al[mt], bp[0], bp[1]);
                }
#pragma unroll
            for (int np = 0; np < 4; np++) {
                const uint32_t baddr = bb + 3 * TIL + SW((wx * 64 + np * 16 + lB_n) * 64 + bchunk);
                LDSM4(bf[np], baddr);
            }
#pragma unroll
            for (int mt = 0; mt < 2; mt++)
#pragma unroll
                for (int nt = 0; nt < 8; nt++) {
                    const uint32_t* bp = &bf[nt >> 1][(nt & 1) * 2];
                    MMA16816(acc[mt][nt], ah[mt], bp[0], bp[1]);
                }
        }
    }

    const int er = lane >> 2, ec = (lane & 3) * 2;
#pragma unroll
    for (int mt = 0; mt < 2; mt++) {
        const int row = m0 + wy * 32 + mt * 16 + er;
#pragma unroll
        for (int nt = 0; nt < 8; nt++) {
            const int col = n0 + wx * 64 + nt * 8 + ec;
            const float b0 = __ldg(&bias[col]), b1 = __ldg(&bias[col + 1]);
            float* cp0 = C + (size_t)row * ldc + col;
            float* cp1 = C + (size_t)(row + 8) * ldc + col;
            cp0[0] = acc[mt][nt][0] + b0;
            cp0[1] = acc[mt][nt][1] + b1;
            cp1[0] = acc[mt][nt][2] + b0;
            cp1[1] = acc[mt][nt][3] + b1;
        }
    }
}

// ---------------- proj GEMM: A = fp32 (mid + convout), split in-kernel ----------------
__global__ void __launch_bounds__(256, 2) gemm_proj(
    const float* __restrict__ A0, const float* __restrict__ A1,
    const __nv_bfloat16* __restrict__ Bhi, const __nv_bfloat16* __restrict__ Blo,
    const float* __restrict__ bias, float* __restrict__ C)
{
    extern __shared__ char smem[];
    const uint32_t sb = smem_u32(smem);
    const int t = threadIdx.x;
    const int m0 = blockIdx.y * 128, n0 = blockIdx.x * 128;
    const int seg = t & 3, r0 = t >> 2;
    const int wid = t >> 5, lane = t & 31;
    const int wy = wid >> 1, wx = wid & 1;
    const int lA_r = lane & 15, lA_k8 = (lane >> 4) & 1;
    const int lB_n = (lane & 7) + ((lane >> 4) & 1) * 8, lB_k8 = (lane >> 3) & 1;
    const int NC = 8;      // K = 256

    float acc[2][8][4];
#pragma unroll
    for (int i = 0; i < 2; i++)
#pragma unroll
        for (int j = 0; j < 8; j++)
#pragma unroll
            for (int q = 0; q < 4; q++) acc[i][j][q] = 0.0f;

    auto prefetch = [&](int c) {
        const uint32_t bb = sb + (c % 3) * BUF;
        const int kc = c * 32;
#pragma unroll
        for (int i = 0; i < 2; i++) {
            const int r = r0 + i * 64;
            const uint32_t so = SW(r * 64 + seg * 16);
            const size_t boff = (size_t)(n0 + r) * 256 + kc + seg * 8;
            CP16(bb + 2 * TIL + so, Bhi + boff);
            CP16(bb + 3 * TIL + so, Blo + boff);
            const size_t aoff = (size_t)(m0 + r) * 256 + kc + seg * 8;
            const float4 p0 = *(const float4*)(A0 + aoff);
            const float4 p1 = *(const float4*)(A1 + aoff);
            const float4 q0 = *(const float4*)(A0 + aoff + 4);
            const float4 q1 = *(const float4*)(A1 + aoff + 4);
            float v[8] = {p0.x + p1.x, p0.y + p1.y, p0.z + p1.z, p0.w + p1.w,
                          q0.x + q1.x, q0.y + q1.y, q0.z + q1.z, q0.w + q1.w};
            uint32_t hw[4], lw[4];
#pragma unroll
            for (int j = 0; j < 4; j++) {
                __nv_bfloat16 h0 = __float2bfloat16(v[2 * j]);
                __nv_bfloat16 h1 = __float2bfloat16(v[2 * j + 1]);
                __nv_bfloat162 hh = __halves2bfloat162(h0, h1);
                hw[j] = *(uint32_t*)&hh;
                __nv_bfloat16 l0 = __float2bfloat16(v[2 * j] - __bfloat162float(h0));
                __nv_bfloat16 l1 = __float2bfloat16(v[2 * j + 1] - __bfloat162float(h1));
                __nv_bfloat162 ll = __halves2bfloat162(l0, l1);
                lw[j] = *(uint32_t*)&ll;
            }
            *(uint4*)(smem + (bb - sb) + so) = make_uint4(hw[0], hw[1], hw[2], hw[3]);
            *(uint4*)(smem + (bb - sb) + TIL + so) = make_uint4(lw[0], lw[1], lw[2], lw[3]);
        }
        CP_COMMIT();
    };

    prefetch(0);
    prefetch(1);
    for (int c = 0; c < NC; c++) {
        if (c + 1 < NC) CP_WAIT1(); else CP_WAIT0();
        __syncthreads();
        if (c + 2 < NC) prefetch(c + 2);
        const uint32_t bb = sb + (c % 3) * BUF;
#pragma unroll
        for (int ks = 0; ks < 2; ks++) {
            const int chunk = ks * 32 + lA_k8 * 16;
            uint32_t ah[2][4], al[2][4];
#pragma unroll
            for (int mt = 0; mt < 2; mt++) {
                const uint32_t aaddr = bb + SW((wy * 32 + mt * 16 + lA_r) * 64 + chunk);
                LDSM4(ah[mt], aaddr);
                LDSM4(al[mt], aaddr + TIL);
            }
            const int bchunk = ks * 32 + lB_k8 * 16;
            uint32_t bf[4][4];
#pragma unroll
            for (int np = 0; np < 4; np++) {
                const uint32_t baddr = bb + 2 * TIL + SW((wx * 64 + np * 16 + lB_n) * 64 + bchunk);
                LDSM4(bf[np], baddr);
            }
#pragma unroll
            for (int mt = 0; mt < 2; mt++)
#pragma unroll
                for (int nt = 0; nt < 8; nt++) {
                    const uint32_t* bp = &bf[nt >> 1][(nt & 1) * 2];
                    MMA16816(acc[mt][nt], ah[mt], bp[0], bp[1]);
                    MMA16816(acc[mt][nt], al[mt], bp[0], bp[1]);
                }
#pragma unroll
            for (int np = 0; np < 4; np++) {
                const uint32_t baddr = bb + 3 * TIL + SW((wx * 64 + np * 16 + lB_n) * 64 + bchunk);
                LDSM4(bf[np], baddr);
            }
#pragma unroll
            for (int mt = 0; mt < 2; mt++)
#pragma unroll
                for (int nt = 0; nt < 8; nt++) {
                    const uint32_t* bp = &bf[nt >> 1][(nt & 1) * 2];
                    MMA16816(acc[mt][nt], ah[mt], bp[0], bp[1]);
                }
        }
    }

    const int er = lane >> 2, ec = (lane & 3) * 2;
#pragma unroll
    for (int mt = 0; mt < 2; mt++) {
        const int row = m0 + wy * 32 + mt * 16 + er;
#pragma unroll
        for (int nt = 0; nt < 8; nt++) {
            const int col = n0 + wx * 64 + nt * 8 + ec;
            const float b0 = __ldg(&bias[col]), b1 = __ldg(&bias[col + 1]);
            float* cp0 = C + (size_t)row * 256 + col;
            float* cp1 = C + (size_t)(row + 8) * 256 + col;
            cp0[0] = acc[mt][nt][0] + b0;
            cp0[1] = acc[mt][nt][1] + b1;
            cp1[0] = acc[mt][nt][2] + b0;
            cp1[1] = acc[mt][nt][3] + b1;
        }
    }
}

// ---------------- attention kernels ----------------
__global__ void k_pool(const float* __restrict__ lin, float* __restrict__ A) {
    const int a = blockIdx.x;
    const int c = threadIdx.x;
    const int p1 = a >> 4, p2 = (a >> 2) & 3, p3 = a & 3;
    const int csub = c >> 5;
    float s = 0.0f;
    for (int b1 = 0; b1 < 8; b1++) {
        const int f1 = p1 * 8 + b1;
        const int ch = (f1 >> 2) * 32 + (c & 31);
        const int nb1 = (f1 & 3) * 8192;
        for (int b2 = 0; b2 < 8; b2++) {
            const int nb2 = nb1 + (p2 * 8 + b2) * 256;
            for (int b3 = 0; b3 < 8; b3++) {
                const int n = nb2 + (p3 * 8 + b3) * 8 + csub;
                s += lin[(size_t)n * 768 + ch];
            }
        }
    }
    A[a * 256 + c] = s * (1.0f / 512.0f);
}

// S[h][a][n] = exp(scale * A_h[a]·k_h[n])  -- no max subtraction (logits tiny)
__global__ void __launch_bounds__(256) k_S(const float* __restrict__ lin,
                                           const float* __restrict__ Amat,
                                           float* __restrict__ S) {
    const int h = blockIdx.y;
    const int n = blockIdx.x * 256 + threadIdx.x;
    __shared__ float4 As[64][8];
    for (int e = threadIdx.x; e < 512; e += 256) {
        int a = e >> 3, dq = e & 7;
        As[a][dq] = *(const float4*)&Amat[a * 256 + h * 32 + dq * 4];
    }
    __syncthreads();
    float4 kv[8];
    const float* kp = lin + (size_t)n * 768 + 256 + h * 32;
#pragma unroll
    for (int i = 0; i < 8; i++) kv[i] = *(const float4*)&kp[i * 4];
    const float scale = 0.17677669529663687f;
    float* Sp = S + (size_t)(h * 64) * NTOK + n;
#pragma unroll 4
    for (int a = 0; a < 64; a++) {
        float s = 0.0f;
#pragma unroll
        for (int i = 0; i < 8; i++) {
            const float4 av = As[a][i];
            s += kv[i].x * av.x + kv[i].y * av.y + kv[i].z * av.z + kv[i].w * av.w;
        }
        Sp[(size_t)a * NTOK] = fexp(s * scale);
    }
}

// agent_v partials + per-agent sum of P, from S = P directly
__global__ void __launch_bounds__(256) k_agentv(const float* __restrict__ lin,
                                                const float* __restrict__ S,
                                                float* __restrict__ part,
                                                float* __restrict__ partl) {
    const int h = blockIdx.y;
    const int chunk = blockIdx.x;
    const int n0 = chunk * 512;
    __shared__ float Ss[64][64];
    __shared__ float vs[64][32];
    const int a = threadIdx.x >> 2, dg = threadIdx.x & 3;
    float4 acc0 = {0, 0, 0, 0}, acc1 = {0, 0, 0, 0};
    float accl = 0.0f;

    for (int sub = 0; sub < 8; sub++) {
        const int nb = n0 + sub * 64;
        for (int e = threadIdx.x; e < 1024; e += 256) {
            int aa = e >> 4, tq = e & 15;
            *(float4*)&Ss[aa][tq * 4] =
                *(const float4*)&S[(size_t)(h * 64 + aa) * NTOK + nb + tq * 4];
        }
        for (int e = threadIdx.x; e < 512; e += 256) {
            int tt = e >> 3, dq = e & 7;
            *(float4*)&vs[tt][dq * 4] =
                *(const float4*)&lin[(size_t)(nb + tt) * 768 + 512 + h * 32 + dq * 4];
        }
        __syncthreads();
#pragma unroll 8
        for (int tt = 0; tt < 64; tt++) {
            const float p = Ss[a][tt];
            accl += p;
            const float4 v0 = *(const float4*)&vs[tt][dg * 8];
            const float4 v1 = *(const float4*)&vs[tt][dg * 8 + 4];
            acc0.x += p * v0.x; acc0.y += p * v0.y; acc0.z += p * v0.z; acc0.w += p * v0.w;
            acc1.x += p * v1.x; acc1.y += p * v1.y; acc1.z += p * v1.z; acc1.w += p * v1.w;
        }
        __syncthreads();
    }
    float* pp = part + (size_t)((chunk * 8 + h) * 64 + a) * 32 + dg * 8;
    *(float4*)pp = acc0;
    *(float4*)(pp + 4) = acc1;
    if (dg == 0) partl[(chunk * 8 + h) * 64 + a] = accl;
}

__global__ void k_avreduce(const float* __restrict__ part, const float* __restrict__ partl,
                           float* __restrict__ av) {
    const int idx = blockIdx.x * 256 + threadIdx.x;      // 16384
    const int row = idx >> 5;                            // h*64+a
    float s = 0.0f, lsum = 0.0f;
    for (int ch = 0; ch < 64; ch++) {
        s += part[(size_t)ch * 16384 + idx];
        lsum += partl[ch * 512 + row];
    }
    av[idx] = s / lsum;
}

__global__ void __launch_bounds__(256) k_stage2(const float* __restrict__ lin,
                                                const float* __restrict__ Amat,
                                                const float* __restrict__ av,
                                                float* __restrict__ mid) {
    const int h = blockIdx.y;
    const int n = blockIdx.x * 256 + threadIdx.x;
    __shared__ float4 As[64][8];
    __shared__ float4 Vs[64][8];
    for (int e = threadIdx.x; e < 512; e += 256) {
        int a = e >> 3, dq = e & 7;
        As[a][dq] = *(const float4*)&Amat[a * 256 + h * 32 + dq * 4];
        Vs[a][dq] = *(const float4*)&av[(size_t)(h * 64 + a) * 32 + dq * 4];
    }
    __syncthreads();
    float4 qv[8];
    const float* qp = lin + (size_t)n * 768 + h * 32;
#pragma unroll
    for (int i = 0; i < 8; i++) qv[i] = *(const float4*)&qp[i * 4];
    const float scale = 0.17677669529663687f;
    float lg[64];
    float mx = -1e30f;
#pragma unroll
    for (int a = 0; a < 64; a++) {
        float s = 0.0f;
#pragma unroll
        for (int i = 0; i < 8; i++) {
            const float4 v = As[a][i];
            s += qv[i].x * v.x + qv[i].y * v.y + qv[i].z * v.z + qv[i].w * v.w;
        }
        s *= scale;
        lg[a] = s;
        mx = fmaxf(mx, s);
    }
    float sum = 0.0f;
#pragma unroll
    for (int a = 0; a < 64; a++) {
        const float p = fexp(lg[a] - mx);
        lg[a] = p;
        sum += p;
    }
    float4 o[8];
#pragma unroll
    for (int i = 0; i < 8; i++) { o[i].x = 0; o[i].y = 0; o[i].z = 0; o[i].w = 0; }
#pragma unroll
    for (int a = 0; a < 64; a++) {
        const float p = lg[a];
#pragma unroll
        for (int i = 0; i < 8; i++) {
            const float4 v = Vs[a][i];
            o[i].x += p * v.x; o[i].y += p * v.y; o[i].z += p * v.z; o[i].w += p * v.w;
        }
    }
    const float inv = 1.0f / sum;
    float* mp = mid + (size_t)h * 1048576 + n;
#pragma unroll
    for (int i = 0; i < 8; i++) {
        mp[(size_t)(i * 4 + 0) * NTOK] = o[i].x * inv;
        mp[(size_t)(i * 4 + 1) * NTOK] = o[i].y * inv;
        mp[(size_t)(i * 4 + 2) * NTOK] = o[i].z * inv;
        mp[(size_t)(i * 4 + 3) * NTOK] = o[i].w * inv;
    }
}

// ---------------- launch ----------------
extern "C" void kernel_launch(void* const* d_in, const int* in_sizes, int n_in,
                              void* d_out, int out_size) {
    const float* x      = (const float*)d_in[0];
    const float* w_qkv  = (const float*)d_in[1];
    const float* b_qkv  = (const float*)d_in[2];
    const float* w_proj = (const float*)d_in[3];
    const float* b_proj = (const float*)d_in[4];
    const float* w_dwc  = (const float*)d_in[5];
    const float* b_dwc  = (const float*)d_in[6];
    float* out = (float*)d_out;

    float *lin, *S, *A, *avpart, *partl, *av, *mid, *convout;
    __nv_bfloat16 *xhi, *xlo, *vph, *vpl, *wqh, *wql, *wph, *wpl, *wch, *wcl;
    cudaGetSymbolAddress((void**)&lin,     g_lin);
    cudaGetSymbolAddress((void**)&S,       g_S);
    cudaGetSymbolAddress((void**)&A,       g_A);
    cudaGetSymbolAddress((void**)&avpart,  g_avpart);
    cudaGetSymbolAddress((void**)&partl,   g_partl);
    cudaGetSymbolAddress((void**)&av,      g_av);
    cudaGetSymbolAddress((void**)&mid,     g_mid);
    cudaGetSymbolAddress((void**)&convout, g_conv);
    cudaGetSymbolAddress((void**)&xhi,     g_xhi);
    cudaGetSymbolAddress((void**)&xlo,     g_xlo);
    cudaGetSymbolAddress((void**)&vph,     g_vph);
    cudaGetSymbolAddress((void**)&vpl,     g_vpl);
    cudaGetSymbolAddress((void**)&wqh,     g_wqh);
    cudaGetSymbolAddress((void**)&wql,     g_wql);
    cudaGetSymbolAddress((void**)&wph,     g_wph);
    cudaGetSymbolAddress((void**)&wpl,     g_wpl);
    cudaGetSymbolAddress((void**)&wch,     g_wch);
    cudaGetSymbolAddress((void**)&wcl,     g_wcl);

    cudaFuncSetAttribute(gemm_mma,  cudaFuncAttributeMaxDynamicSharedMemorySize, SMEM_TOT);
    cudaFuncSetAttribute(gemm_proj, cudaFuncAttributeMaxDynamicSharedMemorySize, SMEM_TOT);

    cudaStream_t side;
    cudaStreamCreateWithFlags(&side, cudaStreamNonBlocking);
    cudaEvent_t evFork, evLin, evConv;
    cudaEventCreateWithFlags(&evFork, cudaEventDisableTiming);
    cudaEventCreateWithFlags(&evLin,  cudaEventDisableTiming);
    cudaEventCreateWithFlags(&evConv, cudaEventDisableTiming);

    // ---- main stream: splits + qkv ----
    k_split<<<(NTOK * CDIM + 255) / 256, 256>>>(x, xhi, xlo, NTOK * CDIM);
    k_split<<<(768 * 256 + 255) / 256, 256>>>(w_qkv, wqh, wql, 768 * 256);
    k_split<<<(256 * 256 + 255) / 256, 256>>>(w_proj, wph, wpl, 256 * 256);
    gemm_mma<<<dim3(6, 256), 256, SMEM_TOT>>>(xhi, xlo, wqh, wql, b_qkv, lin, 256, 768, 0);
    cudaEventRecord(evFork, 0);
    cudaEventRecord(evLin, 0);

    // ---- side stream: conv pipeline ----
    cudaStreamWaitEvent(side, evFork, 0);
    k_wconv<<<(27 * 256 * 256) / 256, 256, 0, side>>>(w_dwc, wch, wcl);
    k_zero_b<<<(PVOL * CDIM / 2 + 255) / 256, 256, 0, side>>>((uint32_t*)vph, PVOL * CDIM / 2);
    k_zero_b<<<(PVOL * CDIM / 2 + 255) / 256, 256, 0, side>>>((uint32_t*)vpl, PVOL * CDIM / 2);
    cudaStreamWaitEvent(side, evLin, 0);
    k_vpadsplit<<<NTOK, 64, 0, side>>>(lin, vph, vpl);
    gemm_mma<<<dim3(2, 256), 256, SMEM_TOT, side>>>(vph, vpl, wch, wcl, b_dwc, convout,
                                                    KCONV, 256, 1);
    cudaEventRecord(evConv, side);

    // ---- main stream: attention chain (concurrent with conv) ----
    k_pool<<<64, 256>>>(lin, A);
    k_S<<<dim3(128, 8), 256>>>(lin, A, S);
    k_agentv<<<dim3(64, 8), 256>>>(lin, S, avpart, partl);
    k_avreduce<<<64, 256>>>(avpart, partl, av);
    k_stage2<<<dim3(128, 8), 256>>>(lin, A, av, mid);

    // ---- join: proj GEMM reads mid + convout ----
    cudaStreamWaitEvent(0, evConv, 0);
    gemm_proj<<<dim3(2, 256), 256, SMEM_TOT>>>(mid, convout, wph, wpl, b_proj, out);
}

// round 11
// speedup vs baseline: 1.1067x; 1.0487x over previous
#include <cuda_runtime.h>
#include <cuda_bf16.h>
#include <math.h>
#include <cstdint>

// ---------------- problem constants ----------------
#define NTOK 32768
#define CDIM 256
#define NHD  8
#define HD   32
#define AGN  64
#define PVOL (34*34*34)
#define KCONV (27*256)

// ---------------- scratch (device globals) ----------------
__device__ float g_lin[NTOK * 768];
__device__ float g_S[NHD * AGN * NTOK];          // holds P = exp(scale*A.k)
__device__ float g_A[AGN * CDIM];
__device__ float g_avpart[64 * NHD * AGN * HD];
__device__ float g_partl[64 * NHD * AGN];
__device__ float g_av[NHD * AGN * HD];
__device__ float g_mid[NTOK * CDIM];
__device__ float g_conv[NTOK * CDIM];
__device__ __nv_bfloat16 g_vph[PVOL * CDIM], g_vpl[PVOL * CDIM];
__device__ __nv_bfloat16 g_wqh[768 * 256], g_wql[768 * 256];
__device__ __nv_bfloat16 g_wph[256 * 256], g_wpl[256 * 256];
__device__ __nv_bfloat16 g_wch[256 * KCONV], g_wcl[256 * KCONV];

// ---------------- fast exp ----------------
__device__ __forceinline__ float fexp(float x) {
    float t = x * 1.4426950408889634f;
    int e = __float2int_rn(t);
    float f = t - (float)e;
    float p = 1.3333558e-3f;
    p = fmaf(p, f, 9.6181291e-3f);
    p = fmaf(p, f, 5.5504109e-2f);
    p = fmaf(p, f, 2.4022651e-1f);
    p = fmaf(p, f, 6.9314718e-1f);
    p = fmaf(p, f, 1.0f);
    return __int_as_float(__float_as_int(p) + (e << 23));
}

// ---------------- asm helpers ----------------
__device__ __forceinline__ uint32_t smem_u32(const void* p) {
    uint32_t a;
    asm("{ .reg .u64 t; cvta.to.shared.u64 t, %1; cvt.u32.u64 %0, t; }" : "=r"(a) : "l"(p));
    return a;
}
#define CP16(dst, src) \
    asm volatile("cp.async.cg.shared.global [%0], [%1], 16;" :: "r"(dst), "l"(src))
#define CP_COMMIT() asm volatile("cp.async.commit_group;")
#define CP_WAIT1()  asm volatile("cp.async.wait_group 1;")
#define CP_WAIT0()  asm volatile("cp.async.wait_group 0;")

#define LDSM4(r, addr) \
    asm volatile("ldmatrix.sync.aligned.m8n8.x4.shared.b16 {%0,%1,%2,%3}, [%4];" \
        : "=r"((r)[0]), "=r"((r)[1]), "=r"((r)[2]), "=r"((r)[3]) : "r"(addr))

#define MMA16816(d, a, b0v, b1v) \
    asm volatile("mma.sync.aligned.m16n8k16.row.col.f32.bf16.bf16.f32 " \
        "{%0,%1,%2,%3}, {%4,%5,%6,%7}, {%8,%9}, {%0,%1,%2,%3};" \
        : "+f"((d)[0]), "+f"((d)[1]), "+f"((d)[2]), "+f"((d)[3]) \
        : "r"((a)[0]), "r"((a)[1]), "r"((a)[2]), "r"((a)[3]), "r"(b0v), "r"(b1v))

#define SW(o) ((o) ^ (((o) >> 3) & 0x70))

// ---------------- conversion kernels ----------------
__global__ void k_split(const float* __restrict__ x, __nv_bfloat16* __restrict__ hi,
                        __nv_bfloat16* __restrict__ lo, int n) {
    int i = blockIdx.x * 256 + threadIdx.x;
    if (i < n) {
        float v = x[i];
        __nv_bfloat16 h = __float2bfloat16(v);
        hi[i] = h;
        lo[i] = __float2bfloat16(v - __bfloat162float(h));
    }
}
__global__ void k_wconv(const float* __restrict__ w, __nv_bfloat16* __restrict__ hi,
                        __nv_bfloat16* __restrict__ lo) {
    int i = blockIdx.x * 256 + threadIdx.x;     // 27*256*256
    int co = i / KCONV;
    int rem = i - co * KCONV;
    int tap = rem >> 8, ci = rem & 255;
    float v = w[(co * 256 + ci) * 27 + tap];
    __nv_bfloat16 h = __float2bfloat16(v);
    hi[i] = h;
    lo[i] = __float2bfloat16(v - __bfloat162float(h));
}
__global__ void k_zero_b(uint32_t* __restrict__ p, int n) {
    int i = blockIdx.x * 256 + threadIdx.x;
    if (i < n) p[i] = 0u;
}
__global__ void k_vpadsplit(const float* __restrict__ lin, __nv_bfloat16* __restrict__ hi,
                            __nv_bfloat16* __restrict__ lo) {
    const int n = blockIdx.x;
    const int c4 = threadIdx.x;     // 64
    const int x = n >> 10, y = (n >> 5) & 31, z = n & 31;
    const int p = ((x + 1) * 34 + (y + 1)) * 34 + (z + 1);
    float4 v = *(const float4*)&lin[(size_t)n * 768 + 512 + c4 * 4];
    size_t o = (size_t)p * 256 + c4 * 4;
    float a[4] = {v.x, v.y, v.z, v.w};
#pragma unroll
    for (int j = 0; j < 4; j++) {
        __nv_bfloat16 h = __float2bfloat16(a[j]);
        hi[o + j] = h;
        lo[o + j] = __float2bfloat16(a[j] - __bfloat162float(h));
    }
}

// ---------------- HMMA split-bf16 GEMM (bf16 A limbs): conv path ----------------
#define TIL 8192
#define BUF 32768
#define SMEM_TOT (3 * BUF)

__global__ void __launch_bounds__(256, 2) gemm_mma(
    const __nv_bfloat16* __restrict__ Ahi, const __nv_bfloat16* __restrict__ Alo,
    const __nv_bfloat16* __restrict__ Bhi, const __nv_bfloat16* __restrict__ Blo,
    const float* __restrict__ bias, float* __restrict__ C,
    int K, int ldc, int mode)
{
    extern __shared__ char smem[];
    const uint32_t sb = smem_u32(smem);
    const int t = threadIdx.x;
    const int m0 = blockIdx.y * 128, n0 = blockIdx.x * 128;
    const int seg = t & 3, r0 = t >> 2;
    const int wid = t >> 5, lane = t & 31;
    const int wy = wid >> 1, wx = wid & 1;
    const int lA_r = lane & 15, lA_k8 = (lane >> 4) & 1;
    const int lB_n = (lane & 7) + ((lane >> 4) & 1) * 8, lB_k8 = (lane >> 3) & 1;
    const int NC = K >> 5;

    float acc[2][8][4];
#pragma unroll
    for (int i = 0; i < 2; i++)
#pragma unroll
        for (int j = 0; j < 8; j++)
#pragma unroll
            for (int q = 0; q < 4; q++) acc[i][j][q] = 0.0f;

    auto prefetch = [&](int c) {
        const uint32_t bb = sb + (c % 3) * BUF;
        const int kc = c * 32;
        int dx = 0, dy = 0, dz = 0;
        const int ci0 = kc & 255;
        if (mode) {
            const int tap = kc >> 8;
            dx = tap / 9 - 1; dy = (tap / 3) % 3 - 1; dz = tap % 3 - 1;
        }
#pragma unroll
        for (int i = 0; i < 2; i++) {
            const int r = r0 + i * 64;
            const uint32_t so = SW(r * 64 + seg * 16);
            size_t aoff;
            if (!mode) {
                aoff = (size_t)(m0 + r) * K + kc + seg * 8;
            } else {
                const int m = m0 + r;
                const int x = m >> 10, y = (m >> 5) & 31, z = m & 31;
                aoff = (size_t)(((x + 1 + dx) * 34 + (y + 1 + dy)) * 34 + (z + 1 + dz)) * 256
                       + ci0 + seg * 8;
            }
            CP16(bb + so, Ahi + aoff);
            CP16(bb + TIL + so, Alo + aoff);
            const size_t boff = (size_t)(n0 + r) * K + kc + seg * 8;
            CP16(bb + 2 * TIL + so, Bhi + boff);
            CP16(bb + 3 * TIL + so, Blo + boff);
        }
        CP_COMMIT();
    };

    prefetch(0);
    prefetch(1);
    for (int c = 0; c < NC; c++) {
        if (c + 1 < NC) CP_WAIT1(); else CP_WAIT0();
        __syncthreads();
        if (c + 2 < NC) prefetch(c + 2);
        const uint32_t bb = sb + (c % 3) * BUF;
#pragma unroll
        for (int ks = 0; ks < 2; ks++) {
            const int chunk = ks * 32 + lA_k8 * 16;
            uint32_t ah[2][4], al[2][4];
#pragma unroll
            for (int mt = 0; mt < 2; mt++) {
                const uint32_t aaddr = bb + SW((wy * 32 + mt * 16 + lA_r) * 64 + chunk);
                LDSM4(ah[mt], aaddr);
                LDSM4(al[mt], aaddr + TIL);
            }
            const int bchunk = ks * 32 + lB_k8 * 16;
            uint32_t bf[4][4];
#pragma unroll
            for (int np = 0; np < 4; np++) {
                const uint32_t baddr = bb + 2 * TIL + SW((wx * 64 + np * 16 + lB_n) * 64 + bchunk);
                LDSM4(bf[np], baddr);
            }
#pragma unroll
            for (int mt = 0; mt < 2; mt++)
#pragma unroll
                for (int nt = 0; nt < 8; nt++) {
                    const uint32_t* bp = &bf[nt >> 1][(nt & 1) * 2];
                    MMA16816(acc[mt][nt], ah[mt], bp[0], bp[1]);
                    MMA16816(acc[mt][nt], al[mt], bp[0], bp[1]);
                }
#pragma unroll
            for (int np = 0; np < 4; np++) {
                const uint32_t baddr = bb + 3 * TIL + SW((wx * 64 + np * 16 + lB_n) * 64 + bchunk);
                LDSM4(bf[np], baddr);
            }
#pragma unroll
            for (int mt = 0; mt < 2; mt++)
#pragma unroll
                for (int nt = 0; nt < 8; nt++) {
                    const uint32_t* bp = &bf[nt >> 1][(nt & 1) * 2];
                    MMA16816(acc[mt][nt], ah[mt], bp[0], bp[1]);
                }
        }
    }

    const int er = lane >> 2, ec = (lane & 3) * 2;
#pragma unroll
    for (int mt = 0; mt < 2; mt++) {
        const int row = m0 + wy * 32 + mt * 16 + er;
#pragma unroll
        for (int nt = 0; nt < 8; nt++) {
            const int col = n0 + wx * 64 + nt * 8 + ec;
            const float b0 = __ldg(&bias[col]), b1 = __ldg(&bias[col + 1]);
            float* cp0 = C + (size_t)row * ldc + col;
            float* cp1 = C + (size_t)(row + 8) * ldc + col;
            cp0[0] = acc[mt][nt][0] + b0;
            cp0[1] = acc[mt][nt][1] + b1;
            cp1[0] = acc[mt][nt][2] + b0;
            cp1[1] = acc[mt][nt][3] + b1;
        }
    }
}

// ---------------- fp32-A GEMM: A = A0 (+ A1 if non-null), split in-kernel ----------------
// serves qkv (A0 = x, A1 = null, ldc = 768) and proj (A0 = mid, A1 = conv, ldc = 256)
__global__ void __launch_bounds__(256, 2) gemm_fp32a(
    const float* __restrict__ A0, const float* __restrict__ A1,
    const __nv_bfloat16* __restrict__ Bhi, const __nv_bfloat16* __restrict__ Blo,
    const float* __restrict__ bias, float* __restrict__ C, int ldc)
{
    extern __shared__ char smem[];
    const uint32_t sb = smem_u32(smem);
    const int t = threadIdx.x;
    const int m0 = blockIdx.y * 128, n0 = blockIdx.x * 128;
    const int seg = t & 3, r0 = t >> 2;
    const int wid = t >> 5, lane = t & 31;
    const int wy = wid >> 1, wx = wid & 1;
    const int lA_r = lane & 15, lA_k8 = (lane >> 4) & 1;
    const int lB_n = (lane & 7) + ((lane >> 4) & 1) * 8, lB_k8 = (lane >> 3) & 1;
    const int NC = 8;      // K = 256

    float acc[2][8][4];
#pragma unroll
    for (int i = 0; i < 2; i++)
#pragma unroll
        for (int j = 0; j < 8; j++)
#pragma unroll
            for (int q = 0; q < 4; q++) acc[i][j][q] = 0.0f;

    auto prefetch = [&](int c) {
        const uint32_t bb = sb + (c % 3) * BUF;
        const int kc = c * 32;
#pragma unroll
        for (int i = 0; i < 2; i++) {
            const int r = r0 + i * 64;
            const uint32_t so = SW(r * 64 + seg * 16);
            const size_t boff = (size_t)(n0 + r) * 256 + kc + seg * 8;
            CP16(bb + 2 * TIL + so, Bhi + boff);
            CP16(bb + 3 * TIL + so, Blo + boff);
            const size_t aoff = (size_t)(m0 + r) * 256 + kc + seg * 8;
            float4 p0 = *(const float4*)(A0 + aoff);
            float4 q0 = *(const float4*)(A0 + aoff + 4);
            float v[8] = {p0.x, p0.y, p0.z, p0.w, q0.x, q0.y, q0.z, q0.w};
            if (A1) {
                const float4 p1 = *(const float4*)(A1 + aoff);
                const float4 q1 = *(const float4*)(A1 + aoff + 4);
                v[0] += p1.x; v[1] += p1.y; v[2] += p1.z; v[3] += p1.w;
                v[4] += q1.x; v[5] += q1.y; v[6] += q1.z; v[7] += q1.w;
            }
            uint32_t hw[4], lw[4];
#pragma unroll
            for (int j = 0; j < 4; j++) {
                __nv_bfloat16 h0 = __float2bfloat16(v[2 * j]);
                __nv_bfloat16 h1 = __float2bfloat16(v[2 * j + 1]);
                __nv_bfloat162 hh = __halves2bfloat162(h0, h1);
                hw[j] = *(uint32_t*)&hh;
                __nv_bfloat16 l0 = __float2bfloat16(v[2 * j] - __bfloat162float(h0));
                __nv_bfloat16 l1 = __float2bfloat16(v[2 * j + 1] - __bfloat162float(h1));
                __nv_bfloat162 ll = __halves2bfloat162(l0, l1);
                lw[j] = *(uint32_t*)&ll;
            }
            *(uint4*)(smem + (bb - sb) + so) = make_uint4(hw[0], hw[1], hw[2], hw[3]);
            *(uint4*)(smem + (bb - sb) + TIL + so) = make_uint4(lw[0], lw[1], lw[2], lw[3]);
        }
        CP_COMMIT();
    };

    prefetch(0);
    prefetch(1);
    for (int c = 0; c < NC; c++) {
        if (c + 1 < NC) CP_WAIT1(); else CP_WAIT0();
        __syncthreads();
        if (c + 2 < NC) prefetch(c + 2);
        const uint32_t bb = sb + (c % 3) * BUF;
#pragma unroll
        for (int ks = 0; ks < 2; ks++) {
            const int chunk = ks * 32 + lA_k8 * 16;
            uint32_t ah[2][4], al[2][4];
#pragma unroll
            for (int mt = 0; mt < 2; mt++) {
                const uint32_t aaddr = bb + SW((wy * 32 + mt * 16 + lA_r) * 64 + chunk);
                LDSM4(ah[mt], aaddr);
                LDSM4(al[mt], aaddr + TIL);
            }
            const int bchunk = ks * 32 + lB_k8 * 16;
            uint32_t bf[4][4];
#pragma unroll
            for (int np = 0; np < 4; np++) {
                const uint32_t baddr = bb + 2 * TIL + SW((wx * 64 + np * 16 + lB_n) * 64 + bchunk);
                LDSM4(bf[np], baddr);
            }
#pragma unroll
            for (int mt = 0; mt < 2; mt++)
#pragma unroll
                for (int nt = 0; nt < 8; nt++) {
                    const uint32_t* bp = &bf[nt >> 1][(nt & 1) * 2];
                    MMA16816(acc[mt][nt], ah[mt], bp[0], bp[1]);
                    MMA16816(acc[mt][nt], al[mt], bp[0], bp[1]);
                }
#pragma unroll
            for (int np = 0; np < 4; np++) {
                const uint32_t baddr = bb + 3 * TIL + SW((wx * 64 + np * 16 + lB_n) * 64 + bchunk);
                LDSM4(bf[np], baddr);
            }
#pragma unroll
            for (int mt = 0; mt < 2; mt++)
#pragma unroll
                for (int nt = 0; nt < 8; nt++) {
                    const uint32_t* bp = &bf[nt >> 1][(nt & 1) * 2];
                    MMA16816(acc[mt][nt], ah[mt], bp[0], bp[1]);
                }
        }
    }

    const int er = lane >> 2, ec = (lane & 3) * 2;
#pragma unroll
    for (int mt = 0; mt < 2; mt++) {
        const int row = m0 + wy * 32 + mt * 16 + er;
#pragma unroll
        for (int nt = 0; nt < 8; nt++) {
            const int col = n0 + wx * 64 + nt * 8 + ec;
            const float b0 = __ldg(&bias[col]), b1 = __ldg(&bias[col + 1]);
            float* cp0 = C + (size_t)row * ldc + col;
            float* cp1 = C + (size_t)(row + 8) * ldc + col;
            cp0[0] = acc[mt][nt][0] + b0;
            cp0[1] = acc[mt][nt][1] + b1;
            cp1[0] = acc[mt][nt][2] + b0;
            cp1[1] = acc[mt][nt][3] + b1;
        }
    }
}

// ---------------- attention kernels ----------------
__global__ void k_pool(const float* __restrict__ lin, float* __restrict__ A) {
    const int a = blockIdx.x;
    const int c = threadIdx.x;
    const int p1 = a >> 4, p2 = (a >> 2) & 3, p3 = a & 3;
    const int csub = c >> 5;
    float s = 0.0f;
    for (int b1 = 0; b1 < 8; b1++) {
        const int f1 = p1 * 8 + b1;
        const int ch = (f1 >> 2) * 32 + (c & 31);
        const int nb1 = (f1 & 3) * 8192;
        for (int b2 = 0; b2 < 8; b2++) {
            const int nb2 = nb1 + (p2 * 8 + b2) * 256;
            for (int b3 = 0; b3 < 8; b3++) {
                const int n = nb2 + (p3 * 8 + b3) * 8 + csub;
                s += lin[(size_t)n * 768 + ch];
            }
        }
    }
    A[a * 256 + c] = s * (1.0f / 512.0f);
}

// S[h][a][n] = exp(scale * A_h[a]·k_h[n])  -- no max subtraction (logits tiny)
__global__ void __launch_bounds__(256) k_S(const float* __restrict__ lin,
                                           const float* __restrict__ Amat,
                                           float* __restrict__ S) {
    const int h = blockIdx.y;
    const int n = blockIdx.x * 256 + threadIdx.x;
    __shared__ float4 As[64][8];
    for (int e = threadIdx.x; e < 512; e += 256) {
        int a = e >> 3, dq = e & 7;
        As[a][dq] = *(const float4*)&Amat[a * 256 + h * 32 + dq * 4];
    }
    __syncthreads();
    float4 kv[8];
    const float* kp = lin + (size_t)n * 768 + 256 + h * 32;
#pragma unroll
    for (int i = 0; i < 8; i++) kv[i] = *(const float4*)&kp[i * 4];
    const float scale = 0.17677669529663687f;
    float* Sp = S + (size_t)(h * 64) * NTOK + n;
#pragma unroll 4
    for (int a = 0; a < 64; a++) {
        float s = 0.0f;
#pragma unroll
        for (int i = 0; i < 8; i++) {
            const float4 av = As[a][i];
            s += kv[i].x * av.x + kv[i].y * av.y + kv[i].z * av.z + kv[i].w * av.w;
        }
        Sp[(size_t)a * NTOK] = fexp(s * scale);
    }
}

// agent_v partials + per-agent sum of P, from S = P directly
__global__ void __launch_bounds__(256) k_agentv(const float* __restrict__ lin,
                                                const float* __restrict__ S,
                                                float* __restrict__ part,
                                                float* __restrict__ partl) {
    const int h = blockIdx.y;
    const int chunk = blockIdx.x;
    const int n0 = chunk * 512;
    __shared__ float Ss[64][64];
    __shared__ float vs[64][32];
    const int a = threadIdx.x >> 2, dg = threadIdx.x & 3;
    float4 acc0 = {0, 0, 0, 0}, acc1 = {0, 0, 0, 0};
    float accl = 0.0f;

    for (int sub = 0; sub < 8; sub++) {
        const int nb = n0 + sub * 64;
        for (int e = threadIdx.x; e < 1024; e += 256) {
            int aa = e >> 4, tq = e & 15;
            *(float4*)&Ss[aa][tq * 4] =
                *(const float4*)&S[(size_t)(h * 64 + aa) * NTOK + nb + tq * 4];
        }
        for (int e = threadIdx.x; e < 512; e += 256) {
            int tt = e >> 3, dq = e & 7;
            *(float4*)&vs[tt][dq * 4] =
                *(const float4*)&lin[(size_t)(nb + tt) * 768 + 512 + h * 32 + dq * 4];
        }
        __syncthreads();
#pragma unroll 8
        for (int tt = 0; tt < 64; tt++) {
            const float p = Ss[a][tt];
            accl += p;
            const float4 v0 = *(const float4*)&vs[tt][dg * 8];
            const float4 v1 = *(const float4*)&vs[tt][dg * 8 + 4];
            acc0.x += p * v0.x; acc0.y += p * v0.y; acc0.z += p * v0.z; acc0.w += p * v0.w;
            acc1.x += p * v1.x; acc1.y += p * v1.y; acc1.z += p * v1.z; acc1.w += p * v1.w;
        }
        __syncthreads();
    }
    float* pp = part + (size_t)((chunk * 8 + h) * 64 + a) * 32 + dg * 8;
    *(float4*)pp = acc0;
    *(float4*)(pp + 4) = acc1;
    if (dg == 0) partl[(chunk * 8 + h) * 64 + a] = accl;
}

__global__ void k_avreduce(const float* __restrict__ part, const float* __restrict__ partl,
                           float* __restrict__ av) {
    const int idx = blockIdx.x * 256 + threadIdx.x;      // 16384
    const int row = idx >> 5;                            // h*64+a
    float s = 0.0f, lsum = 0.0f;
    for (int ch = 0; ch < 64; ch++) {
        s += part[(size_t)ch * 16384 + idx];
        lsum += partl[ch * 512 + row];
    }
    av[idx] = s / lsum;
}

__global__ void __launch_bounds__(256) k_stage2(const float* __restrict__ lin,
                                                const float* __restrict__ Amat,
                                                const float* __restrict__ av,
                                                float* __restrict__ mid) {
    const int h = blockIdx.y;
    const int n = blockIdx.x * 256 + threadIdx.x;
    __shared__ float4 As[64][8];
    __shared__ float4 Vs[64][8];
    for (int e = threadIdx.x; e < 512; e += 256) {
        int a = e >> 3, dq = e & 7;
        As[a][dq] = *(const float4*)&Amat[a * 256 + h * 32 + dq * 4];
        Vs[a][dq] = *(const float4*)&av[(size_t)(h * 64 + a) * 32 + dq * 4];
    }
    __syncthreads();
    float4 qv[8];
    const float* qp = lin + (size_t)n * 768 + h * 32;
#pragma unroll
    for (int i = 0; i < 8; i++) qv[i] = *(const float4*)&qp[i * 4];
    const float scale = 0.17677669529663687f;
    float lg[64];
    float mx = -1e30f;
#pragma unroll
    for (int a = 0; a < 64; a++) {
        float s = 0.0f;
#pragma unroll
        for (int i = 0; i < 8; i++) {
            const float4 v = As[a][i];
            s += qv[i].x * v.x + qv[i].y * v.y + qv[i].z * v.z + qv[i].w * v.w;
        }
        s *= scale;
        lg[a] = s;
        mx = fmaxf(mx, s);
    }
    float sum = 0.0f;
#pragma unroll
    for (int a = 0; a < 64; a++) {
        const float p = fexp(lg[a] - mx);
        lg[a] = p;
        sum += p;
    }
    float4 o[8];
#pragma unroll
    for (int i = 0; i < 8; i++) { o[i].x = 0; o[i].y = 0; o[i].z = 0; o[i].w = 0; }
#pragma unroll
    for (int a = 0; a < 64; a++) {
        const float p = lg[a];
#pragma unroll
        for (int i = 0; i < 8; i++) {
            const float4 v = Vs[a][i];
            o[i].x += p * v.x; o[i].y += p * v.y; o[i].z += p * v.z; o[i].w += p * v.w;
        }
    }
    const float inv = 1.0f / sum;
    float* mp = mid + (size_t)h * 1048576 + n;
#pragma unroll
    for (int i = 0; i < 8; i++) {
        mp[(size_t)(i * 4 + 0) * NTOK] = o[i].x * inv;
        mp[(size_t)(i * 4 + 1) * NTOK] = o[i].y * inv;
        mp[(size_t)(i * 4 + 2) * NTOK] = o[i].z * inv;
        mp[(size_t)(i * 4 + 3) * NTOK] = o[i].w * inv;
    }
}

// ---------------- launch ----------------
extern "C" void kernel_launch(void* const* d_in, const int* in_sizes, int n_in,
                              void* d_out, int out_size) {
    const float* x      = (const float*)d_in[0];
    const float* w_qkv  = (const float*)d_in[1];
    const float* b_qkv  = (const float*)d_in[2];
    const float* w_proj = (const float*)d_in[3];
    const float* b_proj = (const float*)d_in[4];
    const float* w_dwc  = (const float*)d_in[5];
    const float* b_dwc  = (const float*)d_in[6];
    float* out = (float*)d_out;

    float *lin, *S, *A, *avpart, *partl, *av, *mid, *convout;
    __nv_bfloat16 *vph, *vpl, *wqh, *wql, *wph, *wpl, *wch, *wcl;
    cudaGetSymbolAddress((void**)&lin,     g_lin);
    cudaGetSymbolAddress((void**)&S,       g_S);
    cudaGetSymbolAddress((void**)&A,       g_A);
    cudaGetSymbolAddress((void**)&avpart,  g_avpart);
    cudaGetSymbolAddress((void**)&partl,   g_partl);
    cudaGetSymbolAddress((void**)&av,      g_av);
    cudaGetSymbolAddress((void**)&mid,     g_mid);
    cudaGetSymbolAddress((void**)&convout, g_conv);
    cudaGetSymbolAddress((void**)&vph,     g_vph);
    cudaGetSymbolAddress((void**)&vpl,     g_vpl);
    cudaGetSymbolAddress((void**)&wqh,     g_wqh);
    cudaGetSymbolAddress((void**)&wql,     g_wql);
    cudaGetSymbolAddress((void**)&wph,     g_wph);
    cudaGetSymbolAddress((void**)&wpl,     g_wpl);
    cudaGetSymbolAddress((void**)&wch,     g_wch);
    cudaGetSymbolAddress((void**)&wcl,     g_wcl);

    cudaFuncSetAttribute(gemm_mma,   cudaFuncAttributeMaxDynamicSharedMemorySize, SMEM_TOT);
    cudaFuncSetAttribute(gemm_fp32a, cudaFuncAttributeMaxDynamicSharedMemorySize, SMEM_TOT);

    cudaStream_t side;
    cudaStreamCreateWithFlags(&side, cudaStreamNonBlocking);
    cudaEvent_t evLin, evConv;
    cudaEventCreateWithFlags(&evLin,  cudaEventDisableTiming);
    cudaEventCreateWithFlags(&evConv, cudaEventDisableTiming);

    // ---- side stream: weight prep (independent of main) starts at t=0 ----
    k_split<<<(256 * 256 + 255) / 256, 256, 0, side>>>(w_proj, wph, wpl, 256 * 256);
    k_wconv<<<(27 * 256 * 256) / 256, 256, 0, side>>>(w_dwc, wch, wcl);
    k_zero_b<<<(PVOL * CDIM / 2 + 255) / 256, 256, 0, side>>>((uint32_t*)vph, PVOL * CDIM / 2);
    k_zero_b<<<(PVOL * CDIM / 2 + 255) / 256, 256, 0, side>>>((uint32_t*)vpl, PVOL * CDIM / 2);

    // ---- main stream: w_qkv split + qkv GEMM (fp32 A, in-kernel split) ----
    k_split<<<(768 * 256 + 255) / 256, 256>>>(w_qkv, wqh, wql, 768 * 256);
    gemm_fp32a<<<dim3(6, 256), 256, SMEM_TOT>>>(x, (const float*)nullptr,
                                                wqh, wql, b_qkv, lin, 768);
    cudaEventRecord(evLin, 0);

    // ---- side stream: conv pipeline after lin ready ----
    cudaStreamWaitEvent(side, evLin, 0);
    k_vpadsplit<<<NTOK, 64, 0, side>>>(lin, vph, vpl);
    gemm_mma<<<dim3(2, 256), 256, SMEM_TOT, side>>>(vph, vpl, wch, wcl, b_dwc, convout,
                                                    KCONV, 256, 1);
    cudaEventRecord(evConv, side);

    // ---- main stream: attention chain (concurrent with conv) ----
    k_pool<<<64, 256>>>(lin, A);
    k_S<<<dim3(128, 8), 256>>>(lin, A, S);
    k_agentv<<<dim3(64, 8), 256>>>(lin, S, avpart, partl);
    k_avreduce<<<64, 256>>>(avpart, partl, av);
    k_stage2<<<dim3(128, 8), 256>>>(lin, A, av, mid);

    // ---- join: proj GEMM reads mid + convout ----
    cudaStreamWaitEvent(0, evConv, 0);
    gemm_fp32a<<<dim3(2, 256), 256, SMEM_TOT>>>(mid, convout, wph, wpl, b_proj, out, 256);
}

// round 12
// speedup vs baseline: 1.1082x; 1.0014x over previous
#include <cuda_runtime.h>
#include <cuda_bf16.h>
#include <math.h>
#include <cstdint>

// ---------------- problem constants ----------------
#define NTOK 32768
#define CDIM 256
#define NHD  8
#define HD   32
#define AGN  64
#define PVOL (34*34*34)
#define KCONV (27*256)

// ---------------- scratch (device globals) ----------------
__device__ float g_lin[NTOK * 768];
__device__ float g_S[NHD * AGN * NTOK];          // holds P = exp(scale*A.k)
__device__ float g_A[AGN * CDIM];
__device__ float g_avpart[64 * NHD * AGN * HD];
__device__ float g_partl[64 * NHD * AGN];
__device__ float g_av[NHD * AGN * HD];
__device__ float g_mid[NTOK * CDIM];
__device__ float g_conv[NTOK * CDIM];
__device__ __nv_bfloat16 g_vph[PVOL * CDIM], g_vpl[PVOL * CDIM];
__device__ __nv_bfloat16 g_wqh[768 * 256], g_wql[768 * 256];
__device__ __nv_bfloat16 g_wph[256 * 256], g_wpl[256 * 256];
__device__ __nv_bfloat16 g_wch[256 * KCONV], g_wcl[256 * KCONV];

// ---------------- fast exp ----------------
__device__ __forceinline__ float fexp(float x) {
    float t = x * 1.4426950408889634f;
    int e = __float2int_rn(t);
    float f = t - (float)e;
    float p = 1.3333558e-3f;
    p = fmaf(p, f, 9.6181291e-3f);
    p = fmaf(p, f, 5.5504109e-2f);
    p = fmaf(p, f, 2.4022651e-1f);
    p = fmaf(p, f, 6.9314718e-1f);
    p = fmaf(p, f, 1.0f);
    return __int_as_float(__float_as_int(p) + (e << 23));
}

// ---------------- asm helpers ----------------
__device__ __forceinline__ uint32_t smem_u32(const void* p) {
    uint32_t a;
    asm("{ .reg .u64 t; cvta.to.shared.u64 t, %1; cvt.u32.u64 %0, t; }" : "=r"(a) : "l"(p));
    return a;
}
#define CP16(dst, src) \
    asm volatile("cp.async.cg.shared.global [%0], [%1], 16;" :: "r"(dst), "l"(src))
#define CP_COMMIT() asm volatile("cp.async.commit_group;")
#define CP_WAIT1()  asm volatile("cp.async.wait_group 1;")
#define CP_WAIT0()  asm volatile("cp.async.wait_group 0;")

#define LDSM4(r, addr) \
    asm volatile("ldmatrix.sync.aligned.m8n8.x4.shared.b16 {%0,%1,%2,%3}, [%4];" \
        : "=r"((r)[0]), "=r"((r)[1]), "=r"((r)[2]), "=r"((r)[3]) : "r"(addr))

#define MMA16816(d, a, b0v, b1v) \
    asm volatile("mma.sync.aligned.m16n8k16.row.col.f32.bf16.bf16.f32 " \
        "{%0,%1,%2,%3}, {%4,%5,%6,%7}, {%8,%9}, {%0,%1,%2,%3};" \
        : "+f"((d)[0]), "+f"((d)[1]), "+f"((d)[2]), "+f"((d)[3]) \
        : "r"((a)[0]), "r"((a)[1]), "r"((a)[2]), "r"((a)[3]), "r"(b0v), "r"(b1v))

#define SW(o) ((o) ^ (((o) >> 3) & 0x70))

// ---------------- conversion kernels ----------------
__global__ void k_split(const float* __restrict__ x, __nv_bfloat16* __restrict__ hi,
                        __nv_bfloat16* __restrict__ lo, int n) {
    int i = blockIdx.x * 256 + threadIdx.x;
    if (i < n) {
        float v = x[i];
        __nv_bfloat16 h = __float2bfloat16(v);
        hi[i] = h;
        lo[i] = __float2bfloat16(v - __bfloat162float(h));
    }
}
__global__ void k_wconv(const float* __restrict__ w, __nv_bfloat16* __restrict__ hi,
                        __nv_bfloat16* __restrict__ lo) {
    int i = blockIdx.x * 256 + threadIdx.x;     // 27*256*256
    int co = i / KCONV;
    int rem = i - co * KCONV;
    int tap = rem >> 8, ci = rem & 255;
    float v = w[(co * 256 + ci) * 27 + tap];
    __nv_bfloat16 h = __float2bfloat16(v);
    hi[i] = h;
    lo[i] = __float2bfloat16(v - __bfloat162float(h));
}
__global__ void k_zero_b(uint32_t* __restrict__ p, int n) {
    int i = blockIdx.x * 256 + threadIdx.x;
    if (i < n) p[i] = 0u;
}
__global__ void k_vpadsplit(const float* __restrict__ lin, __nv_bfloat16* __restrict__ hi,
                            __nv_bfloat16* __restrict__ lo) {
    const int n = blockIdx.x;
    const int c4 = threadIdx.x;     // 64
    const int x = n >> 10, y = (n >> 5) & 31, z = n & 31;
    const int p = ((x + 1) * 34 + (y + 1)) * 34 + (z + 1);
    float4 v = *(const float4*)&lin[(size_t)n * 768 + 512 + c4 * 4];
    size_t o = (size_t)p * 256 + c4 * 4;
    float a[4] = {v.x, v.y, v.z, v.w};
#pragma unroll
    for (int j = 0; j < 4; j++) {
        __nv_bfloat16 h = __float2bfloat16(a[j]);
        hi[o + j] = h;
        lo[o + j] = __float2bfloat16(a[j] - __bfloat162float(h));
    }
}

// ---------------- HMMA split-bf16 GEMM (bf16 A limbs): conv path ----------------
#define TIL 8192
#define BUF 32768
#define SMEM_TOT (3 * BUF)

__global__ void __launch_bounds__(256, 2) gemm_mma(
    const __nv_bfloat16* __restrict__ Ahi, const __nv_bfloat16* __restrict__ Alo,
    const __nv_bfloat16* __restrict__ Bhi, const __nv_bfloat16* __restrict__ Blo,
    const float* __restrict__ bias, float* __restrict__ C,
    int K, int ldc, int mode)
{
    extern __shared__ char smem[];
    const uint32_t sb = smem_u32(smem);
    const int t = threadIdx.x;
    const int m0 = blockIdx.y * 128, n0 = blockIdx.x * 128;
    const int seg = t & 3, r0 = t >> 2;
    const int wid = t >> 5, lane = t & 31;
    const int wy = wid >> 1, wx = wid & 1;
    const int lA_r = lane & 15, lA_k8 = (lane >> 4) & 1;
    const int lB_n = (lane & 7) + ((lane >> 4) & 1) * 8, lB_k8 = (lane >> 3) & 1;
    const int NC = K >> 5;

    float acc[2][8][4];
#pragma unroll
    for (int i = 0; i < 2; i++)
#pragma unroll
        for (int j = 0; j < 8; j++)
#pragma unroll
            for (int q = 0; q < 4; q++) acc[i][j][q] = 0.0f;

    auto prefetch = [&](int c) {
        const uint32_t bb = sb + (c % 3) * BUF;
        const int kc = c * 32;
        int dx = 0, dy = 0, dz = 0;
        const int ci0 = kc & 255;
        if (mode) {
            const int tap = kc >> 8;
            dx = tap / 9 - 1; dy = (tap / 3) % 3 - 1; dz = tap % 3 - 1;
        }
#pragma unroll
        for (int i = 0; i < 2; i++) {
            const int r = r0 + i * 64;
            const uint32_t so = SW(r * 64 + seg * 16);
            size_t aoff;
            if (!mode) {
                aoff = (size_t)(m0 + r) * K + kc + seg * 8;
            } else {
                const int m = m0 + r;
                const int x = m >> 10, y = (m >> 5) & 31, z = m & 31;
                aoff = (size_t)(((x + 1 + dx) * 34 + (y + 1 + dy)) * 34 + (z + 1 + dz)) * 256
                       + ci0 + seg * 8;
            }
            CP16(bb + so, Ahi + aoff);
            CP16(bb + TIL + so, Alo + aoff);
            const size_t boff = (size_t)(n0 + r) * K + kc + seg * 8;
            CP16(bb + 2 * TIL + so, Bhi + boff);
            CP16(bb + 3 * TIL + so, Blo + boff);
        }
        CP_COMMIT();
    };

    prefetch(0);
    prefetch(1);
    for (int c = 0; c < NC; c++) {
        if (c + 1 < NC) CP_WAIT1(); else CP_WAIT0();
        __syncthreads();
        if (c + 2 < NC) prefetch(c + 2);
        const uint32_t bb = sb + (c % 3) * BUF;
#pragma unroll
        for (int ks = 0; ks < 2; ks++) {
            const int chunk = ks * 32 + lA_k8 * 16;
            uint32_t ah[2][4], al[2][4];
#pragma unroll
            for (int mt = 0; mt < 2; mt++) {
                const uint32_t aaddr = bb + SW((wy * 32 + mt * 16 + lA_r) * 64 + chunk);
                LDSM4(ah[mt], aaddr);
                LDSM4(al[mt], aaddr + TIL);
            }
            const int bchunk = ks * 32 + lB_k8 * 16;
            uint32_t bf[4][4];
#pragma unroll
            for (int np = 0; np < 4; np++) {
                const uint32_t baddr = bb + 2 * TIL + SW((wx * 64 + np * 16 + lB_n) * 64 + bchunk);
                LDSM4(bf[np], baddr);
            }
            // sweep 1: all 16 accumulators <- ah * Bhi (independent chain)
#pragma unroll
            for (int mt = 0; mt < 2; mt++)
#pragma unroll
                for (int nt = 0; nt < 8; nt++) {
                    const uint32_t* bp = &bf[nt >> 1][(nt & 1) * 2];
                    MMA16816(acc[mt][nt], ah[mt], bp[0], bp[1]);
                }
            // sweep 2: all 16 accumulators <- al * Bhi
#pragma unroll
            for (int mt = 0; mt < 2; mt++)
#pragma unroll
                for (int nt = 0; nt < 8; nt++) {
                    const uint32_t* bp = &bf[nt >> 1][(nt & 1) * 2];
                    MMA16816(acc[mt][nt], al[mt], bp[0], bp[1]);
                }
            // load Blo fragments, sweep 3: all 16 <- ah * Blo
#pragma unroll
            for (int np = 0; np < 4; np++) {
                const uint32_t baddr = bb + 3 * TIL + SW((wx * 64 + np * 16 + lB_n) * 64 + bchunk);
                LDSM4(bf[np], baddr);
            }
#pragma unroll
            for (int mt = 0; mt < 2; mt++)
#pragma unroll
                for (int nt = 0; nt < 8; nt++) {
                    const uint32_t* bp = &bf[nt >> 1][(nt & 1) * 2];
                    MMA16816(acc[mt][nt], ah[mt], bp[0], bp[1]);
                }
        }
    }

    const int er = lane >> 2, ec = (lane & 3) * 2;
#pragma unroll
    for (int mt = 0; mt < 2; mt++) {
        const int row = m0 + wy * 32 + mt * 16 + er;
#pragma unroll
        for (int nt = 0; nt < 8; nt++) {
            const int col = n0 + wx * 64 + nt * 8 + ec;
            const float b0 = __ldg(&bias[col]), b1 = __ldg(&bias[col + 1]);
            float* cp0 = C + (size_t)row * ldc + col;
            float* cp1 = C + (size_t)(row + 8) * ldc + col;
            cp0[0] = acc[mt][nt][0] + b0;
            cp0[1] = acc[mt][nt][1] + b1;
            cp1[0] = acc[mt][nt][2] + b0;
            cp1[1] = acc[mt][nt][3] + b1;
        }
    }
}

// ---------------- fp32-A GEMM: A = A0 (+ A1 if non-null), split in-kernel ----------------
__global__ void __launch_bounds__(256, 2) gemm_fp32a(
    const float* __restrict__ A0, const float* __restrict__ A1,
    const __nv_bfloat16* __restrict__ Bhi, const __nv_bfloat16* __restrict__ Blo,
    const float* __restrict__ bias, float* __restrict__ C, int ldc)
{
    extern __shared__ char smem[];
    const uint32_t sb = smem_u32(smem);
    const int t = threadIdx.x;
    const int m0 = blockIdx.y * 128, n0 = blockIdx.x * 128;
    const int seg = t & 3, r0 = t >> 2;
    const int wid = t >> 5, lane = t & 31;
    const int wy = wid >> 1, wx = wid & 1;
    const int lA_r = lane & 15, lA_k8 = (lane >> 4) & 1;
    const int lB_n = (lane & 7) + ((lane >> 4) & 1) * 8, lB_k8 = (lane >> 3) & 1;
    const int NC = 8;      // K = 256

    float acc[2][8][4];
#pragma unroll
    for (int i = 0; i < 2; i++)
#pragma unroll
        for (int j = 0; j < 8; j++)
#pragma unroll
            for (int q = 0; q < 4; q++) acc[i][j][q] = 0.0f;

    auto prefetch = [&](int c) {
        const uint32_t bb = sb + (c % 3) * BUF;
        const int kc = c * 32;
#pragma unroll
        for (int i = 0; i < 2; i++) {
            const int r = r0 + i * 64;
            const uint32_t so = SW(r * 64 + seg * 16);
            const size_t boff = (size_t)(n0 + r) * 256 + kc + seg * 8;
            CP16(bb + 2 * TIL + so, Bhi + boff);
            CP16(bb + 3 * TIL + so, Blo + boff);
            const size_t aoff = (size_t)(m0 + r) * 256 + kc + seg * 8;
            float4 p0 = *(const float4*)(A0 + aoff);
            float4 q0 = *(const float4*)(A0 + aoff + 4);
            float v[8] = {p0.x, p0.y, p0.z, p0.w, q0.x, q0.y, q0.z, q0.w};
            if (A1) {
                const float4 p1 = *(const float4*)(A1 + aoff);
                const float4 q1 = *(const float4*)(A1 + aoff + 4);
                v[0] += p1.x; v[1] += p1.y; v[2] += p1.z; v[3] += p1.w;
                v[4] += q1.x; v[5] += q1.y; v[6] += q1.z; v[7] += q1.w;
            }
            uint32_t hw[4], lw[4];
#pragma unroll
            for (int j = 0; j < 4; j++) {
                __nv_bfloat16 h0 = __float2bfloat16(v[2 * j]);
                __nv_bfloat16 h1 = __float2bfloat16(v[2 * j + 1]);
                __nv_bfloat162 hh = __halves2bfloat162(h0, h1);
                hw[j] = *(uint32_t*)&hh;
                __nv_bfloat16 l0 = __float2bfloat16(v[2 * j] - __bfloat162float(h0));
                __nv_bfloat16 l1 = __float2bfloat16(v[2 * j + 1] - __bfloat162float(h1));
                __nv_bfloat162 ll = __halves2bfloat162(l0, l1);
                lw[j] = *(uint32_t*)&ll;
            }
            *(uint4*)(smem + (bb - sb) + so) = make_uint4(hw[0], hw[1], hw[2], hw[3]);
            *(uint4*)(smem + (bb - sb) + TIL + so) = make_uint4(lw[0], lw[1], lw[2], lw[3]);
        }
        CP_COMMIT();
    };

    prefetch(0);
    prefetch(1);
    for (int c = 0; c < NC; c++) {
        if (c + 1 < NC) CP_WAIT1(); else CP_WAIT0();
        __syncthreads();
        if (c + 2 < NC) prefetch(c + 2);
        const uint32_t bb = sb + (c % 3) * BUF;
#pragma unroll
        for (int ks = 0; ks < 2; ks++) {
            const int chunk = ks * 32 + lA_k8 * 16;
            uint32_t ah[2][4], al[2][4];
#pragma unroll
            for (int mt = 0; mt < 2; mt++) {
                const uint32_t aaddr = bb + SW((wy * 32 + mt * 16 + lA_r) * 64 + chunk);
                LDSM4(ah[mt], aaddr);
                LDSM4(al[mt], aaddr + TIL);
            }
            const int bchunk = ks * 32 + lB_k8 * 16;
            uint32_t bf[4][4];
#pragma unroll
            for (int np = 0; np < 4; np++) {
                const uint32_t baddr = bb + 2 * TIL + SW((wx * 64 + np * 16 + lB_n) * 64 + bchunk);
                LDSM4(bf[np], baddr);
            }
            // sweep 1: ah * Bhi
#pragma unroll
            for (int mt = 0; mt < 2; mt++)
#pragma unroll
                for (int nt = 0; nt < 8; nt++) {
                    const uint32_t* bp = &bf[nt >> 1][(nt & 1) * 2];
                    MMA16816(acc[mt][nt], ah[mt], bp[0], bp[1]);
                }
            // sweep 2: al * Bhi
#pragma unroll
            for (int mt = 0; mt < 2; mt++)
#pragma unroll
                for (int nt = 0; nt < 8; nt++) {
                    const uint32_t* bp = &bf[nt >> 1][(nt & 1) * 2];
                    MMA16816(acc[mt][nt], al[mt], bp[0], bp[1]);
                }
            // sweep 3: ah * Blo
#pragma unroll
            for (int np = 0; np < 4; np++) {
                const uint32_t baddr = bb + 3 * TIL + SW((wx * 64 + np * 16 + lB_n) * 64 + bchunk);
                LDSM4(bf[np], baddr);
            }
#pragma unroll
            for (int mt = 0; mt < 2; mt++)
#pragma unroll
                for (int nt = 0; nt < 8; nt++) {
                    const uint32_t* bp = &bf[nt >> 1][(nt & 1) * 2];
                    MMA16816(acc[mt][nt], ah[mt], bp[0], bp[1]);
                }
        }
    }

    const int er = lane >> 2, ec = (lane & 3) * 2;
#pragma unroll
    for (int mt = 0; mt < 2; mt++) {
        const int row = m0 + wy * 32 + mt * 16 + er;
#pragma unroll
        for (int nt = 0; nt < 8; nt++) {
            const int col = n0 + wx * 64 + nt * 8 + ec;
            const float b0 = __ldg(&bias[col]), b1 = __ldg(&bias[col + 1]);
            float* cp0 = C + (size_t)row * ldc + col;
            float* cp1 = C + (size_t)(row + 8) * ldc + col;
            cp0[0] = acc[mt][nt][0] + b0;
            cp0[1] = acc[mt][nt][1] + b1;
            cp1[0] = acc[mt][nt][2] + b0;
            cp1[1] = acc[mt][nt][3] + b1;
        }
    }
}

// ---------------- attention kernels ----------------
__global__ void k_pool(const float* __restrict__ lin, float* __restrict__ A) {
    const int a = blockIdx.x;
    const int c = threadIdx.x;
    const int p1 = a >> 4, p2 = (a >> 2) & 3, p3 = a & 3;
    const int csub = c >> 5;
    float s = 0.0f;
    for (int b1 = 0; b1 < 8; b1++) {
        const int f1 = p1 * 8 + b1;
        const int ch = (f1 >> 2) * 32 + (c & 31);
        const int nb1 = (f1 & 3) * 8192;
        for (int b2 = 0; b2 < 8; b2++) {
            const int nb2 = nb1 + (p2 * 8 + b2) * 256;
            for (int b3 = 0; b3 < 8; b3++) {
                const int n = nb2 + (p3 * 8 + b3) * 8 + csub;
                s += lin[(size_t)n * 768 + ch];
            }
        }
    }
    A[a * 256 + c] = s * (1.0f / 512.0f);
}

// S[h][a][n] = exp(scale * A_h[a]·k_h[n])  -- no max subtraction (logits tiny)
__global__ void __launch_bounds__(256) k_S(const float* __restrict__ lin,
                                           const float* __restrict__ Amat,
                                           float* __restrict__ S) {
    const int h = blockIdx.y;
    const int n = blockIdx.x * 256 + threadIdx.x;
    __shared__ float4 As[64][8];
    for (int e = threadIdx.x; e < 512; e += 256) {
        int a = e >> 3, dq = e & 7;
        As[a][dq] = *(const float4*)&Amat[a * 256 + h * 32 + dq * 4];
    }
    __syncthreads();
    float4 kv[8];
    const float* kp = lin + (size_t)n * 768 + 256 + h * 32;
#pragma unroll
    for (int i = 0; i < 8; i++) kv[i] = *(const float4*)&kp[i * 4];
    const float scale = 0.17677669529663687f;
    float* Sp = S + (size_t)(h * 64) * NTOK + n;
#pragma unroll 4
    for (int a = 0; a < 64; a++) {
        float s = 0.0f;
#pragma unroll
        for (int i = 0; i < 8; i++) {
            const float4 av = As[a][i];
            s += kv[i].x * av.x + kv[i].y * av.y + kv[i].z * av.z + kv[i].w * av.w;
        }
        Sp[(size_t)a * NTOK] = fexp(s * scale);
    }
}

// agent_v partials + per-agent sum of P, from S = P directly
__global__ void __launch_bounds__(256) k_agentv(const float* __restrict__ lin,
                                                const float* __restrict__ S,
                                                float* __restrict__ part,
                                                float* __restrict__ partl) {
    const int h = blockIdx.y;
    const int chunk = blockIdx.x;
    const int n0 = chunk * 512;
    __shared__ float Ss[64][64];
    __shared__ float vs[64][32];
    const int a = threadIdx.x >> 2, dg = threadIdx.x & 3;
    float4 acc0 = {0, 0, 0, 0}, acc1 = {0, 0, 0, 0};
    float accl = 0.0f;

    for (int sub = 0; sub < 8; sub++) {
        const int nb = n0 + sub * 64;
        for (int e = threadIdx.x; e < 1024; e += 256) {
            int aa = e >> 4, tq = e & 15;
            *(float4*)&Ss[aa][tq * 4] =
                *(const float4*)&S[(size_t)(h * 64 + aa) * NTOK + nb + tq * 4];
        }
        for (int e = threadIdx.x; e < 512; e += 256) {
            int tt = e >> 3, dq = e & 7;
            *(float4*)&vs[tt][dq * 4] =
                *(const float4*)&lin[(size_t)(nb + tt) * 768 + 512 + h * 32 + dq * 4];
        }
        __syncthreads();
#pragma unroll 8
        for (int tt = 0; tt < 64; tt++) {
            const float p = Ss[a][tt];
            accl += p;
            const float4 v0 = *(const float4*)&vs[tt][dg * 8];
            const float4 v1 = *(const float4*)&vs[tt][dg * 8 + 4];
            acc0.x += p * v0.x; acc0.y += p * v0.y; acc0.z += p * v0.z; acc0.w += p * v0.w;
            acc1.x += p * v1.x; acc1.y += p * v1.y; acc1.z += p * v1.z; acc1.w += p * v1.w;
        }
        __syncthreads();
    }
    float* pp = part + (size_t)((chunk * 8 + h) * 64 + a) * 32 + dg * 8;
    *(float4*)pp = acc0;
    *(float4*)(pp + 4) = acc1;
    if (dg == 0) partl[(chunk * 8 + h) * 64 + a] = accl;
}

__global__ void k_avreduce(const float* __restrict__ part, const float* __restrict__ partl,
                           float* __restrict__ av) {
    const int idx = blockIdx.x * 256 + threadIdx.x;      // 16384
    const int row = idx >> 5;                            // h*64+a
    float s = 0.0f, lsum = 0.0f;
    for (int ch = 0; ch < 64; ch++) {
        s += part[(size_t)ch * 16384 + idx];
        lsum += partl[ch * 512 + row];
    }
    av[idx] = s / lsum;
}

__global__ void __launch_bounds__(256) k_stage2(const float* __restrict__ lin,
                                                const float* __restrict__ Amat,
                                                const float* __restrict__ av,
                                                float* __restrict__ mid) {
    const int h = blockIdx.y;
    const int n = blockIdx.x * 256 + threadIdx.x;
    __shared__ float4 As[64][8];
    __shared__ float4 Vs[64][8];
    for (int e = threadIdx.x; e < 512; e += 256) {
        int a = e >> 3, dq = e & 7;
        As[a][dq] = *(const float4*)&Amat[a * 256 + h * 32 + dq * 4];
        Vs[a][dq] = *(const float4*)&av[(size_t)(h * 64 + a) * 32 + dq * 4];
    }
    __syncthreads();
    float4 qv[8];
    const float* qp = lin + (size_t)n * 768 + h * 32;
#pragma unroll
    for (int i = 0; i < 8; i++) qv[i] = *(const float4*)&qp[i * 4];
    const float scale = 0.17677669529663687f;
    float lg[64];
    float mx = -1e30f;
#pragma unroll
    for (int a = 0; a < 64; a++) {
        float s = 0.0f;
#pragma unroll
        for (int i = 0; i < 8; i++) {
            const float4 v = As[a][i];
            s += qv[i].x * v.x + qv[i].y * v.y + qv[i].z * v.z + qv[i].w * v.w;
        }
        s *= scale;
        lg[a] = s;
        mx = fmaxf(mx, s);
    }
    float sum = 0.0f;
#pragma unroll
    for (int a = 0; a < 64; a++) {
        const float p = fexp(lg[a] - mx);
        lg[a] = p;
        sum += p;
    }
    float4 o[8];
#pragma unroll
    for (int i = 0; i < 8; i++) { o[i].x = 0; o[i].y = 0; o[i].z = 0; o[i].w = 0; }
#pragma unroll
    for (int a = 0; a < 64; a++) {
        const float p = lg[a];
#pragma unroll
        for (int i = 0; i < 8; i++) {
            const float4 v = Vs[a][i];
            o[i].x += p * v.x; o[i].y += p * v.y; o[i].z += p * v.z; o[i].w += p * v.w;
        }
    }
    const float inv = 1.0f / sum;
    float* mp = mid + (size_t)h * 1048576 + n;
#pragma unroll
    for (int i = 0; i < 8; i++) {
        mp[(size_t)(i * 4 + 0) * NTOK] = o[i].x * inv;
        mp[(size_t)(i * 4 + 1) * NTOK] = o[i].y * inv;
        mp[(size_t)(i * 4 + 2) * NTOK] = o[i].z * inv;
        mp[(size_t)(i * 4 + 3) * NTOK] = o[i].w * inv;
    }
}

// ---------------- launch ----------------
extern "C" void kernel_launch(void* const* d_in, const int* in_sizes, int n_in,
                              void* d_out, int out_size) {
    const float* x      = (const float*)d_in[0];
    const float* w_qkv  = (const float*)d_in[1];
    const float* b_qkv  = (const float*)d_in[2];
    const float* w_proj = (const float*)d_in[3];
    const float* b_proj = (const float*)d_in[4];
    const float* w_dwc  = (const float*)d_in[5];
    const float* b_dwc  = (const float*)d_in[6];
    float* out = (float*)d_out;

    float *lin, *S, *A, *avpart, *partl, *av, *mid, *convout;
    __nv_bfloat16 *vph, *vpl, *wqh, *wql, *wph, *wpl, *wch, *wcl;
    cudaGetSymbolAddress((void**)&lin,     g_lin);
    cudaGetSymbolAddress((void**)&S,       g_S);
    cudaGetSymbolAddress((void**)&A,       g_A);
    cudaGetSymbolAddress((void**)&avpart,  g_avpart);
    cudaGetSymbolAddress((void**)&partl,   g_partl);
    cudaGetSymbolAddress((void**)&av,      g_av);
    cudaGetSymbolAddress((void**)&mid,     g_mid);
    cudaGetSymbolAddress((void**)&convout, g_conv);
    cudaGetSymbolAddress((void**)&vph,     g_vph);
    cudaGetSymbolAddress((void**)&vpl,     g_vpl);
    cudaGetSymbolAddress((void**)&wqh,     g_wqh);
    cudaGetSymbolAddress((void**)&wql,     g_wql);
    cudaGetSymbolAddress((void**)&wph,     g_wph);
    cudaGetSymbolAddress((void**)&wpl,     g_wpl);
    cudaGetSymbolAddress((void**)&wch,     g_wch);
    cudaGetSymbolAddress((void**)&wcl,     g_wcl);

    cudaFuncSetAttribute(gemm_mma,   cudaFuncAttributeMaxDynamicSharedMemorySize, SMEM_TOT);
    cudaFuncSetAttribute(gemm_fp32a, cudaFuncAttributeMaxDynamicSharedMemorySize, SMEM_TOT);

    cudaStream_t side;
    cudaStreamCreateWithFlags(&side, cudaStreamNonBlocking);
    cudaEvent_t evLin, evConv;
    cudaEventCreateWithFlags(&evLin,  cudaEventDisableTiming);
    cudaEventCreateWithFlags(&evConv, cudaEventDisableTiming);

    // ---- side stream: weight prep (independent of main) starts at t=0 ----
    k_split<<<(256 * 256 + 255) / 256, 256, 0, side>>>(w_proj, wph, wpl, 256 * 256);
    k_wconv<<<(27 * 256 * 256) / 256, 256, 0, side>>>(w_dwc, wch, wcl);
    k_zero_b<<<(PVOL * CDIM / 2 + 255) / 256, 256, 0, side>>>((uint32_t*)vph, PVOL * CDIM / 2);
    k_zero_b<<<(PVOL * CDIM / 2 + 255) / 256, 256, 0, side>>>((uint32_t*)vpl, PVOL * CDIM / 2);

    // ---- main stream: w_qkv split + qkv GEMM (fp32 A, in-kernel split) ----
    k_split<<<(768 * 256 + 255) / 256, 256>>>(w_qkv, wqh, wql, 768 * 256);
    gemm_fp32a<<<dim3(6, 256), 256, SMEM_TOT>>>(x, (const float*)nullptr,
                                                wqh, wql, b_qkv, lin, 768);
    cudaEventRecord(evLin, 0);

    // ---- side stream: conv pipeline after lin ready ----
    cudaStreamWaitEvent(side, evLin, 0);
    k_vpadsplit<<<NTOK, 64, 0, side>>>(lin, vph, vpl);
    gemm_mma<<<dim3(2, 256), 256, SMEM_TOT, side>>>(vph, vpl, wch, wcl, b_dwc, convout,
                                                    KCONV, 256, 1);
    cudaEventRecord(evConv, side);

    // ---- main stream: attention chain (concurrent with conv) ----
    k_pool<<<64, 256>>>(lin, A);
    k_S<<<dim3(128, 8), 256>>>(lin, A, S);
    k_agentv<<<dim3(64, 8), 256>>>(lin, S, avpart, partl);
    k_avreduce<<<64, 256>>>(avpart, partl, av);
    k_stage2<<<dim3(128, 8), 256>>>(lin, A, av, mid);

    // ---- join: proj GEMM reads mid + convout ----
    cudaStreamWaitEvent(0, evConv, 0);
    gemm_fp32a<<<dim3(2, 256), 256, SMEM_TOT>>>(mid, convout, wph, wpl, b_proj, out, 256);
}

// round 13
// speedup vs baseline: 1.3762x; 1.2418x over previous
#include <cuda_runtime.h>
#include <cuda_bf16.h>
#include <cuda_fp16.h>
#include <math.h>
#include <cstdint>

// ---------------- problem constants ----------------
#define NTOK 32768
#define CDIM 256
#define NHD  8
#define HD   32
#define AGN  64
#define PVOL (34*34*34)
#define KCONV (27*256)

// ---------------- scratch (device globals) ----------------
__device__ float g_lin[NTOK * 768];
__device__ float g_S[NHD * AGN * NTOK];          // holds P = exp(scale*A.k)
__device__ float g_A[AGN * CDIM];
__device__ float g_avpart[64 * NHD * AGN * HD];
__device__ float g_partl[64 * NHD * AGN];
__device__ float g_av[NHD * AGN * HD];
__device__ float g_mid[NTOK * CDIM];
__device__ float g_conv[NTOK * CDIM];
__device__ __half g_vph[PVOL * CDIM], g_vpl[PVOL * CDIM];   // fp16 limbs of v
__device__ __half g_wc[256 * KCONV];                        // fp16 conv weights
__device__ __nv_bfloat16 g_wqh[768 * 256], g_wql[768 * 256];
__device__ __nv_bfloat16 g_wph[256 * 256], g_wpl[256 * 256];

// ---------------- fast exp ----------------
__device__ __forceinline__ float fexp(float x) {
    float t = x * 1.4426950408889634f;
    int e = __float2int_rn(t);
    float f = t - (float)e;
    float p = 1.3333558e-3f;
    p = fmaf(p, f, 9.6181291e-3f);
    p = fmaf(p, f, 5.5504109e-2f);
    p = fmaf(p, f, 2.4022651e-1f);
    p = fmaf(p, f, 6.9314718e-1f);
    p = fmaf(p, f, 1.0f);
    return __int_as_float(__float_as_int(p) + (e << 23));
}

// ---------------- asm helpers ----------------
__device__ __forceinline__ uint32_t smem_u32(const void* p) {
    uint32_t a;
    asm("{ .reg .u64 t; cvta.to.shared.u64 t, %1; cvt.u32.u64 %0, t; }" : "=r"(a) : "l"(p));
    return a;
}
#define CP16(dst, src) \
    asm volatile("cp.async.cg.shared.global [%0], [%1], 16;" :: "r"(dst), "l"(src))
#define CP_COMMIT() asm volatile("cp.async.commit_group;")
#define CP_WAIT1()  asm volatile("cp.async.wait_group 1;")
#define CP_WAIT0()  asm volatile("cp.async.wait_group 0;")

#define LDSM4(r, addr) \
    asm volatile("ldmatrix.sync.aligned.m8n8.x4.shared.b16 {%0,%1,%2,%3}, [%4];" \
        : "=r"((r)[0]), "=r"((r)[1]), "=r"((r)[2]), "=r"((r)[3]) : "r"(addr))

#define MMA16816(d, a, b0v, b1v) \
    asm volatile("mma.sync.aligned.m16n8k16.row.col.f32.bf16.bf16.f32 " \
        "{%0,%1,%2,%3}, {%4,%5,%6,%7}, {%8,%9}, {%0,%1,%2,%3};" \
        : "+f"((d)[0]), "+f"((d)[1]), "+f"((d)[2]), "+f"((d)[3]) \
        : "r"((a)[0]), "r"((a)[1]), "r"((a)[2]), "r"((a)[3]), "r"(b0v), "r"(b1v))

#define MMA16816H(d, a, b0v, b1v) \
    asm volatile("mma.sync.aligned.m16n8k16.row.col.f32.f16.f16.f32 " \
        "{%0,%1,%2,%3}, {%4,%5,%6,%7}, {%8,%9}, {%0,%1,%2,%3};" \
        : "+f"((d)[0]), "+f"((d)[1]), "+f"((d)[2]), "+f"((d)[3]) \
        : "r"((a)[0]), "r"((a)[1]), "r"((a)[2]), "r"((a)[3]), "r"(b0v), "r"(b1v))

#define SW(o) ((o) ^ (((o) >> 3) & 0x70))

// ---------------- conversion kernels ----------------
__global__ void k_split(const float* __restrict__ x, __nv_bfloat16* __restrict__ hi,
                        __nv_bfloat16* __restrict__ lo, int n) {
    int i = blockIdx.x * 256 + threadIdx.x;
    if (i < n) {
        float v = x[i];
        __nv_bfloat16 h = __float2bfloat16(v);
        hi[i] = h;
        lo[i] = __float2bfloat16(v - __bfloat162float(h));
    }
}
// conv weights -> single fp16, layout [co][tap*256+ci]
__global__ void k_wconv_h(const float* __restrict__ w, __half* __restrict__ wc) {
    int i = blockIdx.x * 256 + threadIdx.x;     // 27*256*256
    int co = i / KCONV;
    int rem = i - co * KCONV;
    int tap = rem >> 8, ci = rem & 255;
    wc[i] = __float2half(w[(co * 256 + ci) * 27 + tap]);
}
__global__ void k_zero_b(uint32_t* __restrict__ p, int n) {
    int i = blockIdx.x * 256 + threadIdx.x;
    if (i < n) p[i] = 0u;
}
// v -> fp16 hi/lo limbs into padded volume
__global__ void k_vpadsplit_h(const float* __restrict__ lin, __half* __restrict__ hi,
                              __half* __restrict__ lo) {
    const int n = blockIdx.x;
    const int c4 = threadIdx.x;     // 64
    const int x = n >> 10, y = (n >> 5) & 31, z = n & 31;
    const int p = ((x + 1) * 34 + (y + 1)) * 34 + (z + 1);
    float4 v = *(const float4*)&lin[(size_t)n * 768 + 512 + c4 * 4];
    size_t o = (size_t)p * 256 + c4 * 4;
    float a[4] = {v.x, v.y, v.z, v.w};
#pragma unroll
    for (int j = 0; j < 4; j++) {
        __half h = __float2half(a[j]);
        hi[o + j] = h;
        lo[o + j] = __float2half(a[j] - __half2float(h));
    }
}

// ---------------- conv GEMM: fp16 2-pass implicit GEMM ----------------
// smem per buffer: Ah(0) Al(8K) B(16K) = 24KB; 3 buffers = 72KB
#define TIL 8192
#define CBUF 24576
#define CSMEM_TOT (3 * CBUF)
#define BUF 32768
#define SMEM_TOT (3 * BUF)

__global__ void __launch_bounds__(256, 2) gemm_conv_h(
    const __half* __restrict__ Ahi, const __half* __restrict__ Alo,
    const __half* __restrict__ B,
    const float* __restrict__ bias, float* __restrict__ C)
{
    extern __shared__ char smem[];
    const uint32_t sb = smem_u32(smem);
    const int t = threadIdx.x;
    const int m0 = blockIdx.y * 128, n0 = blockIdx.x * 128;
    const int seg = t & 3, r0 = t >> 2;
    const int wid = t >> 5, lane = t & 31;
    const int wy = wid >> 1, wx = wid & 1;
    const int lA_r = lane & 15, lA_k8 = (lane >> 4) & 1;
    const int lB_n = (lane & 7) + ((lane >> 4) & 1) * 8, lB_k8 = (lane >> 3) & 1;
    const int NC = KCONV >> 5;     // 216

    float acc[2][8][4];
#pragma unroll
    for (int i = 0; i < 2; i++)
#pragma unroll
        for (int j = 0; j < 8; j++)
#pragma unroll
            for (int q = 0; q < 4; q++) acc[i][j][q] = 0.0f;

    auto prefetch = [&](int c) {
        const uint32_t bb = sb + (c % 3) * CBUF;
        const int kc = c * 32;
        const int tap = kc >> 8;
        const int ci0 = kc & 255;
        const int dx = tap / 9 - 1, dy = (tap / 3) % 3 - 1, dz = tap % 3 - 1;
#pragma unroll
        for (int i = 0; i < 2; i++) {
            const int r = r0 + i * 64;
            const uint32_t so = SW(r * 64 + seg * 16);
            const int m = m0 + r;
            const int x = m >> 10, y = (m >> 5) & 31, z = m & 31;
            const size_t aoff =
                (size_t)(((x + 1 + dx) * 34 + (y + 1 + dy)) * 34 + (z + 1 + dz)) * 256
                + ci0 + seg * 8;
            CP16(bb + so, Ahi + aoff);
            CP16(bb + TIL + so, Alo + aoff);
            const size_t boff = (size_t)(n0 + r) * KCONV + kc + seg * 8;
            CP16(bb + 2 * TIL + so, B + boff);
        }
        CP_COMMIT();
    };

    prefetch(0);
    prefetch(1);
    for (int c = 0; c < NC; c++) {
        if (c + 1 < NC) CP_WAIT1(); else CP_WAIT0();
        __syncthreads();
        if (c + 2 < NC) prefetch(c + 2);
        const uint32_t bb = sb + (c % 3) * CBUF;
#pragma unroll
        for (int ks = 0; ks < 2; ks++) {
            const int chunk = ks * 32 + lA_k8 * 16;
            uint32_t ah[2][4], al[2][4];
#pragma unroll
            for (int mt = 0; mt < 2; mt++) {
                const uint32_t aaddr = bb + SW((wy * 32 + mt * 16 + lA_r) * 64 + chunk);
                LDSM4(ah[mt], aaddr);
                LDSM4(al[mt], aaddr + TIL);
            }
            const int bchunk = ks * 32 + lB_k8 * 16;
            uint32_t bf[4][4];
#pragma unroll
            for (int np = 0; np < 4; np++) {
                const uint32_t baddr = bb + 2 * TIL + SW((wx * 64 + np * 16 + lB_n) * 64 + bchunk);
                LDSM4(bf[np], baddr);
            }
            // pass 1: Ah * B
#pragma unroll
            for (int mt = 0; mt < 2; mt++)
#pragma unroll
                for (int nt = 0; nt < 8; nt++) {
                    const uint32_t* bp = &bf[nt >> 1][(nt & 1) * 2];
                    MMA16816H(acc[mt][nt], ah[mt], bp[0], bp[1]);
                }
            // pass 2: Al * B
#pragma unroll
            for (int mt = 0; mt < 2; mt++)
#pragma unroll
                for (int nt = 0; nt < 8; nt++) {
                    const uint32_t* bp = &bf[nt >> 1][(nt & 1) * 2];
                    MMA16816H(acc[mt][nt], al[mt], bp[0], bp[1]);
                }
        }
    }

    const int er = lane >> 2, ec = (lane & 3) * 2;
#pragma unroll
    for (int mt = 0; mt < 2; mt++) {
        const int row = m0 + wy * 32 + mt * 16 + er;
#pragma unroll
        for (int nt = 0; nt < 8; nt++) {
            const int col = n0 + wx * 64 + nt * 8 + ec;
            const float b0 = __ldg(&bias[col]), b1 = __ldg(&bias[col + 1]);
            float* cp0 = C + (size_t)row * 256 + col;
            float* cp1 = C + (size_t)(row + 8) * 256 + col;
            cp0[0] = acc[mt][nt][0] + b0;
            cp0[1] = acc[mt][nt][1] + b1;
            cp1[0] = acc[mt][nt][2] + b0;
            cp1[1] = acc[mt][nt][3] + b1;
        }
    }
}

// ---------------- fp32-A bf16 3-pass GEMM: qkv / proj ----------------
__global__ void __launch_bounds__(256, 2) gemm_fp32a(
    const float* __restrict__ A0, const float* __restrict__ A1,
    const __nv_bfloat16* __restrict__ Bhi, const __nv_bfloat16* __restrict__ Blo,
    const float* __restrict__ bias, float* __restrict__ C, int ldc)
{
    extern __shared__ char smem[];
    const uint32_t sb = smem_u32(smem);
    const int t = threadIdx.x;
    const int m0 = blockIdx.y * 128, n0 = blockIdx.x * 128;
    const int seg = t & 3, r0 = t >> 2;
    const int wid = t >> 5, lane = t & 31;
    const int wy = wid >> 1, wx = wid & 1;
    const int lA_r = lane & 15, lA_k8 = (lane >> 4) & 1;
    const int lB_n = (lane & 7) + ((lane >> 4) & 1) * 8, lB_k8 = (lane >> 3) & 1;
    const int NC = 8;      // K = 256

    float acc[2][8][4];
#pragma unroll
    for (int i = 0; i < 2; i++)
#pragma unroll
        for (int j = 0; j < 8; j++)
#pragma unroll
            for (int q = 0; q < 4; q++) acc[i][j][q] = 0.0f;

    auto prefetch = [&](int c) {
        const uint32_t bb = sb + (c % 3) * BUF;
        const int kc = c * 32;
#pragma unroll
        for (int i = 0; i < 2; i++) {
            const int r = r0 + i * 64;
            const uint32_t so = SW(r * 64 + seg * 16);
            const size_t boff = (size_t)(n0 + r) * 256 + kc + seg * 8;
            CP16(bb + 2 * TIL + so, Bhi + boff);
            CP16(bb + 3 * TIL + so, Blo + boff);
            const size_t aoff = (size_t)(m0 + r) * 256 + kc + seg * 8;
            float4 p0 = *(const float4*)(A0 + aoff);
            float4 q0 = *(const float4*)(A0 + aoff + 4);
            float v[8] = {p0.x, p0.y, p0.z, p0.w, q0.x, q0.y, q0.z, q0.w};
            if (A1) {
                const float4 p1 = *(const float4*)(A1 + aoff);
                const float4 q1 = *(const float4*)(A1 + aoff + 4);
                v[0] += p1.x; v[1] += p1.y; v[2] += p1.z; v[3] += p1.w;
                v[4] += q1.x; v[5] += q1.y; v[6] += q1.z; v[7] += q1.w;
            }
            uint32_t hw[4], lw[4];
#pragma unroll
            for (int j = 0; j < 4; j++) {
                __nv_bfloat16 h0 = __float2bfloat16(v[2 * j]);
                __nv_bfloat16 h1 = __float2bfloat16(v[2 * j + 1]);
                __nv_bfloat162 hh = __halves2bfloat162(h0, h1);
                hw[j] = *(uint32_t*)&hh;
                __nv_bfloat16 l0 = __float2bfloat16(v[2 * j] - __bfloat162float(h0));
                __nv_bfloat16 l1 = __float2bfloat16(v[2 * j + 1] - __bfloat162float(h1));
                __nv_bfloat162 ll = __halves2bfloat162(l0, l1);
                lw[j] = *(uint32_t*)&ll;
            }
            *(uint4*)(smem + (bb - sb) + so) = make_uint4(hw[0], hw[1], hw[2], hw[3]);
            *(uint4*)(smem + (bb - sb) + TIL + so) = make_uint4(lw[0], lw[1], lw[2], lw[3]);
        }
        CP_COMMIT();
    };

    prefetch(0);
    prefetch(1);
    for (int c = 0; c < NC; c++) {
        if (c + 1 < NC) CP_WAIT1(); else CP_WAIT0();
        __syncthreads();
        if (c + 2 < NC) prefetch(c + 2);
        const uint32_t bb = sb + (c % 3) * BUF;
#pragma unroll
        for (int ks = 0; ks < 2; ks++) {
            const int chunk = ks * 32 + lA_k8 * 16;
            uint32_t ah[2][4], al[2][4];
#pragma unroll
            for (int mt = 0; mt < 2; mt++) {
                const uint32_t aaddr = bb + SW((wy * 32 + mt * 16 + lA_r) * 64 + chunk);
                LDSM4(ah[mt], aaddr);
                LDSM4(al[mt], aaddr + TIL);
            }
            const int bchunk = ks * 32 + lB_k8 * 16;
            uint32_t bf[4][4];
#pragma unroll
            for (int np = 0; np < 4; np++) {
                const uint32_t baddr = bb + 2 * TIL + SW((wx * 64 + np * 16 + lB_n) * 64 + bchunk);
                LDSM4(bf[np], baddr);
            }
#pragma unroll
            for (int mt = 0; mt < 2; mt++)
#pragma unroll
                for (int nt = 0; nt < 8; nt++) {
                    const uint32_t* bp = &bf[nt >> 1][(nt & 1) * 2];
                    MMA16816(acc[mt][nt], ah[mt], bp[0], bp[1]);
                }
#pragma unroll
            for (int mt = 0; mt < 2; mt++)
#pragma unroll
                for (int nt = 0; nt < 8; nt++) {
                    const uint32_t* bp = &bf[nt >> 1][(nt & 1) * 2];
                    MMA16816(acc[mt][nt], al[mt], bp[0], bp[1]);
                }
#pragma unroll
            for (int np = 0; np < 4; np++) {
                const uint32_t baddr = bb + 3 * TIL + SW((wx * 64 + np * 16 + lB_n) * 64 + bchunk);
                LDSM4(bf[np], baddr);
            }
#pragma unroll
            for (int mt = 0; mt < 2; mt++)
#pragma unroll
                for (int nt = 0; nt < 8; nt++) {
                    const uint32_t* bp = &bf[nt >> 1][(nt & 1) * 2];
                    MMA16816(acc[mt][nt], ah[mt], bp[0], bp[1]);
                }
        }
    }

    const int er = lane >> 2, ec = (lane & 3) * 2;
#pragma unroll
    for (int mt = 0; mt < 2; mt++) {
        const int row = m0 + wy * 32 + mt * 16 + er;
#pragma unroll
        for (int nt = 0; nt < 8; nt++) {
            const int col = n0 + wx * 64 + nt * 8 + ec;
            const float b0 = __ldg(&bias[col]), b1 = __ldg(&bias[col + 1]);
            float* cp0 = C + (size_t)row * ldc + col;
            float* cp1 = C + (size_t)(row + 8) * ldc + col;
            cp0[0] = acc[mt][nt][0] + b0;
            cp0[1] = acc[mt][nt][1] + b1;
            cp1[0] = acc[mt][nt][2] + b0;
            cp1[1] = acc[mt][nt][3] + b1;
        }
    }
}

// ---------------- attention kernels ----------------
__global__ void k_pool(const float* __restrict__ lin, float* __restrict__ A) {
    const int a = blockIdx.x;
    const int c = threadIdx.x;
    const int p1 = a >> 4, p2 = (a >> 2) & 3, p3 = a & 3;
    const int csub = c >> 5;
    float s = 0.0f;
    for (int b1 = 0; b1 < 8; b1++) {
        const int f1 = p1 * 8 + b1;
        const int ch = (f1 >> 2) * 32 + (c & 31);
        const int nb1 = (f1 & 3) * 8192;
        for (int b2 = 0; b2 < 8; b2++) {
            const int nb2 = nb1 + (p2 * 8 + b2) * 256;
            for (int b3 = 0; b3 < 8; b3++) {
                const int n = nb2 + (p3 * 8 + b3) * 8 + csub;
                s += lin[(size_t)n * 768 + ch];
            }
        }
    }
    A[a * 256 + c] = s * (1.0f / 512.0f);
}

__global__ void __launch_bounds__(256) k_S(const float* __restrict__ lin,
                                           const float* __restrict__ Amat,
                                           float* __restrict__ S) {
    const int h = blockIdx.y;
    const int n = blockIdx.x * 256 + threadIdx.x;
    __shared__ float4 As[64][8];
    for (int e = threadIdx.x; e < 512; e += 256) {
        int a = e >> 3, dq = e & 7;
        As[a][dq] = *(const float4*)&Amat[a * 256 + h * 32 + dq * 4];
    }
    __syncthreads();
    float4 kv[8];
    const float* kp = lin + (size_t)n * 768 + 256 + h * 32;
#pragma unroll
    for (int i = 0; i < 8; i++) kv[i] = *(const float4*)&kp[i * 4];
    const float scale = 0.17677669529663687f;
    float* Sp = S + (size_t)(h * 64) * NTOK + n;
#pragma unroll 4
    for (int a = 0; a < 64; a++) {
        float s = 0.0f;
#pragma unroll
        for (int i = 0; i < 8; i++) {
            const float4 av = As[a][i];
            s += kv[i].x * av.x + kv[i].y * av.y + kv[i].z * av.z + kv[i].w * av.w;
        }
        Sp[(size_t)a * NTOK] = fexp(s * scale);
    }
}

__global__ void __launch_bounds__(256) k_agentv(const float* __restrict__ lin,
                                                const float* __restrict__ S,
                                                float* __restrict__ part,
                                                float* __restrict__ partl) {
    const int h = blockIdx.y;
    const int chunk = blockIdx.x;
    const int n0 = chunk * 512;
    __shared__ float Ss[64][64];
    __shared__ float vs[64][32];
    const int a = threadIdx.x >> 2, dg = threadIdx.x & 3;
    float4 acc0 = {0, 0, 0, 0}, acc1 = {0, 0, 0, 0};
    float accl = 0.0f;

    for (int sub = 0; sub < 8; sub++) {
        const int nb = n0 + sub * 64;
        for (int e = threadIdx.x; e < 1024; e += 256) {
            int aa = e >> 4, tq = e & 15;
            *(float4*)&Ss[aa][tq * 4] =
                *(const float4*)&S[(size_t)(h * 64 + aa) * NTOK + nb + tq * 4];
        }
        for (int e = threadIdx.x; e < 512; e += 256) {
            int tt = e >> 3, dq = e & 7;
            *(float4*)&vs[tt][dq * 4] =
                *(const float4*)&lin[(size_t)(nb + tt) * 768 + 512 + h * 32 + dq * 4];
        }
        __syncthreads();
#pragma unroll 8
        for (int tt = 0; tt < 64; tt++) {
            const float p = Ss[a][tt];
            accl += p;
            const float4 v0 = *(const float4*)&vs[tt][dg * 8];
            const float4 v1 = *(const float4*)&vs[tt][dg * 8 + 4];
            acc0.x += p * v0.x; acc0.y += p * v0.y; acc0.z += p * v0.z; acc0.w += p * v0.w;
            acc1.x += p * v1.x; acc1.y += p * v1.y; acc1.z += p * v1.z; acc1.w += p * v1.w;
        }
        __syncthreads();
    }
    float* pp = part + (size_t)((chunk * 8 + h) * 64 + a) * 32 + dg * 8;
    *(float4*)pp = acc0;
    *(float4*)(pp + 4) = acc1;
    if (dg == 0) partl[(chunk * 8 + h) * 64 + a] = accl;
}

__global__ void k_avreduce(const float* __restrict__ part, const float* __restrict__ partl,
                           float* __restrict__ av) {
    const int idx = blockIdx.x * 256 + threadIdx.x;      // 16384
    const int row = idx >> 5;                            // h*64+a
    float s = 0.0f, lsum = 0.0f;
    for (int ch = 0; ch < 64; ch++) {
        s += part[(size_t)ch * 16384 + idx];
        lsum += partl[ch * 512 + row];
    }
    av[idx] = s / lsum;
}

__global__ void __launch_bounds__(256) k_stage2(const float* __restrict__ lin,
                                                const float* __restrict__ Amat,
                                                const float* __restrict__ av,
                                                float* __restrict__ mid) {
    const int h = blockIdx.y;
    const int n = blockIdx.x * 256 + threadIdx.x;
    __shared__ float4 As[64][8];
    __shared__ float4 Vs[64][8];
    for (int e = threadIdx.x; e < 512; e += 256) {
        int a = e >> 3, dq = e & 7;
        As[a][dq] = *(const float4*)&Amat[a * 256 + h * 32 + dq * 4];
        Vs[a][dq] = *(const float4*)&av[(size_t)(h * 64 + a) * 32 + dq * 4];
    }
    __syncthreads();
    float4 qv[8];
    const float* qp = lin + (size_t)n * 768 + h * 32;
#pragma unroll
    for (int i = 0; i < 8; i++) qv[i] = *(const float4*)&qp[i * 4];
    const float scale = 0.17677669529663687f;
    float lg[64];
    float mx = -1e30f;
#pragma unroll
    for (int a = 0; a < 64; a++) {
        float s = 0.0f;
#pragma unroll
        for (int i = 0; i < 8; i++) {
            const float4 v = As[a][i];
            s += qv[i].x * v.x + qv[i].y * v.y + qv[i].z * v.z + qv[i].w * v.w;
        }
        s *= scale;
        lg[a] = s;
        mx = fmaxf(mx, s);
    }
    float sum = 0.0f;
#pragma unroll
    for (int a = 0; a < 64; a++) {
        const float p = fexp(lg[a] - mx);
        lg[a] = p;
        sum += p;
    }
    float4 o[8];
#pragma unroll
    for (int i = 0; i < 8; i++) { o[i].x = 0; o[i].y = 0; o[i].z = 0; o[i].w = 0; }
#pragma unroll
    for (int a = 0; a < 64; a++) {
        const float p = lg[a];
#pragma unroll
        for (int i = 0; i < 8; i++) {
            const float4 v = Vs[a][i];
            o[i].x += p * v.x; o[i].y += p * v.y; o[i].z += p * v.z; o[i].w += p * v.w;
        }
    }
    const float inv = 1.0f / sum;
    float* mp = mid + (size_t)h * 1048576 + n;
#pragma unroll
    for (int i = 0; i < 8; i++) {
        mp[(size_t)(i * 4 + 0) * NTOK] = o[i].x * inv;
        mp[(size_t)(i * 4 + 1) * NTOK] = o[i].y * inv;
        mp[(size_t)(i * 4 + 2) * NTOK] = o[i].z * inv;
        mp[(size_t)(i * 4 + 3) * NTOK] = o[i].w * inv;
    }
}

// ---------------- launch ----------------
extern "C" void kernel_launch(void* const* d_in, const int* in_sizes, int n_in,
                              void* d_out, int out_size) {
    const float* x      = (const float*)d_in[0];
    const float* w_qkv  = (const float*)d_in[1];
    const float* b_qkv  = (const float*)d_in[2];
    const float* w_proj = (const float*)d_in[3];
    const float* b_proj = (const float*)d_in[4];
    const float* w_dwc  = (const float*)d_in[5];
    const float* b_dwc  = (const float*)d_in[6];
    float* out = (float*)d_out;

    float *lin, *S, *A, *avpart, *partl, *av, *mid, *convout;
    __half *vph, *vpl, *wc;
    __nv_bfloat16 *wqh, *wql, *wph, *wpl;
    cudaGetSymbolAddress((void**)&lin,     g_lin);
    cudaGetSymbolAddress((void**)&S,       g_S);
    cudaGetSymbolAddress((void**)&A,       g_A);
    cudaGetSymbolAddress((void**)&avpart,  g_avpart);
    cudaGetSymbolAddress((void**)&partl,   g_partl);
    cudaGetSymbolAddress((void**)&av,      g_av);
    cudaGetSymbolAddress((void**)&mid,     g_mid);
    cudaGetSymbolAddress((void**)&convout, g_conv);
    cudaGetSymbolAddress((void**)&vph,     g_vph);
    cudaGetSymbolAddress((void**)&vpl,     g_vpl);
    cudaGetSymbolAddress((void**)&wc,      g_wc);
    cudaGetSymbolAddress((void**)&wqh,     g_wqh);
    cudaGetSymbolAddress((void**)&wql,     g_wql);
    cudaGetSymbolAddress((void**)&wph,     g_wph);
    cudaGetSymbolAddress((void**)&wpl,     g_wpl);

    cudaFuncSetAttribute(gemm_conv_h, cudaFuncAttributeMaxDynamicSharedMemorySize, CSMEM_TOT);
    cudaFuncSetAttribute(gemm_fp32a,  cudaFuncAttributeMaxDynamicSharedMemorySize, SMEM_TOT);

    cudaStream_t side;
    cudaStreamCreateWithFlags(&side, cudaStreamNonBlocking);
    cudaEvent_t evLin, evConv;
    cudaEventCreateWithFlags(&evLin,  cudaEventDisableTiming);
    cudaEventCreateWithFlags(&evConv, cudaEventDisableTiming);

    // ---- side stream: weight prep (independent of main) starts at t=0 ----
    k_split<<<(256 * 256 + 255) / 256, 256, 0, side>>>(w_proj, wph, wpl, 256 * 256);
    k_wconv_h<<<(27 * 256 * 256) / 256, 256, 0, side>>>(w_dwc, wc);
    k_zero_b<<<(PVOL * CDIM / 2 + 255) / 256, 256, 0, side>>>((uint32_t*)vph, PVOL * CDIM / 2);
    k_zero_b<<<(PVOL * CDIM / 2 + 255) / 256, 256, 0, side>>>((uint32_t*)vpl, PVOL * CDIM / 2);

    // ---- main stream: w_qkv split + qkv GEMM (fp32 A, in-kernel bf16 split) ----
    k_split<<<(768 * 256 + 255) / 256, 256>>>(w_qkv, wqh, wql, 768 * 256);
    gemm_fp32a<<<dim3(6, 256), 256, SMEM_TOT>>>(x, (const float*)nullptr,
                                                wqh, wql, b_qkv, lin, 768);
    cudaEventRecord(evLin, 0);

    // ---- side stream: conv pipeline after lin ready ----
    cudaStreamWaitEvent(side, evLin, 0);
    k_vpadsplit_h<<<NTOK, 64, 0, side>>>(lin, vph, vpl);
    gemm_conv_h<<<dim3(2, 256), 256, CSMEM_TOT, side>>>(vph, vpl, wc, b_dwc, convout);
    cudaEventRecord(evConv, side);

    // ---- main stream: attention chain (concurrent with conv) ----
    k_pool<<<64, 256>>>(lin, A);
    k_S<<<dim3(128, 8), 256>>>(lin, A, S);
    k_agentv<<<dim3(64, 8), 256>>>(lin, S, avpart, partl);
    k_avreduce<<<64, 256>>>(avpart, partl, av);
    k_stage2<<<dim3(128, 8), 256>>>(lin, A, av, mid);

    // ---- join: proj GEMM reads mid + convout ----
    cudaStreamWaitEvent(0, evConv, 0);
    gemm_fp32a<<<dim3(2, 256), 256, SMEM_TOT>>>(mid, convout, wph, wpl, b_proj, out, 256);
}

// round 14
// speedup vs baseline: 1.6279x; 1.1828x over previous
#include <cuda_runtime.h>
#include <cuda_bf16.h>
#include <cuda_fp16.h>
#include <math.h>
#include <cstdint>

// ---------------- problem constants ----------------
#define NTOK 32768
#define CDIM 256
#define NHD  8
#define HD   32
#define AGN  64
#define PVOL (34*34*34)
#define KCONV (27*256)

// ---------------- scratch (device globals) ----------------
__device__ float g_lin[NTOK * 768];
__device__ float g_S[NHD * AGN * NTOK];          // holds P = exp(scale*A.k)
__device__ float g_A[AGN * CDIM];
__device__ float g_avpart[64 * NHD * AGN * HD];
__device__ float g_partl[64 * NHD * AGN];
__device__ float g_av[NHD * AGN * HD];
__device__ float g_mid[NTOK * CDIM];
__device__ float g_conv[NTOK * CDIM];
__device__ __half g_vph[PVOL * CDIM];            // fp16 v (padded volume)
__device__ __half g_wc[256 * KCONV];             // fp16 conv weights
__device__ __nv_bfloat16 g_wqh[768 * 256], g_wql[768 * 256];
__device__ __nv_bfloat16 g_wph[256 * 256], g_wpl[256 * 256];

// ---------------- fast exp ----------------
__device__ __forceinline__ float fexp(float x) {
    float t = x * 1.4426950408889634f;
    int e = __float2int_rn(t);
    float f = t - (float)e;
    float p = 1.3333558e-3f;
    p = fmaf(p, f, 9.6181291e-3f);
    p = fmaf(p, f, 5.5504109e-2f);
    p = fmaf(p, f, 2.4022651e-1f);
    p = fmaf(p, f, 6.9314718e-1f);
    p = fmaf(p, f, 1.0f);
    return __int_as_float(__float_as_int(p) + (e << 23));
}

// ---------------- asm helpers ----------------
__device__ __forceinline__ uint32_t smem_u32(const void* p) {
    uint32_t a;
    asm("{ .reg .u64 t; cvta.to.shared.u64 t, %1; cvt.u32.u64 %0, t; }" : "=r"(a) : "l"(p));
    return a;
}
#define CP16(dst, src) \
    asm volatile("cp.async.cg.shared.global [%0], [%1], 16;" :: "r"(dst), "l"(src))
#define CP_COMMIT() asm volatile("cp.async.commit_group;")
#define CP_WAIT1()  asm volatile("cp.async.wait_group 1;")
#define CP_WAIT0()  asm volatile("cp.async.wait_group 0;")

#define LDSM4(r, addr) \
    asm volatile("ldmatrix.sync.aligned.m8n8.x4.shared.b16 {%0,%1,%2,%3}, [%4];" \
        : "=r"((r)[0]), "=r"((r)[1]), "=r"((r)[2]), "=r"((r)[3]) : "r"(addr))

#define MMA16816(d, a, b0v, b1v) \
    asm volatile("mma.sync.aligned.m16n8k16.row.col.f32.bf16.bf16.f32 " \
        "{%0,%1,%2,%3}, {%4,%5,%6,%7}, {%8,%9}, {%0,%1,%2,%3};" \
        : "+f"((d)[0]), "+f"((d)[1]), "+f"((d)[2]), "+f"((d)[3]) \
        : "r"((a)[0]), "r"((a)[1]), "r"((a)[2]), "r"((a)[3]), "r"(b0v), "r"(b1v))

#define MMA16816H(d, a, b0v, b1v) \
    asm volatile("mma.sync.aligned.m16n8k16.row.col.f32.f16.f16.f32 " \
        "{%0,%1,%2,%3}, {%4,%5,%6,%7}, {%8,%9}, {%0,%1,%2,%3};" \
        : "+f"((d)[0]), "+f"((d)[1]), "+f"((d)[2]), "+f"((d)[3]) \
        : "r"((a)[0]), "r"((a)[1]), "r"((a)[2]), "r"((a)[3]), "r"(b0v), "r"(b1v))

#define SW(o) ((o) ^ (((o) >> 3) & 0x70))

// ---------------- conversion kernels ----------------
__global__ void k_split(const float* __restrict__ x, __nv_bfloat16* __restrict__ hi,
                        __nv_bfloat16* __restrict__ lo, int n) {
    int i = blockIdx.x * 256 + threadIdx.x;
    if (i < n) {
        float v = x[i];
        __nv_bfloat16 h = __float2bfloat16(v);
        hi[i] = h;
        lo[i] = __float2bfloat16(v - __bfloat162float(h));
    }
}
__global__ void k_wconv_h(const float* __restrict__ w, __half* __restrict__ wc) {
    int i = blockIdx.x * 256 + threadIdx.x;     // 27*256*256
    int co = i / KCONV;
    int rem = i - co * KCONV;
    int tap = rem >> 8, ci = rem & 255;
    wc[i] = __float2half(w[(co * 256 + ci) * 27 + tap]);
}
__global__ void k_zero_b(uint32_t* __restrict__ p, int n) {
    int i = blockIdx.x * 256 + threadIdx.x;
    if (i < n) p[i] = 0u;
}
// v -> single fp16 into padded volume
__global__ void k_vpadh(const float* __restrict__ lin, __half* __restrict__ hi) {
    const int n = blockIdx.x;
    const int c4 = threadIdx.x;     // 64
    const int x = n >> 10, y = (n >> 5) & 31, z = n & 31;
    const int p = ((x + 1) * 34 + (y + 1)) * 34 + (z + 1);
    float4 v = *(const float4*)&lin[(size_t)n * 768 + 512 + c4 * 4];
    __half2* hp = (__half2*)(hi + (size_t)p * 256 + c4 * 4);
    hp[0] = __floats2half2_rn(v.x, v.y);
    hp[1] = __floats2half2_rn(v.z, v.w);
}

// ---------------- conv GEMM: fp16 1-pass implicit GEMM ----------------
// smem per buffer: A(8K) B(8K) = 16KB; 3 buffers = 48KB
#define TIL 8192
#define CBUF 16384
#define CSMEM_TOT (3 * CBUF)
#define BUF 32768
#define SMEM_TOT (3 * BUF)

__global__ void __launch_bounds__(256, 2) gemm_conv_h(
    const __half* __restrict__ Ah, const __half* __restrict__ B,
    const float* __restrict__ bias, float* __restrict__ C)
{
    extern __shared__ char smem[];
    const uint32_t sb = smem_u32(smem);
    const int t = threadIdx.x;
    const int m0 = blockIdx.y * 128, n0 = blockIdx.x * 128;
    const int seg = t & 3, r0 = t >> 2;
    const int wid = t >> 5, lane = t & 31;
    const int wy = wid >> 1, wx = wid & 1;
    const int lA_r = lane & 15, lA_k8 = (lane >> 4) & 1;
    const int lB_n = (lane & 7) + ((lane >> 4) & 1) * 8, lB_k8 = (lane >> 3) & 1;
    const int NC = KCONV >> 5;     // 216

    float acc[2][8][4];
#pragma unroll
    for (int i = 0; i < 2; i++)
#pragma unroll
        for (int j = 0; j < 8; j++)
#pragma unroll
            for (int q = 0; q < 4; q++) acc[i][j][q] = 0.0f;

    auto prefetch = [&](int c) {
        const uint32_t bb = sb + (c % 3) * CBUF;
        const int kc = c * 32;
        const int tap = kc >> 8;
        const int ci0 = kc & 255;
        const int dx = tap / 9 - 1, dy = (tap / 3) % 3 - 1, dz = tap % 3 - 1;
#pragma unroll
        for (int i = 0; i < 2; i++) {
            const int r = r0 + i * 64;
            const uint32_t so = SW(r * 64 + seg * 16);
            const int m = m0 + r;
            const int x = m >> 10, y = (m >> 5) & 31, z = m & 31;
            const size_t aoff =
                (size_t)(((x + 1 + dx) * 34 + (y + 1 + dy)) * 34 + (z + 1 + dz)) * 256
                + ci0 + seg * 8;
            CP16(bb + so, Ah + aoff);
            const size_t boff = (size_t)(n0 + r) * KCONV + kc + seg * 8;
            CP16(bb + TIL + so, B + boff);
        }
        CP_COMMIT();
    };

    prefetch(0);
    prefetch(1);
    for (int c = 0; c < NC; c++) {
        if (c + 1 < NC) CP_WAIT1(); else CP_WAIT0();
        __syncthreads();
        if (c + 2 < NC) prefetch(c + 2);
        const uint32_t bb = sb + (c % 3) * CBUF;
#pragma unroll
        for (int ks = 0; ks < 2; ks++) {
            const int chunk = ks * 32 + lA_k8 * 16;
            uint32_t ah[2][4];
#pragma unroll
            for (int mt = 0; mt < 2; mt++) {
                const uint32_t aaddr = bb + SW((wy * 32 + mt * 16 + lA_r) * 64 + chunk);
                LDSM4(ah[mt], aaddr);
            }
            const int bchunk = ks * 32 + lB_k8 * 16;
            uint32_t bf[4][4];
#pragma unroll
            for (int np = 0; np < 4; np++) {
                const uint32_t baddr = bb + TIL + SW((wx * 64 + np * 16 + lB_n) * 64 + bchunk);
                LDSM4(bf[np], baddr);
            }
#pragma unroll
            for (int mt = 0; mt < 2; mt++)
#pragma unroll
                for (int nt = 0; nt < 8; nt++) {
                    const uint32_t* bp = &bf[nt >> 1][(nt & 1) * 2];
                    MMA16816H(acc[mt][nt], ah[mt], bp[0], bp[1]);
                }
        }
    }

    const int er = lane >> 2, ec = (lane & 3) * 2;
#pragma unroll
    for (int mt = 0; mt < 2; mt++) {
        const int row = m0 + wy * 32 + mt * 16 + er;
#pragma unroll
        for (int nt = 0; nt < 8; nt++) {
            const int col = n0 + wx * 64 + nt * 8 + ec;
            const float b0 = __ldg(&bias[col]), b1 = __ldg(&bias[col + 1]);
            float* cp0 = C + (size_t)row * 256 + col;
            float* cp1 = C + (size_t)(row + 8) * 256 + col;
            cp0[0] = acc[mt][nt][0] + b0;
            cp0[1] = acc[mt][nt][1] + b1;
            cp1[0] = acc[mt][nt][2] + b0;
            cp1[1] = acc[mt][nt][3] + b1;
        }
    }
}

// ---------------- fp32-A bf16 3-pass GEMM: qkv / proj ----------------
__global__ void __launch_bounds__(256, 2) gemm_fp32a(
    const float* __restrict__ A0, const float* __restrict__ A1,
    const __nv_bfloat16* __restrict__ Bhi, const __nv_bfloat16* __restrict__ Blo,
    const float* __restrict__ bias, float* __restrict__ C, int ldc)
{
    extern __shared__ char smem[];
    const uint32_t sb = smem_u32(smem);
    const int t = threadIdx.x;
    const int m0 = blockIdx.y * 128, n0 = blockIdx.x * 128;
    const int seg = t & 3, r0 = t >> 2;
    const int wid = t >> 5, lane = t & 31;
    const int wy = wid >> 1, wx = wid & 1;
    const int lA_r = lane & 15, lA_k8 = (lane >> 4) & 1;
    const int lB_n = (lane & 7) + ((lane >> 4) & 1) * 8, lB_k8 = (lane >> 3) & 1;
    const int NC = 8;      // K = 256

    float acc[2][8][4];
#pragma unroll
    for (int i = 0; i < 2; i++)
#pragma unroll
        for (int j = 0; j < 8; j++)
#pragma unroll
            for (int q = 0; q < 4; q++) acc[i][j][q] = 0.0f;

    auto prefetch = [&](int c) {
        const uint32_t bb = sb + (c % 3) * BUF;
        const int kc = c * 32;
#pragma unroll
        for (int i = 0; i < 2; i++) {
            const int r = r0 + i * 64;
            const uint32_t so = SW(r * 64 + seg * 16);
            const size_t boff = (size_t)(n0 + r) * 256 + kc + seg * 8;
            CP16(bb + 2 * TIL + so, Bhi + boff);
            CP16(bb + 3 * TIL + so, Blo + boff);
            const size_t aoff = (size_t)(m0 + r) * 256 + kc + seg * 8;
            float4 p0 = *(const float4*)(A0 + aoff);
            float4 q0 = *(const float4*)(A0 + aoff + 4);
            float v[8] = {p0.x, p0.y, p0.z, p0.w, q0.x, q0.y, q0.z, q0.w};
            if (A1) {
                const float4 p1 = *(const float4*)(A1 + aoff);
                const float4 q1 = *(const float4*)(A1 + aoff + 4);
                v[0] += p1.x; v[1] += p1.y; v[2] += p1.z; v[3] += p1.w;
                v[4] += q1.x; v[5] += q1.y; v[6] += q1.z; v[7] += q1.w;
            }
            uint32_t hw[4], lw[4];
#pragma unroll
            for (int j = 0; j < 4; j++) {
                __nv_bfloat16 h0 = __float2bfloat16(v[2 * j]);
                __nv_bfloat16 h1 = __float2bfloat16(v[2 * j + 1]);
                __nv_bfloat162 hh = __halves2bfloat162(h0, h1);
                hw[j] = *(uint32_t*)&hh;
                __nv_bfloat16 l0 = __float2bfloat16(v[2 * j] - __bfloat162float(h0));
                __nv_bfloat16 l1 = __float2bfloat16(v[2 * j + 1] - __bfloat162float(h1));
                __nv_bfloat162 ll = __halves2bfloat162(l0, l1);
                lw[j] = *(uint32_t*)&ll;
            }
            *(uint4*)(smem + (bb - sb) + so) = make_uint4(hw[0], hw[1], hw[2], hw[3]);
            *(uint4*)(smem + (bb - sb) + TIL + so) = make_uint4(lw[0], lw[1], lw[2], lw[3]);
        }
        CP_COMMIT();
    };

    prefetch(0);
    prefetch(1);
    for (int c = 0; c < NC; c++) {
        if (c + 1 < NC) CP_WAIT1(); else CP_WAIT0();
        __syncthreads();
        if (c + 2 < NC) prefetch(c + 2);
        const uint32_t bb = sb + (c % 3) * BUF;
#pragma unroll
        for (int ks = 0; ks < 2; ks++) {
            const int chunk = ks * 32 + lA_k8 * 16;
            uint32_t ah[2][4], al[2][4];
#pragma unroll
            for (int mt = 0; mt < 2; mt++) {
                const uint32_t aaddr = bb + SW((wy * 32 + mt * 16 + lA_r) * 64 + chunk);
                LDSM4(ah[mt], aaddr);
                LDSM4(al[mt], aaddr + TIL);
            }
            const int bchunk = ks * 32 + lB_k8 * 16;
            uint32_t bf[4][4];
#pragma unroll
            for (int np = 0; np < 4; np++) {
                const uint32_t baddr = bb + 2 * TIL + SW((wx * 64 + np * 16 + lB_n) * 64 + bchunk);
                LDSM4(bf[np], baddr);
            }
#pragma unroll
            for (int mt = 0; mt < 2; mt++)
#pragma unroll
                for (int nt = 0; nt < 8; nt++) {
                    const uint32_t* bp = &bf[nt >> 1][(nt & 1) * 2];
                    MMA16816(acc[mt][nt], ah[mt], bp[0], bp[1]);
                }
#pragma unroll
            for (int mt = 0; mt < 2; mt++)
#pragma unroll
                for (int nt = 0; nt < 8; nt++) {
                    const uint32_t* bp = &bf[nt >> 1][(nt & 1) * 2];
                    MMA16816(acc[mt][nt], al[mt], bp[0], bp[1]);
                }
#pragma unroll
            for (int np = 0; np < 4; np++) {
                const uint32_t baddr = bb + 3 * TIL + SW((wx * 64 + np * 16 + lB_n) * 64 + bchunk);
                LDSM4(bf[np], baddr);
            }
#pragma unroll
            for (int mt = 0; mt < 2; mt++)
#pragma unroll
                for (int nt = 0; nt < 8; nt++) {
                    const uint32_t* bp = &bf[nt >> 1][(nt & 1) * 2];
                    MMA16816(acc[mt][nt], ah[mt], bp[0], bp[1]);
                }
        }
    }

    const int er = lane >> 2, ec = (lane & 3) * 2;
#pragma unroll
    for (int mt = 0; mt < 2; mt++) {
        const int row = m0 + wy * 32 + mt * 16 + er;
#pragma unroll
        for (int nt = 0; nt < 8; nt++) {
            const int col = n0 + wx * 64 + nt * 8 + ec;
            const float b0 = __ldg(&bias[col]), b1 = __ldg(&bias[col + 1]);
            float* cp0 = C + (size_t)row * ldc + col;
            float* cp1 = C + (size_t)(row + 8) * ldc + col;
            cp0[0] = acc[mt][nt][0] + b0;
            cp0[1] = acc[mt][nt][1] + b1;
            cp1[0] = acc[mt][nt][2] + b0;
            cp1[1] = acc[mt][nt][3] + b1;
        }
    }
}

// ---------------- attention kernels ----------------
__global__ void k_pool(const float* __restrict__ lin, float* __restrict__ A) {
    const int a = blockIdx.x;
    const int c = threadIdx.x;
    const int p1 = a >> 4, p2 = (a >> 2) & 3, p3 = a & 3;
    const int csub = c >> 5;
    float s = 0.0f;
    for (int b1 = 0; b1 < 8; b1++) {
        const int f1 = p1 * 8 + b1;
        const int ch = (f1 >> 2) * 32 + (c & 31);
        const int nb1 = (f1 & 3) * 8192;
        for (int b2 = 0; b2 < 8; b2++) {
            const int nb2 = nb1 + (p2 * 8 + b2) * 256;
            for (int b3 = 0; b3 < 8; b3++) {
                const int n = nb2 + (p3 * 8 + b3) * 8 + csub;
                s += lin[(size_t)n * 768 + ch];
            }
        }
    }
    A[a * 256 + c] = s * (1.0f / 512.0f);
}

__global__ void __launch_bounds__(256) k_S(const float* __restrict__ lin,
                                           const float* __restrict__ Amat,
                                           float* __restrict__ S) {
    const int h = blockIdx.y;
    const int n = blockIdx.x * 256 + threadIdx.x;
    __shared__ float4 As[64][8];
    for (int e = threadIdx.x; e < 512; e += 256) {
        int a = e >> 3, dq = e & 7;
        As[a][dq] = *(const float4*)&Amat[a * 256 + h * 32 + dq * 4];
    }
    __syncthreads();
    float4 kv[8];
    const float* kp = lin + (size_t)n * 768 + 256 + h * 32;
#pragma unroll
    for (int i = 0; i < 8; i++) kv[i] = *(const float4*)&kp[i * 4];
    const float scale = 0.17677669529663687f;
    float* Sp = S + (size_t)(h * 64) * NTOK + n;
#pragma unroll 4
    for (int a = 0; a < 64; a++) {
        float s = 0.0f;
#pragma unroll
        for (int i = 0; i < 8; i++) {
            const float4 av = As[a][i];
            s += kv[i].x * av.x + kv[i].y * av.y + kv[i].z * av.z + kv[i].w * av.w;
        }
        Sp[(size_t)a * NTOK] = fexp(s * scale);
    }
}

__global__ void __launch_bounds__(256) k_agentv(const float* __restrict__ lin,
                                                const float* __restrict__ S,
                                                float* __restrict__ part,
                                                float* __restrict__ partl) {
    const int h = blockIdx.y;
    const int chunk = blockIdx.x;
    const int n0 = chunk * 512;
    __shared__ float Ss[64][64];
    __shared__ float vs[64][32];
    const int a = threadIdx.x >> 2, dg = threadIdx.x & 3;
    float4 acc0 = {0, 0, 0, 0}, acc1 = {0, 0, 0, 0};
    float accl = 0.0f;

    for (int sub = 0; sub < 8; sub++) {
        const int nb = n0 + sub * 64;
        for (int e = threadIdx.x; e < 1024; e += 256) {
            int aa = e >> 4, tq = e & 15;
            *(float4*)&Ss[aa][tq * 4] =
                *(const float4*)&S[(size_t)(h * 64 + aa) * NTOK + nb + tq * 4];
        }
        for (int e = threadIdx.x; e < 512; e += 256) {
            int tt = e >> 3, dq = e & 7;
            *(float4*)&vs[tt][dq * 4] =
                *(const float4*)&lin[(size_t)(nb + tt) * 768 + 512 + h * 32 + dq * 4];
        }
        __syncthreads();
#pragma unroll 8
        for (int tt = 0; tt < 64; tt++) {
            const float p = Ss[a][tt];
            accl += p;
            const float4 v0 = *(const float4*)&vs[tt][dg * 8];
            const float4 v1 = *(const float4*)&vs[tt][dg * 8 + 4];
            acc0.x += p * v0.x; acc0.y += p * v0.y; acc0.z += p * v0.z; acc0.w += p * v0.w;
            acc1.x += p * v1.x; acc1.y += p * v1.y; acc1.z += p * v1.z; acc1.w += p * v1.w;
        }
        __syncthreads();
    }
    float* pp = part + (size_t)((chunk * 8 + h) * 64 + a) * 32 + dg * 8;
    *(float4*)pp = acc0;
    *(float4*)(pp + 4) = acc1;
    if (dg == 0) partl[(chunk * 8 + h) * 64 + a] = accl;
}

__global__ void k_avreduce(const float* __restrict__ part, const float* __restrict__ partl,
                           float* __restrict__ av) {
    const int idx = blockIdx.x * 256 + threadIdx.x;      // 16384
    const int row = idx >> 5;                            // h*64+a
    float s = 0.0f, lsum = 0.0f;
    for (int ch = 0; ch < 64; ch++) {
        s += part[(size_t)ch * 16384 + idx];
        lsum += partl[ch * 512 + row];
    }
    av[idx] = s / lsum;
}

__global__ void __launch_bounds__(256) k_stage2(const float* __restrict__ lin,
                                                const float* __restrict__ Amat,
                                                const float* __restrict__ av,
                                                float* __restrict__ mid) {
    const int h = blockIdx.y;
    const int n = blockIdx.x * 256 + threadIdx.x;
    __shared__ float4 As[64][8];
    __shared__ float4 Vs[64][8];
    for (int e = threadIdx.x; e < 512; e += 256) {
        int a = e >> 3, dq = e & 7;
        As[a][dq] = *(const float4*)&Amat[a * 256 + h * 32 + dq * 4];
        Vs[a][dq] = *(const float4*)&av[(size_t)(h * 64 + a) * 32 + dq * 4];
    }
    __syncthreads();
    float4 qv[8];
    const float* qp = lin + (size_t)n * 768 + h * 32;
#pragma unroll
    for (int i = 0; i < 8; i++) qv[i] = *(const float4*)&qp[i * 4];
    const float scale = 0.17677669529663687f;
    float lg[64];
    float mx = -1e30f;
#pragma unroll
    for (int a = 0; a < 64; a++) {
        float s = 0.0f;
#pragma unroll
        for (int i = 0; i < 8; i++) {
            const float4 v = As[a][i];
            s += qv[i].x * v.x + qv[i].y * v.y + qv[i].z * v.z + qv[i].w * v.w;
        }
        s *= scale;
        lg[a] = s;
        mx = fmaxf(mx, s);
    }
    float sum = 0.0f;
#pragma unroll
    for (int a = 0; a < 64; a++) {
        const float p = fexp(lg[a] - mx);
        lg[a] = p;
        sum += p;
    }
    float4 o[8];
#pragma unroll
    for (int i = 0; i < 8; i++) { o[i].x = 0; o[i].y = 0; o[i].z = 0; o[i].w = 0; }
#pragma unroll
    for (int a = 0; a < 64; a++) {
        const float p = lg[a];
#pragma unroll
        for (int i = 0; i < 8; i++) {
            const float4 v = Vs[a][i];
            o[i].x += p * v.x; o[i].y += p * v.y; o[i].z += p * v.z; o[i].w += p * v.w;
        }
    }
    const float inv = 1.0f / sum;
    float* mp = mid + (size_t)h * 1048576 + n;
#pragma unroll
    for (int i = 0; i < 8; i++) {
        mp[(size_t)(i * 4 + 0) * NTOK] = o[i].x * inv;
        mp[(size_t)(i * 4 + 1) * NTOK] = o[i].y * inv;
        mp[(size_t)(i * 4 + 2) * NTOK] = o[i].z * inv;
        mp[(size_t)(i * 4 + 3) * NTOK] = o[i].w * inv;
    }
}

// ---------------- launch ----------------
extern "C" void kernel_launch(void* const* d_in, const int* in_sizes, int n_in,
                              void* d_out, int out_size) {
    const float* x      = (const float*)d_in[0];
    const float* w_qkv  = (const float*)d_in[1];
    const float* b_qkv  = (const float*)d_in[2];
    const float* w_proj = (const float*)d_in[3];
    const float* b_proj = (const float*)d_in[4];
    const float* w_dwc  = (const float*)d_in[5];
    const float* b_dwc  = (const float*)d_in[6];
    float* out = (float*)d_out;

    float *lin, *S, *A, *avpart, *partl, *av, *mid, *convout;
    __half *vph, *wc;
    __nv_bfloat16 *wqh, *wql, *wph, *wpl;
    cudaGetSymbolAddress((void**)&lin,     g_lin);
    cudaGetSymbolAddress((void**)&S,       g_S);
    cudaGetSymbolAddress((void**)&A,       g_A);
    cudaGetSymbolAddress((void**)&avpart,  g_avpart);
    cudaGetSymbolAddress((void**)&partl,   g_partl);
    cudaGetSymbolAddress((void**)&av,      g_av);
    cudaGetSymbolAddress((void**)&mid,     g_mid);
    cudaGetSymbolAddress((void**)&convout, g_conv);
    cudaGetSymbolAddress((void**)&vph,     g_vph);
    cudaGetSymbolAddress((void**)&wc,      g_wc);
    cudaGetSymbolAddress((void**)&wqh,     g_wqh);
    cudaGetSymbolAddress((void**)&wql,     g_wql);
    cudaGetSymbolAddress((void**)&wph,     g_wph);
    cudaGetSymbolAddress((void**)&wpl,     g_wpl);

    cudaFuncSetAttribute(gemm_conv_h, cudaFuncAttributeMaxDynamicSharedMemorySize, CSMEM_TOT);
    cudaFuncSetAttribute(gemm_fp32a,  cudaFuncAttributeMaxDynamicSharedMemorySize, SMEM_TOT);

    cudaStream_t side;
    cudaStreamCreateWithFlags(&side, cudaStreamNonBlocking);
    cudaEvent_t evLin, evConv;
    cudaEventCreateWithFlags(&evLin,  cudaEventDisableTiming);
    cudaEventCreateWithFlags(&evConv, cudaEventDisableTiming);

    // ---- side stream: weight prep (independent of main) starts at t=0 ----
    k_split<<<(256 * 256 + 255) / 256, 256, 0, side>>>(w_proj, wph, wpl, 256 * 256);
    k_wconv_h<<<(27 * 256 * 256) / 256, 256, 0, side>>>(w_dwc, wc);
    k_zero_b<<<(PVOL * CDIM / 2 + 255) / 256, 256, 0, side>>>((uint32_t*)vph, PVOL * CDIM / 2);

    // ---- main stream: w_qkv split + qkv GEMM (fp32 A, in-kernel bf16 split) ----
    k_split<<<(768 * 256 + 255) / 256, 256>>>(w_qkv, wqh, wql, 768 * 256);
    gemm_fp32a<<<dim3(6, 256), 256, SMEM_TOT>>>(x, (const float*)nullptr,
                                                wqh, wql, b_qkv, lin, 768);
    cudaEventRecord(evLin, 0);

    // ---- side stream: conv pipeline after lin ready ----
    cudaStreamWaitEvent(side, evLin, 0);
    k_vpadh<<<NTOK, 64, 0, side>>>(lin, vph);
    gemm_conv_h<<<dim3(2, 256), 256, CSMEM_TOT, side>>>(vph, wc, b_dwc, convout);
    cudaEventRecord(evConv, side);

    // ---- main stream: attention chain (concurrent with conv) ----
    k_pool<<<64, 256>>>(lin, A);
    k_S<<<dim3(128, 8), 256>>>(lin, A, S);
    k_agentv<<<dim3(64, 8), 256>>>(lin, S, avpart, partl);
    k_avreduce<<<64, 256>>>(avpart, partl, av);
    k_stage2<<<dim3(128, 8), 256>>>(lin, A, av, mid);

    // ---- join: proj GEMM reads mid + convout ----
    cudaStreamWaitEvent(0, evConv, 0);
    gemm_fp32a<<<dim3(2, 256), 256, SMEM_TOT>>>(mid, convout, wph, wpl, b_proj, out, 256);
}

// round 15
// speedup vs baseline: 1.8011x; 1.1064x over previous
#include <cuda_runtime.h>
#include <cuda_bf16.h>
#include <cuda_fp16.h>
#include <math.h>
#include <cstdint>

// ---------------- problem constants ----------------
#define NTOK 32768
#define CDIM 256
#define NHD  8
#define HD   32
#define AGN  64
#define PVOL (34*34*34)
#define KCONV (27*256)

// ---------------- scratch (device globals) ----------------
__device__ float g_lin[NTOK * 768];
__device__ __half g_S[NHD * AGN * NTOK];         // P = exp(scale*A.k), fp16
__device__ float g_A[AGN * CDIM];
__device__ float g_avpart[64 * NHD * AGN * HD];
__device__ float g_partl[64 * NHD * AGN];
__device__ float g_av[NHD * AGN * HD];
__device__ float g_mid[NTOK * CDIM];
__device__ float g_conv[NTOK * CDIM];
__device__ __half g_vph[PVOL * CDIM];            // fp16 v (padded volume)
__device__ __half g_wc[256 * KCONV];             // fp16 conv weights
__device__ __half g_wq16[768 * 256];             // fp16 qkv weights
__device__ __half g_wp16[256 * 256];             // fp16 proj weights

// ---------------- fast exp ----------------
__device__ __forceinline__ float fexp(float x) {
    float t = x * 1.4426950408889634f;
    int e = __float2int_rn(t);
    float f = t - (float)e;
    float p = 1.3333558e-3f;
    p = fmaf(p, f, 9.6181291e-3f);
    p = fmaf(p, f, 5.5504109e-2f);
    p = fmaf(p, f, 2.4022651e-1f);
    p = fmaf(p, f, 6.9314718e-1f);
    p = fmaf(p, f, 1.0f);
    return __int_as_float(__float_as_int(p) + (e << 23));
}

// ---------------- asm helpers ----------------
__device__ __forceinline__ uint32_t smem_u32(const void* p) {
    uint32_t a;
    asm("{ .reg .u64 t; cvta.to.shared.u64 t, %1; cvt.u32.u64 %0, t; }" : "=r"(a) : "l"(p));
    return a;
}
#define CP16(dst, src) \
    asm volatile("cp.async.cg.shared.global [%0], [%1], 16;" :: "r"(dst), "l"(src))
#define CP_COMMIT() asm volatile("cp.async.commit_group;")
#define CP_WAIT1()  asm volatile("cp.async.wait_group 1;")
#define CP_WAIT0()  asm volatile("cp.async.wait_group 0;")

#define LDSM4(r, addr) \
    asm volatile("ldmatrix.sync.aligned.m8n8.x4.shared.b16 {%0,%1,%2,%3}, [%4];" \
        : "=r"((r)[0]), "=r"((r)[1]), "=r"((r)[2]), "=r"((r)[3]) : "r"(addr))

#define MMA16816H(d, a, b0v, b1v) \
    asm volatile("mma.sync.aligned.m16n8k16.row.col.f32.f16.f16.f32 " \
        "{%0,%1,%2,%3}, {%4,%5,%6,%7}, {%8,%9}, {%0,%1,%2,%3};" \
        : "+f"((d)[0]), "+f"((d)[1]), "+f"((d)[2]), "+f"((d)[3]) \
        : "r"((a)[0]), "r"((a)[1]), "r"((a)[2]), "r"((a)[3]), "r"(b0v), "r"(b1v))

#define SW(o) ((o) ^ (((o) >> 3) & 0x70))

// ---------------- conversion kernels ----------------
__global__ void k_f2h(const float* __restrict__ w, __half* __restrict__ o, int n) {
    int i = blockIdx.x * 256 + threadIdx.x;
    if (i < n) o[i] = __float2half(w[i]);
}
__global__ void k_wconv_h(const float* __restrict__ w, __half* __restrict__ wc) {
    int i = blockIdx.x * 256 + threadIdx.x;     // 27*256*256
    int co = i / KCONV;
    int rem = i - co * KCONV;
    int tap = rem >> 8, ci = rem & 255;
    wc[i] = __float2half(w[(co * 256 + ci) * 27 + tap]);
}
__global__ void k_zero_b(uint32_t* __restrict__ p, int n) {
    int i = blockIdx.x * 256 + threadIdx.x;
    if (i < n) p[i] = 0u;
}
__global__ void k_vpadh(const float* __restrict__ lin, __half* __restrict__ hi) {
    const int n = blockIdx.x;
    const int c4 = threadIdx.x;     // 64
    const int x = n >> 10, y = (n >> 5) & 31, z = n & 31;
    const int p = ((x + 1) * 34 + (y + 1)) * 34 + (z + 1);
    float4 v = *(const float4*)&lin[(size_t)n * 768 + 512 + c4 * 4];
    __half2* hp = (__half2*)(hi + (size_t)p * 256 + c4 * 4);
    hp[0] = __floats2half2_rn(v.x, v.y);
    hp[1] = __floats2half2_rn(v.z, v.w);
}

// ---------------- conv GEMM: fp16 1-pass implicit GEMM ----------------
#define TIL 8192
#define CBUF 16384
#define CSMEM_TOT (3 * CBUF)
#define FBUF 24576
#define FSMEM_TOT (3 * FBUF)

__global__ void __launch_bounds__(256, 2) gemm_conv_h(
    const __half* __restrict__ Ah, const __half* __restrict__ B,
    const float* __restrict__ bias, float* __restrict__ C)
{
    extern __shared__ char smem[];
    const uint32_t sb = smem_u32(smem);
    const int t = threadIdx.x;
    const int m0 = blockIdx.y * 128, n0 = blockIdx.x * 128;
    const int seg = t & 3, r0 = t >> 2;
    const int wid = t >> 5, lane = t & 31;
    const int wy = wid >> 1, wx = wid & 1;
    const int lA_r = lane & 15, lA_k8 = (lane >> 4) & 1;
    const int lB_n = (lane & 7) + ((lane >> 4) & 1) * 8, lB_k8 = (lane >> 3) & 1;
    const int NC = KCONV >> 5;     // 216

    float acc[2][8][4];
#pragma unroll
    for (int i = 0; i < 2; i++)
#pragma unroll
        for (int j = 0; j < 8; j++)
#pragma unroll
            for (int q = 0; q < 4; q++) acc[i][j][q] = 0.0f;

    auto prefetch = [&](int c) {
        const uint32_t bb = sb + (c % 3) * CBUF;
        const int kc = c * 32;
        const int tap = kc >> 8;
        const int ci0 = kc & 255;
        const int dx = tap / 9 - 1, dy = (tap / 3) % 3 - 1, dz = tap % 3 - 1;
#pragma unroll
        for (int i = 0; i < 2; i++) {
            const int r = r0 + i * 64;
            const uint32_t so = SW(r * 64 + seg * 16);
            const int m = m0 + r;
            const int x = m >> 10, y = (m >> 5) & 31, z = m & 31;
            const size_t aoff =
                (size_t)(((x + 1 + dx) * 34 + (y + 1 + dy)) * 34 + (z + 1 + dz)) * 256
                + ci0 + seg * 8;
            CP16(bb + so, Ah + aoff);
            const size_t boff = (size_t)(n0 + r) * KCONV + kc + seg * 8;
            CP16(bb + TIL + so, B + boff);
        }
        CP_COMMIT();
    };

    prefetch(0);
    prefetch(1);
    for (int c = 0; c < NC; c++) {
        if (c + 1 < NC) CP_WAIT1(); else CP_WAIT0();
        __syncthreads();
        if (c + 2 < NC) prefetch(c + 2);
        const uint32_t bb = sb + (c % 3) * CBUF;
#pragma unroll
        for (int ks = 0; ks < 2; ks++) {
            const int chunk = ks * 32 + lA_k8 * 16;
            uint32_t ah[2][4];
#pragma unroll
            for (int mt = 0; mt < 2; mt++) {
                const uint32_t aaddr = bb + SW((wy * 32 + mt * 16 + lA_r) * 64 + chunk);
                LDSM4(ah[mt], aaddr);
            }
            const int bchunk = ks * 32 + lB_k8 * 16;
            uint32_t bf[4][4];
#pragma unroll
            for (int np = 0; np < 4; np++) {
                const uint32_t baddr = bb + TIL + SW((wx * 64 + np * 16 + lB_n) * 64 + bchunk);
                LDSM4(bf[np], baddr);
            }
#pragma unroll
            for (int mt = 0; mt < 2; mt++)
#pragma unroll
                for (int nt = 0; nt < 8; nt++) {
                    const uint32_t* bp = &bf[nt >> 1][(nt & 1) * 2];
                    MMA16816H(acc[mt][nt], ah[mt], bp[0], bp[1]);
                }
        }
    }

    const int er = lane >> 2, ec = (lane & 3) * 2;
#pragma unroll
    for (int mt = 0; mt < 2; mt++) {
        const int row = m0 + wy * 32 + mt * 16 + er;
#pragma unroll
        for (int nt = 0; nt < 8; nt++) {
            const int col = n0 + wx * 64 + nt * 8 + ec;
            const float b0 = __ldg(&bias[col]), b1 = __ldg(&bias[col + 1]);
            float* cp0 = C + (size_t)row * 256 + col;
            float* cp1 = C + (size_t)(row + 8) * 256 + col;
            cp0[0] = acc[mt][nt][0] + b0;
            cp0[1] = acc[mt][nt][1] + b1;
            cp1[0] = acc[mt][nt][2] + b0;
            cp1[1] = acc[mt][nt][3] + b1;
        }
    }
}

// ---------------- fp32-A fp16 2-pass GEMM: qkv / proj ----------------
// A = A0 (+A1), split to 2 fp16 limbs in-kernel; B single fp16. K=256.
__global__ void __launch_bounds__(256, 2) gemm_fp16a(
    const float* __restrict__ A0, const float* __restrict__ A1,
    const __half* __restrict__ B,
    const float* __restrict__ bias, float* __restrict__ C, int ldc)
{
    extern __shared__ char smem[];
    const uint32_t sb = smem_u32(smem);
    const int t = threadIdx.x;
    const int m0 = blockIdx.y * 128, n0 = blockIdx.x * 128;
    const int seg = t & 3, r0 = t >> 2;
    const int wid = t >> 5, lane = t & 31;
    const int wy = wid >> 1, wx = wid & 1;
    const int lA_r = lane & 15, lA_k8 = (lane >> 4) & 1;
    const int lB_n = (lane & 7) + ((lane >> 4) & 1) * 8, lB_k8 = (lane >> 3) & 1;
    const int NC = 8;      // K = 256

    float acc[2][8][4];
#pragma unroll
    for (int i = 0; i < 2; i++)
#pragma unroll
        for (int j = 0; j < 8; j++)
#pragma unroll
            for (int q = 0; q < 4; q++) acc[i][j][q] = 0.0f;

    auto prefetch = [&](int c) {
        const uint32_t bb = sb + (c % 3) * FBUF;
        const int kc = c * 32;
#pragma unroll
        for (int i = 0; i < 2; i++) {
            const int r = r0 + i * 64;
            const uint32_t so = SW(r * 64 + seg * 16);
            const size_t boff = (size_t)(n0 + r) * 256 + kc + seg * 8;
            CP16(bb + 2 * TIL + so, B + boff);
            const size_t aoff = (size_t)(m0 + r) * 256 + kc + seg * 8;
            float4 p0 = *(const float4*)(A0 + aoff);
            float4 q0 = *(const float4*)(A0 + aoff + 4);
            float v[8] = {p0.x, p0.y, p0.z, p0.w, q0.x, q0.y, q0.z, q0.w};
            if (A1) {
                const float4 p1 = *(const float4*)(A1 + aoff);
                const float4 q1 = *(const float4*)(A1 + aoff + 4);
                v[0] += p1.x; v[1] += p1.y; v[2] += p1.z; v[3] += p1.w;
                v[4] += q1.x; v[5] += q1.y; v[6] += q1.z; v[7] += q1.w;
            }
            uint32_t hw[4], lw[4];
#pragma unroll
            for (int j = 0; j < 4; j++) {
                __half h0 = __float2half(v[2 * j]);
                __half h1 = __float2half(v[2 * j + 1]);
                __half2 hh = __halves2half2(h0, h1);
                hw[j] = *(uint32_t*)&hh;
                __half l0 = __float2half(v[2 * j] - __half2float(h0));
                __half l1 = __float2half(v[2 * j + 1] - __half2float(h1));
                __half2 ll = __halves2half2(l0, l1);
                lw[j] = *(uint32_t*)&ll;
            }
            *(uint4*)(smem + (bb - sb) + so) = make_uint4(hw[0], hw[1], hw[2], hw[3]);
            *(uint4*)(smem + (bb - sb) + TIL + so) = make_uint4(lw[0], lw[1], lw[2], lw[3]);
        }
        CP_COMMIT();
    };

    prefetch(0);
    prefetch(1);
    for (int c = 0; c < NC; c++) {
        if (c + 1 < NC) CP_WAIT1(); else CP_WAIT0();
        __syncthreads();
        if (c + 2 < NC) prefetch(c + 2);
        const uint32_t bb = sb + (c % 3) * FBUF;
#pragma unroll
        for (int ks = 0; ks < 2; ks++) {
            const int chunk = ks * 32 + lA_k8 * 16;
            uint32_t ah[2][4], al[2][4];
#pragma unroll
            for (int mt = 0; mt < 2; mt++) {
                const uint32_t aaddr = bb + SW((wy * 32 + mt * 16 + lA_r) * 64 + chunk);
                LDSM4(ah[mt], aaddr);
                LDSM4(al[mt], aaddr + TIL);
            }
            const int bchunk = ks * 32 + lB_k8 * 16;
            uint32_t bf[4][4];
#pragma unroll
            for (int np = 0; np < 4; np++) {
                const uint32_t baddr = bb + 2 * TIL + SW((wx * 64 + np * 16 + lB_n) * 64 + bchunk);
                LDSM4(bf[np], baddr);
            }
            // pass 1: Ah * B
#pragma unroll
            for (int mt = 0; mt < 2; mt++)
#pragma unroll
                for (int nt = 0; nt < 8; nt++) {
                    const uint32_t* bp = &bf[nt >> 1][(nt & 1) * 2];
                    MMA16816H(acc[mt][nt], ah[mt], bp[0], bp[1]);
                }
            // pass 2: Al * B
#pragma unroll
            for (int mt = 0; mt < 2; mt++)
#pragma unroll
                for (int nt = 0; nt < 8; nt++) {
                    const uint32_t* bp = &bf[nt >> 1][(nt & 1) * 2];
                    MMA16816H(acc[mt][nt], al[mt], bp[0], bp[1]);
                }
        }
    }

    const int er = lane >> 2, ec = (lane & 3) * 2;
#pragma unroll
    for (int mt = 0; mt < 2; mt++) {
        const int row = m0 + wy * 32 + mt * 16 + er;
#pragma unroll
        for (int nt = 0; nt < 8; nt++) {
            const int col = n0 + wx * 64 + nt * 8 + ec;
            const float b0 = __ldg(&bias[col]), b1 = __ldg(&bias[col + 1]);
            float* cp0 = C + (size_t)row * ldc + col;
            float* cp1 = C + (size_t)(row + 8) * ldc + col;
            cp0[0] = acc[mt][nt][0] + b0;
            cp0[1] = acc[mt][nt][1] + b1;
            cp1[0] = acc[mt][nt][2] + b0;
            cp1[1] = acc[mt][nt][3] + b1;
        }
    }
}

// ---------------- attention kernels ----------------
__global__ void k_pool(const float* __restrict__ lin, float* __restrict__ A) {
    const int a = blockIdx.x;
    const int c = threadIdx.x;
    const int p1 = a >> 4, p2 = (a >> 2) & 3, p3 = a & 3;
    const int csub = c >> 5;
    float s = 0.0f;
    for (int b1 = 0; b1 < 8; b1++) {
        const int f1 = p1 * 8 + b1;
        const int ch = (f1 >> 2) * 32 + (c & 31);
        const int nb1 = (f1 & 3) * 8192;
        for (int b2 = 0; b2 < 8; b2++) {
            const int nb2 = nb1 + (p2 * 8 + b2) * 256;
            for (int b3 = 0; b3 < 8; b3++) {
                const int n = nb2 + (p3 * 8 + b3) * 8 + csub;
                s += lin[(size_t)n * 768 + ch];
            }
        }
    }
    A[a * 256 + c] = s * (1.0f / 512.0f);
}

// S[h][a][n] = fp16( exp(scale * A_h[a]·k_h[n]) )
__global__ void __launch_bounds__(256) k_S(const float* __restrict__ lin,
                                           const float* __restrict__ Amat,
                                           __half* __restrict__ S) {
    const int h = blockIdx.y;
    const int n = blockIdx.x * 256 + threadIdx.x;
    __shared__ float4 As[64][8];
    for (int e = threadIdx.x; e < 512; e += 256) {
        int a = e >> 3, dq = e & 7;
        As[a][dq] = *(const float4*)&Amat[a * 256 + h * 32 + dq * 4];
    }
    __syncthreads();
    float4 kv[8];
    const float* kp = lin + (size_t)n * 768 + 256 + h * 32;
#pragma unroll
    for (int i = 0; i < 8; i++) kv[i] = *(const float4*)&kp[i * 4];
    const float scale = 0.17677669529663687f;
    __half* Sp = S + (size_t)(h * 64) * NTOK + n;
#pragma unroll 4
    for (int a = 0; a < 64; a++) {
        float s = 0.0f;
#pragma unroll
        for (int i = 0; i < 8; i++) {
            const float4 av = As[a][i];
            s += kv[i].x * av.x + kv[i].y * av.y + kv[i].z * av.z + kv[i].w * av.w;
        }
        Sp[(size_t)a * NTOK] = __float2half(fexp(s * scale));
    }
}

// agent_v partials + per-agent sum of P (S in fp16, converted at smem load)
__global__ void __launch_bounds__(256) k_agentv(const float* __restrict__ lin,
                                                const __half* __restrict__ S,
                                                float* __restrict__ part,
                                                float* __restrict__ partl) {
    const int h = blockIdx.y;
    const int chunk = blockIdx.x;
    const int n0 = chunk * 512;
    __shared__ float Ss[64][64];
    __shared__ float vs[64][32];
    const int a = threadIdx.x >> 2, dg = threadIdx.x & 3;
    float4 acc0 = {0, 0, 0, 0}, acc1 = {0, 0, 0, 0};
    float accl = 0.0f;

    for (int sub = 0; sub < 8; sub++) {
        const int nb = n0 + sub * 64;
        for (int e = threadIdx.x; e < 512; e += 256) {
            int aa = e >> 3, tq = e & 7;
            uint4 raw = *(const uint4*)(S + (size_t)(h * 64 + aa) * NTOK + nb + tq * 8);
            const __half2* hp = (const __half2*)&raw;
            float2 f0 = __half22float2(hp[0]);
            float2 f1 = __half22float2(hp[1]);
            float2 f2 = __half22float2(hp[2]);
            float2 f3 = __half22float2(hp[3]);
            *(float4*)&Ss[aa][tq * 8]     = make_float4(f0.x, f0.y, f1.x, f1.y);
            *(float4*)&Ss[aa][tq * 8 + 4] = make_float4(f2.x, f2.y, f3.x, f3.y);
        }
        for (int e = threadIdx.x; e < 512; e += 256) {
            int tt = e >> 3, dq = e & 7;
            *(float4*)&vs[tt][dq * 4] =
                *(const float4*)&lin[(size_t)(nb + tt) * 768 + 512 + h * 32 + dq * 4];
        }
        __syncthreads();
#pragma unroll 8
        for (int tt = 0; tt < 64; tt++) {
            const float p = Ss[a][tt];
            accl += p;
            const float4 v0 = *(const float4*)&vs[tt][dg * 8];
            const float4 v1 = *(const float4*)&vs[tt][dg * 8 + 4];
            acc0.x += p * v0.x; acc0.y += p * v0.y; acc0.z += p * v0.z; acc0.w += p * v0.w;
            acc1.x += p * v1.x; acc1.y += p * v1.y; acc1.z += p * v1.z; acc1.w += p * v1.w;
        }
        __syncthreads();
    }
    float* pp = part + (size_t)((chunk * 8 + h) * 64 + a) * 32 + dg * 8;
    *(float4*)pp = acc0;
    *(float4*)(pp + 4) = acc1;
    if (dg == 0) partl[(chunk * 8 + h) * 64 + a] = accl;
}

__global__ void k_avreduce(const float* __restrict__ part, const float* __restrict__ partl,
                           float* __restrict__ av) {
    const int idx = blockIdx.x * 256 + threadIdx.x;      // 16384
    const int row = idx >> 5;                            // h*64+a
    float s = 0.0f, lsum = 0.0f;
    for (int ch = 0; ch < 64; ch++) {
        s += part[(size_t)ch * 16384 + idx];
        lsum += partl[ch * 512 + row];
    }
    av[idx] = s / lsum;
}

__global__ void __launch_bounds__(256) k_stage2(const float* __restrict__ lin,
                                                const float* __restrict__ Amat,
                                                const float* __restrict__ av,
                                                float* __restrict__ mid) {
    const int h = blockIdx.y;
    const int n = blockIdx.x * 256 + threadIdx.x;
    __shared__ float4 As[64][8];
    __shared__ float4 Vs[64][8];
    for (int e = threadIdx.x; e < 512; e += 256) {
        int a = e >> 3, dq = e & 7;
        As[a][dq] = *(const float4*)&Amat[a * 256 + h * 32 + dq * 4];
        Vs[a][dq] = *(const float4*)&av[(size_t)(h * 64 + a) * 32 + dq * 4];
    }
    __syncthreads();
    float4 qv[8];
    const float* qp = lin + (size_t)n * 768 + h * 32;
#pragma unroll
    for (int i = 0; i < 8; i++) qv[i] = *(const float4*)&qp[i * 4];
    const float scale = 0.17677669529663687f;
    float lg[64];
    float mx = -1e30f;
#pragma unroll
    for (int a = 0; a < 64; a++) {
        float s = 0.0f;
#pragma unroll
        for (int i = 0; i < 8; i++) {
            const float4 v = As[a][i];
            s += qv[i].x * v.x + qv[i].y * v.y + qv[i].z * v.z + qv[i].w * v.w;
        }
        s *= scale;
        lg[a] = s;
        mx = fmaxf(mx, s);
    }
    float sum = 0.0f;
#pragma unroll
    for (int a = 0; a < 64; a++) {
        const float p = fexp(lg[a] - mx);
        lg[a] = p;
        sum += p;
    }
    float4 o[8];
#pragma unroll
    for (int i = 0; i < 8; i++) { o[i].x = 0; o[i].y = 0; o[i].z = 0; o[i].w = 0; }
#pragma unroll
    for (int a = 0; a < 64; a++) {
        const float p = lg[a];
#pragma unroll
        for (int i = 0; i < 8; i++) {
            const float4 v = Vs[a][i];
            o[i].x += p * v.x; o[i].y += p * v.y; o[i].z += p * v.z; o[i].w += p * v.w;
        }
    }
    const float inv = 1.0f / sum;
    float* mp = mid + (size_t)h * 1048576 + n;
#pragma unroll
    for (int i = 0; i < 8; i++) {
        mp[(size_t)(i * 4 + 0) * NTOK] = o[i].x * inv;
        mp[(size_t)(i * 4 + 1) * NTOK] = o[i].y * inv;
        mp[(size_t)(i * 4 + 2) * NTOK] = o[i].z * inv;
        mp[(size_t)(i * 4 + 3) * NTOK] = o[i].w * inv;
    }
}

// ---------------- launch ----------------
extern "C" void kernel_launch(void* const* d_in, const int* in_sizes, int n_in,
                              void* d_out, int out_size) {
    const float* x      = (const float*)d_in[0];
    const float* w_qkv  = (const float*)d_in[1];
    const float* b_qkv  = (const float*)d_in[2];
    const float* w_proj = (const float*)d_in[3];
    const float* b_proj = (const float*)d_in[4];
    const float* w_dwc  = (const float*)d_in[5];
    const float* b_dwc  = (const float*)d_in[6];
    float* out = (float*)d_out;

    float *lin, *A, *avpart, *partl, *av, *mid, *convout;
    __half *S, *vph, *wc, *wq16, *wp16;
    cudaGetSymbolAddress((void**)&lin,     g_lin);
    cudaGetSymbolAddress((void**)&S,       g_S);
    cudaGetSymbolAddress((void**)&A,       g_A);
    cudaGetSymbolAddress((void**)&avpart,  g_avpart);
    cudaGetSymbolAddress((void**)&partl,   g_partl);
    cudaGetSymbolAddress((void**)&av,      g_av);
    cudaGetSymbolAddress((void**)&mid,     g_mid);
    cudaGetSymbolAddress((void**)&convout, g_conv);
    cudaGetSymbolAddress((void**)&vph,     g_vph);
    cudaGetSymbolAddress((void**)&wc,      g_wc);
    cudaGetSymbolAddress((void**)&wq16,    g_wq16);
    cudaGetSymbolAddress((void**)&wp16,    g_wp16);

    cudaFuncSetAttribute(gemm_conv_h, cudaFuncAttributeMaxDynamicSharedMemorySize, CSMEM_TOT);
    cudaFuncSetAttribute(gemm_fp16a,  cudaFuncAttributeMaxDynamicSharedMemorySize, FSMEM_TOT);

    cudaStream_t side;
    cudaStreamCreateWithFlags(&side, cudaStreamNonBlocking);
    cudaEvent_t evLin, evConv;
    cudaEventCreateWithFlags(&evLin,  cudaEventDisableTiming);
    cudaEventCreateWithFlags(&evConv, cudaEventDisableTiming);

    // ---- side stream: weight prep (independent of main) starts at t=0 ----
    k_f2h<<<(256 * 256 + 255) / 256, 256, 0, side>>>(w_proj, wp16, 256 * 256);
    k_wconv_h<<<(27 * 256 * 256) / 256, 256, 0, side>>>(w_dwc, wc);
    k_zero_b<<<(PVOL * CDIM / 2 + 255) / 256, 256, 0, side>>>((uint32_t*)vph, PVOL * CDIM / 2);

    // ---- main stream: w_qkv convert + qkv GEMM (fp32 A split to fp16 limbs) ----
    k_f2h<<<(768 * 256 + 255) / 256, 256>>>(w_qkv, wq16, 768 * 256);
    gemm_fp16a<<<dim3(6, 256), 256, FSMEM_TOT>>>(x, (const float*)nullptr,
                                                 wq16, b_qkv, lin, 768);
    cudaEventRecord(evLin, 0);

    // ---- side stream: conv pipeline after lin ready ----
    cudaStreamWaitEvent(side, evLin, 0);
    k_vpadh<<<NTOK, 64, 0, side>>>(lin, vph);
    gemm_conv_h<<<dim3(2, 256), 256, CSMEM_TOT, side>>>(vph, wc, b_dwc, convout);
    cudaEventRecord(evConv, side);

    // ---- main stream: attention chain (concurrent with conv) ----
    k_pool<<<64, 256>>>(lin, A);
    k_S<<<dim3(128, 8), 256>>>(lin, A, S);
    k_agentv<<<dim3(64, 8), 256>>>(lin, S, avpart, partl);
    k_avreduce<<<64, 256>>>(avpart, partl, av);
    k_stage2<<<dim3(128, 8), 256>>>(lin, A, av, mid);

    // ---- join: proj GEMM reads mid + convout ----
    cudaStreamWaitEvent(0, evConv, 0);
    gemm_fp16a<<<dim3(2, 256), 256, FSMEM_TOT>>>(mid, convout, wp16, b_proj, out, 256);
}

// round 16
// speedup vs baseline: 1.8781x; 1.0428x over previous
#include <cuda_runtime.h>
#include <cuda_bf16.h>
#include <cuda_fp16.h>
#include <math.h>
#include <cstdint>

// ---------------- problem constants ----------------
#define NTOK 32768
#define CDIM 256
#define NHD  8
#define HD   32
#define AGN  64
#define PVOL (34*34*34)
#define KCONV (27*256)

// ---------------- scratch (device globals) ----------------
__device__ float g_lin[NTOK * 768];
__device__ __half g_S[NHD * AGN * NTOK];         // P = exp(scale*A.k), fp16
__device__ float g_A[AGN * CDIM];
__device__ float g_avpart[64 * NHD * AGN * HD];
__device__ float g_partl[64 * NHD * AGN];
__device__ float g_av[NHD * AGN * HD];
__device__ float g_mid[NTOK * CDIM];
__device__ float g_conv[NTOK * CDIM];
__device__ __half g_vph[PVOL * CDIM];            // fp16 v (padded volume)
__device__ __half g_wc[256 * KCONV];             // fp16 conv weights
__device__ __half g_wq16[768 * 256];             // fp16 qkv weights
__device__ __half g_wp16[256 * 256];             // fp16 proj weights

// ---------------- fast exp ----------------
__device__ __forceinline__ float fexp(float x) {
    float t = x * 1.4426950408889634f;
    int e = __float2int_rn(t);
    float f = t - (float)e;
    float p = 1.3333558e-3f;
    p = fmaf(p, f, 9.6181291e-3f);
    p = fmaf(p, f, 5.5504109e-2f);
    p = fmaf(p, f, 2.4022651e-1f);
    p = fmaf(p, f, 6.9314718e-1f);
    p = fmaf(p, f, 1.0f);
    return __int_as_float(__float_as_int(p) + (e << 23));
}

// ---------------- asm helpers ----------------
__device__ __forceinline__ uint32_t smem_u32(const void* p) {
    uint32_t a;
    asm("{ .reg .u64 t; cvta.to.shared.u64 t, %1; cvt.u32.u64 %0, t; }" : "=r"(a) : "l"(p));
    return a;
}
#define CP16(dst, src) \
    asm volatile("cp.async.cg.shared.global [%0], [%1], 16;" :: "r"(dst), "l"(src))
#define CP_COMMIT() asm volatile("cp.async.commit_group;")
#define CP_WAIT1()  asm volatile("cp.async.wait_group 1;")
#define CP_WAIT0()  asm volatile("cp.async.wait_group 0;")

#define LDSM4(r, addr) \
    asm volatile("ldmatrix.sync.aligned.m8n8.x4.shared.b16 {%0,%1,%2,%3}, [%4];" \
        : "=r"((r)[0]), "=r"((r)[1]), "=r"((r)[2]), "=r"((r)[3]) : "r"(addr))

#define MMA16816H(d, a, b0v, b1v) \
    asm volatile("mma.sync.aligned.m16n8k16.row.col.f32.f16.f16.f32 " \
        "{%0,%1,%2,%3}, {%4,%5,%6,%7}, {%8,%9}, {%0,%1,%2,%3};" \
        : "+f"((d)[0]), "+f"((d)[1]), "+f"((d)[2]), "+f"((d)[3]) \
        : "r"((a)[0]), "r"((a)[1]), "r"((a)[2]), "r"((a)[3]), "r"(b0v), "r"(b1v))

#define SW(o) ((o) ^ (((o) >> 3) & 0x70))

// ---------------- conversion kernels ----------------
__global__ void k_f2h(const float* __restrict__ w, __half* __restrict__ o, int n) {
    int i = blockIdx.x * 256 + threadIdx.x;
    if (i < n) o[i] = __float2half(w[i]);
}
__global__ void k_wconv_h(const float* __restrict__ w, __half* __restrict__ wc) {
    int i = blockIdx.x * 256 + threadIdx.x;     // 27*256*256
    int co = i / KCONV;
    int rem = i - co * KCONV;
    int tap = rem >> 8, ci = rem & 255;
    wc[i] = __float2half(w[(co * 256 + ci) * 27 + tap]);
}
__global__ void k_zero_b(uint32_t* __restrict__ p, int n) {
    int i = blockIdx.x * 256 + threadIdx.x;
    if (i < n) p[i] = 0u;
}
__global__ void k_vpadh(const float* __restrict__ lin, __half* __restrict__ hi) {
    const int n = blockIdx.x;
    const int c4 = threadIdx.x;     // 64
    const int x = n >> 10, y = (n >> 5) & 31, z = n & 31;
    const int p = ((x + 1) * 34 + (y + 1)) * 34 + (z + 1);
    float4 v = *(const float4*)&lin[(size_t)n * 768 + 512 + c4 * 4];
    __half2* hp = (__half2*)(hi + (size_t)p * 256 + c4 * 4);
    hp[0] = __floats2half2_rn(v.x, v.y);
    hp[1] = __floats2half2_rn(v.z, v.w);
}

// ---------------- conv GEMM: fp16 1-pass implicit GEMM ----------------
#define TIL 8192
#define CBUF 16384
#define CSMEM_TOT (3 * CBUF)
#define FBUF 24576
#define FSMEM_TOT (3 * FBUF)

__global__ void __launch_bounds__(256, 2) gemm_conv_h(
    const __half* __restrict__ Ah, const __half* __restrict__ B,
    const float* __restrict__ bias, float* __restrict__ C)
{
    extern __shared__ char smem[];
    const uint32_t sb = smem_u32(smem);
    const int t = threadIdx.x;
    const int m0 = blockIdx.y * 128, n0 = blockIdx.x * 128;
    const int seg = t & 3, r0 = t >> 2;
    const int wid = t >> 5, lane = t & 31;
    const int wy = wid >> 1, wx = wid & 1;
    const int lA_r = lane & 15, lA_k8 = (lane >> 4) & 1;
    const int lB_n = (lane & 7) + ((lane >> 4) & 1) * 8, lB_k8 = (lane >> 3) & 1;
    const int NC = KCONV >> 5;     // 216

    float acc[2][8][4];
#pragma unroll
    for (int i = 0; i < 2; i++)
#pragma unroll
        for (int j = 0; j < 8; j++)
#pragma unroll
            for (int q = 0; q < 4; q++) acc[i][j][q] = 0.0f;

    auto prefetch = [&](int c) {
        const uint32_t bb = sb + (c % 3) * CBUF;
        const int kc = c * 32;
        const int tap = kc >> 8;
        const int ci0 = kc & 255;
        const int dx = tap / 9 - 1, dy = (tap / 3) % 3 - 1, dz = tap % 3 - 1;
#pragma unroll
        for (int i = 0; i < 2; i++) {
            const int r = r0 + i * 64;
            const uint32_t so = SW(r * 64 + seg * 16);
            const int m = m0 + r;
            const int x = m >> 10, y = (m >> 5) & 31, z = m & 31;
            const size_t aoff =
                (size_t)(((x + 1 + dx) * 34 + (y + 1 + dy)) * 34 + (z + 1 + dz)) * 256
                + ci0 + seg * 8;
            CP16(bb + so, Ah + aoff);
            const size_t boff = (size_t)(n0 + r) * KCONV + kc + seg * 8;
            CP16(bb + TIL + so, B + boff);
        }
        CP_COMMIT();
    };

    prefetch(0);
    prefetch(1);
    for (int c = 0; c < NC; c++) {
        if (c + 1 < NC) CP_WAIT1(); else CP_WAIT0();
        __syncthreads();
        if (c + 2 < NC) prefetch(c + 2);
        const uint32_t bb = sb + (c % 3) * CBUF;
#pragma unroll
        for (int ks = 0; ks < 2; ks++) {
            const int chunk = ks * 32 + lA_k8 * 16;
            uint32_t ah[2][4];
#pragma unroll
            for (int mt = 0; mt < 2; mt++) {
                const uint32_t aaddr = bb + SW((wy * 32 + mt * 16 + lA_r) * 64 + chunk);
                LDSM4(ah[mt], aaddr);
            }
            const int bchunk = ks * 32 + lB_k8 * 16;
            uint32_t bf[4][4];
#pragma unroll
            for (int np = 0; np < 4; np++) {
                const uint32_t baddr = bb + TIL + SW((wx * 64 + np * 16 + lB_n) * 64 + bchunk);
                LDSM4(bf[np], baddr);
            }
#pragma unroll
            for (int mt = 0; mt < 2; mt++)
#pragma unroll
                for (int nt = 0; nt < 8; nt++) {
                    const uint32_t* bp = &bf[nt >> 1][(nt & 1) * 2];
                    MMA16816H(acc[mt][nt], ah[mt], bp[0], bp[1]);
                }
        }
    }

    const int er = lane >> 2, ec = (lane & 3) * 2;
#pragma unroll
    for (int mt = 0; mt < 2; mt++) {
        const int row = m0 + wy * 32 + mt * 16 + er;
#pragma unroll
        for (int nt = 0; nt < 8; nt++) {
            const int col = n0 + wx * 64 + nt * 8 + ec;
            const float b0 = __ldg(&bias[col]), b1 = __ldg(&bias[col + 1]);
            float* cp0 = C + (size_t)row * 256 + col;
            float* cp1 = C + (size_t)(row + 8) * 256 + col;
            cp0[0] = acc[mt][nt][0] + b0;
            cp0[1] = acc[mt][nt][1] + b1;
            cp1[0] = acc[mt][nt][2] + b0;
            cp1[1] = acc[mt][nt][3] + b1;
        }
    }
}

// ---------------- fp32-A fp16 GEMM (npass = 1 or 2): qkv / proj ----------------
__global__ void __launch_bounds__(256, 2) gemm_fp16a(
    const float* __restrict__ A0, const float* __restrict__ A1,
    const __half* __restrict__ B,
    const float* __restrict__ bias, float* __restrict__ C, int ldc, int npass)
{
    extern __shared__ char smem[];
    const uint32_t sb = smem_u32(smem);
    const int t = threadIdx.x;
    const int m0 = blockIdx.y * 128, n0 = blockIdx.x * 128;
    const int seg = t & 3, r0 = t >> 2;
    const int wid = t >> 5, lane = t & 31;
    const int wy = wid >> 1, wx = wid & 1;
    const int lA_r = lane & 15, lA_k8 = (lane >> 4) & 1;
    const int lB_n = (lane & 7) + ((lane >> 4) & 1) * 8, lB_k8 = (lane >> 3) & 1;
    const int NC = 8;      // K = 256

    float acc[2][8][4];
#pragma unroll
    for (int i = 0; i < 2; i++)
#pragma unroll
        for (int j = 0; j < 8; j++)
#pragma unroll
            for (int q = 0; q < 4; q++) acc[i][j][q] = 0.0f;

    auto prefetch = [&](int c) {
        const uint32_t bb = sb + (c % 3) * FBUF;
        const int kc = c * 32;
#pragma unroll
        for (int i = 0; i < 2; i++) {
            const int r = r0 + i * 64;
            const uint32_t so = SW(r * 64 + seg * 16);
            const size_t boff = (size_t)(n0 + r) * 256 + kc + seg * 8;
            CP16(bb + 2 * TIL + so, B + boff);
            const size_t aoff = (size_t)(m0 + r) * 256 + kc + seg * 8;
            float4 p0 = *(const float4*)(A0 + aoff);
            float4 q0 = *(const float4*)(A0 + aoff + 4);
            float v[8] = {p0.x, p0.y, p0.z, p0.w, q0.x, q0.y, q0.z, q0.w};
            if (A1) {
                const float4 p1 = *(const float4*)(A1 + aoff);
                const float4 q1 = *(const float4*)(A1 + aoff + 4);
                v[0] += p1.x; v[1] += p1.y; v[2] += p1.z; v[3] += p1.w;
                v[4] += q1.x; v[5] += q1.y; v[6] += q1.z; v[7] += q1.w;
            }
            uint32_t hw[4], lw[4];
#pragma unroll
            for (int j = 0; j < 4; j++) {
                __half h0 = __float2half(v[2 * j]);
                __half h1 = __float2half(v[2 * j + 1]);
                __half2 hh = __halves2half2(h0, h1);
                hw[j] = *(uint32_t*)&hh;
                __half l0 = __float2half(v[2 * j] - __half2float(h0));
                __half l1 = __float2half(v[2 * j + 1] - __half2float(h1));
                __half2 ll = __halves2half2(l0, l1);
                lw[j] = *(uint32_t*)&ll;
            }
            *(uint4*)(smem + (bb - sb) + so) = make_uint4(hw[0], hw[1], hw[2], hw[3]);
            *(uint4*)(smem + (bb - sb) + TIL + so) = make_uint4(lw[0], lw[1], lw[2], lw[3]);
        }
        CP_COMMIT();
    };

    prefetch(0);
    prefetch(1);
    for (int c = 0; c < NC; c++) {
        if (c + 1 < NC) CP_WAIT1(); else CP_WAIT0();
        __syncthreads();
        if (c + 2 < NC) prefetch(c + 2);
        const uint32_t bb = sb + (c % 3) * FBUF;
#pragma unroll
        for (int ks = 0; ks < 2; ks++) {
            const int chunk = ks * 32 + lA_k8 * 16;
            uint32_t ah[2][4];
#pragma unroll
            for (int mt = 0; mt < 2; mt++) {
                const uint32_t aaddr = bb + SW((wy * 32 + mt * 16 + lA_r) * 64 + chunk);
                LDSM4(ah[mt], aaddr);
            }
            const int bchunk = ks * 32 + lB_k8 * 16;
            uint32_t bf[4][4];
#pragma unroll
            for (int np = 0; np < 4; np++) {
                const uint32_t baddr = bb + 2 * TIL + SW((wx * 64 + np * 16 + lB_n) * 64 + bchunk);
                LDSM4(bf[np], baddr);
            }
            // pass 1: Ah * B
#pragma unroll
            for (int mt = 0; mt < 2; mt++)
#pragma unroll
                for (int nt = 0; nt < 8; nt++) {
                    const uint32_t* bp = &bf[nt >> 1][(nt & 1) * 2];
                    MMA16816H(acc[mt][nt], ah[mt], bp[0], bp[1]);
                }
            // pass 2 (optional): Al * B
            if (npass == 2) {
                uint32_t al[2][4];
#pragma unroll
                for (int mt = 0; mt < 2; mt++) {
                    const uint32_t aaddr = bb + SW((wy * 32 + mt * 16 + lA_r) * 64 + chunk);
                    LDSM4(al[mt], aaddr + TIL);
                }
#pragma unroll
                for (int mt = 0; mt < 2; mt++)
#pragma unroll
                    for (int nt = 0; nt < 8; nt++) {
                        const uint32_t* bp = &bf[nt >> 1][(nt & 1) * 2];
                        MMA16816H(acc[mt][nt], al[mt], bp[0], bp[1]);
                    }
            }
        }
    }

    const int er = lane >> 2, ec = (lane & 3) * 2;
#pragma unroll
    for (int mt = 0; mt < 2; mt++) {
        const int row = m0 + wy * 32 + mt * 16 + er;
#pragma unroll
        for (int nt = 0; nt < 8; nt++) {
            const int col = n0 + wx * 64 + nt * 8 + ec;
            const float b0 = __ldg(&bias[col]), b1 = __ldg(&bias[col + 1]);
            float* cp0 = C + (size_t)row * ldc + col;
            float* cp1 = C + (size_t)(row + 8) * ldc + col;
            cp0[0] = acc[mt][nt][0] + b0;
            cp0[1] = acc[mt][nt][1] + b1;
            cp1[0] = acc[mt][nt][2] + b0;
            cp1[1] = acc[mt][nt][3] + b1;
        }
    }
}

// ---------------- attention kernels ----------------
__global__ void k_pool(const float* __restrict__ lin, float* __restrict__ A) {
    const int a = blockIdx.x;
    const int c = threadIdx.x;
    const int p1 = a >> 4, p2 = (a >> 2) & 3, p3 = a & 3;
    const int csub = c >> 5;
    float s = 0.0f;
    for (int b1 = 0; b1 < 8; b1++) {
        const int f1 = p1 * 8 + b1;
        const int ch = (f1 >> 2) * 32 + (c & 31);
        const int nb1 = (f1 & 3) * 8192;
        for (int b2 = 0; b2 < 8; b2++) {
            const int nb2 = nb1 + (p2 * 8 + b2) * 256;
            for (int b3 = 0; b3 < 8; b3++) {
                const int n = nb2 + (p3 * 8 + b3) * 8 + csub;
                s += lin[(size_t)n * 768 + ch];
            }
        }
    }
    A[a * 256 + c] = s * (1.0f / 512.0f);
}

__global__ void __launch_bounds__(256) k_S(const float* __restrict__ lin,
                                           const float* __restrict__ Amat,
                                           __half* __restrict__ S) {
    const int h = blockIdx.y;
    const int n = blockIdx.x * 256 + threadIdx.x;
    __shared__ float4 As[64][8];
    for (int e = threadIdx.x; e < 512; e += 256) {
        int a = e >> 3, dq = e & 7;
        As[a][dq] = *(const float4*)&Amat[a * 256 + h * 32 + dq * 4];
    }
    __syncthreads();
    float4 kv[8];
    const float* kp = lin + (size_t)n * 768 + 256 + h * 32;
#pragma unroll
    for (int i = 0; i < 8; i++) kv[i] = *(const float4*)&kp[i * 4];
    const float scale = 0.17677669529663687f;
    __half* Sp = S + (size_t)(h * 64) * NTOK + n;
#pragma unroll 4
    for (int a = 0; a < 64; a++) {
        float s = 0.0f;
#pragma unroll
        for (int i = 0; i < 8; i++) {
            const float4 av = As[a][i];
            s += kv[i].x * av.x + kv[i].y * av.y + kv[i].z * av.z + kv[i].w * av.w;
        }
        Sp[(size_t)a * NTOK] = __float2half(fexp(s * scale));
    }
}

// agent_v partials + per-agent sum of P (Ss padded to stride 68: bank-conflict-free)
__global__ void __launch_bounds__(256) k_agentv(const float* __restrict__ lin,
                                                const __half* __restrict__ S,
                                                float* __restrict__ part,
                                                float* __restrict__ partl) {
    const int h = blockIdx.y;
    const int chunk = blockIdx.x;
    const int n0 = chunk * 512;
    __shared__ float Ss[64][68];
    __shared__ float vs[64][32];
    const int a = threadIdx.x >> 2, dg = threadIdx.x & 3;
    float4 acc0 = {0, 0, 0, 0}, acc1 = {0, 0, 0, 0};
    float accl = 0.0f;

    for (int sub = 0; sub < 8; sub++) {
        const int nb = n0 + sub * 64;
        for (int e = threadIdx.x; e < 512; e += 256) {
            int aa = e >> 3, tq = e & 7;
            uint4 raw = *(const uint4*)(S + (size_t)(h * 64 + aa) * NTOK + nb + tq * 8);
            const __half2* hp = (const __half2*)&raw;
            float2 f0 = __half22float2(hp[0]);
            float2 f1 = __half22float2(hp[1]);
            float2 f2 = __half22float2(hp[2]);
            float2 f3 = __half22float2(hp[3]);
            *(float4*)&Ss[aa][tq * 8]     = make_float4(f0.x, f0.y, f1.x, f1.y);
            *(float4*)&Ss[aa][tq * 8 + 4] = make_float4(f2.x, f2.y, f3.x, f3.y);
        }
        for (int e = threadIdx.x; e < 512; e += 256) {
            int tt = e >> 3, dq = e & 7;
            *(float4*)&vs[tt][dq * 4] =
                *(const float4*)&lin[(size_t)(nb + tt) * 768 + 512 + h * 32 + dq * 4];
        }
        __syncthreads();
#pragma unroll 8
        for (int tt = 0; tt < 64; tt++) {
            const float p = Ss[a][tt];
            accl += p;
            const float4 v0 = *(const float4*)&vs[tt][dg * 8];
            const float4 v1 = *(const float4*)&vs[tt][dg * 8 + 4];
            acc0.x += p * v0.x; acc0.y += p * v0.y; acc0.z += p * v0.z; acc0.w += p * v0.w;
            acc1.x += p * v1.x; acc1.y += p * v1.y; acc1.z += p * v1.z; acc1.w += p * v1.w;
        }
        __syncthreads();
    }
    float* pp = part + (size_t)((chunk * 8 + h) * 64 + a) * 32 + dg * 8;
    *(float4*)pp = acc0;
    *(float4*)(pp + 4) = acc1;
    if (dg == 0) partl[(chunk * 8 + h) * 64 + a] = accl;
}

__global__ void k_avreduce(const float* __restrict__ part, const float* __restrict__ partl,
                           float* __restrict__ av) {
    const int idx = blockIdx.x * 256 + threadIdx.x;      // 16384
    const int row = idx >> 5;                            // h*64+a
    float s = 0.0f, lsum = 0.0f;
    for (int ch = 0; ch < 64; ch++) {
        s += part[(size_t)ch * 16384 + idx];
        lsum += partl[ch * 512 + row];
    }
    av[idx] = s / lsum;
}

__global__ void __launch_bounds__(256) k_stage2(const float* __restrict__ lin,
                                                const float* __restrict__ Amat,
                                                const float* __restrict__ av,
                                                float* __restrict__ mid) {
    const int h = blockIdx.y;
    const int n = blockIdx.x * 256 + threadIdx.x;
    __shared__ float4 As[64][8];
    __shared__ float4 Vs[64][8];
    for (int e = threadIdx.x; e < 512; e += 256) {
        int a = e >> 3, dq = e & 7;
        As[a][dq] = *(const float4*)&Amat[a * 256 + h * 32 + dq * 4];
        Vs[a][dq] = *(const float4*)&av[(size_t)(h * 64 + a) * 32 + dq * 4];
    }
    __syncthreads();
    float4 qv[8];
    const float* qp = lin + (size_t)n * 768 + h * 32;
#pragma unroll
    for (int i = 0; i < 8; i++) qv[i] = *(const float4*)&qp[i * 4];
    const float scale = 0.17677669529663687f;
    float lg[64];
    float mx = -1e30f;
#pragma unroll
    for (int a = 0; a < 64; a++) {
        float s = 0.0f;
#pragma unroll
        for (int i = 0; i < 8; i++) {
            const float4 v = As[a][i];
            s += qv[i].x * v.x + qv[i].y * v.y + qv[i].z * v.z + qv[i].w * v.w;
        }
        s *= scale;
        lg[a] = s;
        mx = fmaxf(mx, s);
    }
    float sum = 0.0f;
#pragma unroll
    for (int a = 0; a < 64; a++) {
        const float p = fexp(lg[a] - mx);
        lg[a] = p;
        sum += p;
    }
    float4 o[8];
#pragma unroll
    for (int i = 0; i < 8; i++) { o[i].x = 0; o[i].y = 0; o[i].z = 0; o[i].w = 0; }
#pragma unroll
    for (int a = 0; a < 64; a++) {
        const float p = lg[a];
#pragma unroll
        for (int i = 0; i < 8; i++) {
            const float4 v = Vs[a][i];
            o[i].x += p * v.x; o[i].y += p * v.y; o[i].z += p * v.z; o[i].w += p * v.w;
        }
    }
    const float inv = 1.0f / sum;
    float* mp = mid + (size_t)h * 1048576 + n;
#pragma unroll
    for (int i = 0; i < 8; i++) {
        mp[(size_t)(i * 4 + 0) * NTOK] = o[i].x * inv;
        mp[(size_t)(i * 4 + 1) * NTOK] = o[i].y * inv;
        mp[(size_t)(i * 4 + 2) * NTOK] = o[i].z * inv;
        mp[(size_t)(i * 4 + 3) * NTOK] = o[i].w * inv;
    }
}

// ---------------- launch ----------------
extern "C" void kernel_launch(void* const* d_in, const int* in_sizes, int n_in,
                              void* d_out, int out_size) {
    const float* x      = (const float*)d_in[0];
    const float* w_qkv  = (const float*)d_in[1];
    const float* b_qkv  = (const float*)d_in[2];
    const float* w_proj = (const float*)d_in[3];
    const float* b_proj = (const float*)d_in[4];
    const float* w_dwc  = (const float*)d_in[5];
    const float* b_dwc  = (const float*)d_in[6];
    float* out = (float*)d_out;

    float *lin, *A, *avpart, *partl, *av, *mid, *convout;
    __half *S, *vph, *wc, *wq16, *wp16;
    cudaGetSymbolAddress((void**)&lin,     g_lin);
    cudaGetSymbolAddress((void**)&S,       g_S);
    cudaGetSymbolAddress((void**)&A,       g_A);
    cudaGetSymbolAddress((void**)&avpart,  g_avpart);
    cudaGetSymbolAddress((void**)&partl,   g_partl);
    cudaGetSymbolAddress((void**)&av,      g_av);
    cudaGetSymbolAddress((void**)&mid,     g_mid);
    cudaGetSymbolAddress((void**)&convout, g_conv);
    cudaGetSymbolAddress((void**)&vph,     g_vph);
    cudaGetSymbolAddress((void**)&wc,      g_wc);
    cudaGetSymbolAddress((void**)&wq16,    g_wq16);
    cudaGetSymbolAddress((void**)&wp16,    g_wp16);

    cudaFuncSetAttribute(gemm_conv_h, cudaFuncAttributeMaxDynamicSharedMemorySize, CSMEM_TOT);
    cudaFuncSetAttribute(gemm_fp16a,  cudaFuncAttributeMaxDynamicSharedMemorySize, FSMEM_TOT);

    cudaStream_t side;
    cudaStreamCreateWithFlags(&side, cudaStreamNonBlocking);
    cudaEvent_t evLin, evConv;
    cudaEventCreateWithFlags(&evLin,  cudaEventDisableTiming);
    cudaEventCreateWithFlags(&evConv, cudaEventDisableTiming);

    // ---- side stream: weight prep starts at t=0 ----
    k_f2h<<<(256 * 256 + 255) / 256, 256, 0, side>>>(w_proj, wp16, 256 * 256);
    k_wconv_h<<<(27 * 256 * 256) / 256, 256, 0, side>>>(w_dwc, wc);
    k_zero_b<<<(PVOL * CDIM / 2 + 255) / 256, 256, 0, side>>>((uint32_t*)vph, PVOL * CDIM / 2);

    // ---- main stream: w_qkv convert + qkv GEMM (fp16 1-pass) ----
    k_f2h<<<(768 * 256 + 255) / 256, 256>>>(w_qkv, wq16, 768 * 256);
    gemm_fp16a<<<dim3(6, 256), 256, FSMEM_TOT>>>(x, (const float*)nullptr,
                                                 wq16, b_qkv, lin, 768, 1);
    cudaEventRecord(evLin, 0);

    // ---- side stream: conv pipeline after lin ready ----
    cudaStreamWaitEvent(side, evLin, 0);
    k_vpadh<<<NTOK, 64, 0, side>>>(lin, vph);
    gemm_conv_h<<<dim3(2, 256), 256, CSMEM_TOT, side>>>(vph, wc, b_dwc, convout);
    cudaEventRecord(evConv, side);

    // ---- main stream: attention chain (concurrent with conv) ----
    k_pool<<<64, 256>>>(lin, A);
    k_S<<<dim3(128, 8), 256>>>(lin, A, S);
    k_agentv<<<dim3(64, 8), 256>>>(lin, S, avpart, partl);
    k_avreduce<<<64, 256>>>(avpart, partl, av);
    k_stage2<<<dim3(128, 8), 256>>>(lin, A, av, mid);

    // ---- join: proj GEMM (fp16 2-pass) reads mid + convout ----
    cudaStreamWaitEvent(0, evConv, 0);
    gemm_fp16a<<<dim3(2, 256), 256, FSMEM_TOT>>>(mid, convout, wp16, b_proj, out, 256, 2);
}

// round 17
// speedup vs baseline: 2.0313x; 1.0815x over previous
#include <cuda_runtime.h>
#include <cuda_bf16.h>
#include <cuda_fp16.h>
#include <math.h>
#include <cstdint>

// ---------------- problem constants ----------------
#define NTOK 32768
#define CDIM 256
#define NHD  8
#define HD   32
#define AGN  64
#define PVOL (34*34*34)
#define KCONV (27*256)

// ---------------- scratch (device globals) ----------------
__device__ float g_lin[NTOK * 768];
__device__ __half g_S[NHD * AGN * NTOK];         // P = exp(scale*A.k), fp16
__device__ float g_A[AGN * CDIM];
__device__ float g_avpart[64 * NHD * AGN * HD];
__device__ float g_partl[64 * NHD * AGN];
__device__ float g_av[NHD * AGN * HD];
__device__ float g_mid[NTOK * CDIM];
__device__ float g_conv[NTOK * CDIM];
__device__ __half g_vph[PVOL * CDIM];            // fp16 v (padded volume)
__device__ __half g_wc[256 * KCONV];             // fp16 conv weights
__device__ __half g_wq16[768 * 256];             // fp16 qkv weights
__device__ __half g_wp16[256 * 256];             // fp16 proj weights

// ---------------- fast exp ----------------
__device__ __forceinline__ float fexp(float x) {
    float t = x * 1.4426950408889634f;
    int e = __float2int_rn(t);
    float f = t - (float)e;
    float p = 1.3333558e-3f;
    p = fmaf(p, f, 9.6181291e-3f);
    p = fmaf(p, f, 5.5504109e-2f);
    p = fmaf(p, f, 2.4022651e-1f);
    p = fmaf(p, f, 6.9314718e-1f);
    p = fmaf(p, f, 1.0f);
    return __int_as_float(__float_as_int(p) + (e << 23));
}

// ---------------- asm helpers ----------------
__device__ __forceinline__ uint32_t smem_u32(const void* p) {
    uint32_t a;
    asm("{ .reg .u64 t; cvta.to.shared.u64 t, %1; cvt.u32.u64 %0, t; }" : "=r"(a) : "l"(p));
    return a;
}
#define CP16(dst, src) \
    asm volatile("cp.async.cg.shared.global [%0], [%1], 16;" :: "r"(dst), "l"(src))
#define CP_COMMIT() asm volatile("cp.async.commit_group;")
#define CP_WAIT1()  asm volatile("cp.async.wait_group 1;")
#define CP_WAIT0()  asm volatile("cp.async.wait_group 0;")

#define LDSM4(r, addr) \
    asm volatile("ldmatrix.sync.aligned.m8n8.x4.shared.b16 {%0,%1,%2,%3}, [%4];" \
        : "=r"((r)[0]), "=r"((r)[1]), "=r"((r)[2]), "=r"((r)[3]) : "r"(addr))

#define MMA16816H(d, a, b0v, b1v) \
    asm volatile("mma.sync.aligned.m16n8k16.row.col.f32.f16.f16.f32 " \
        "{%0,%1,%2,%3}, {%4,%5,%6,%7}, {%8,%9}, {%0,%1,%2,%3};" \
        : "+f"((d)[0]), "+f"((d)[1]), "+f"((d)[2]), "+f"((d)[3]) \
        : "r"((a)[0]), "r"((a)[1]), "r"((a)[2]), "r"((a)[3]), "r"(b0v), "r"(b1v))

#define SW(o) ((o) ^ (((o) >> 3) & 0x70))

// ---------------- conversion kernels ----------------
__global__ void k_f2h(const float* __restrict__ w, __half* __restrict__ o, int n) {
    int i = blockIdx.x * 256 + threadIdx.x;
    if (i < n) o[i] = __float2half(w[i]);
}
__global__ void k_wconv_h(const float* __restrict__ w, __half* __restrict__ wc) {
    int i = blockIdx.x * 256 + threadIdx.x;     // 27*256*256
    int co = i / KCONV;
    int rem = i - co * KCONV;
    int tap = rem >> 8, ci = rem & 255;
    wc[i] = __float2half(w[(co * 256 + ci) * 27 + tap]);
}
__global__ void k_zero_b(uint32_t* __restrict__ p, int n) {
    int i = blockIdx.x * 256 + threadIdx.x;
    if (i < n) p[i] = 0u;
}
__global__ void k_vpadh(const float* __restrict__ lin, __half* __restrict__ hi) {
    const int n = blockIdx.x;
    const int c4 = threadIdx.x;     // 64
    const int x = n >> 10, y = (n >> 5) & 31, z = n & 31;
    const int p = ((x + 1) * 34 + (y + 1)) * 34 + (z + 1);
    float4 v = *(const float4*)&lin[(size_t)n * 768 + 512 + c4 * 4];
    __half2* hp = (__half2*)(hi + (size_t)p * 256 + c4 * 4);
    hp[0] = __floats2half2_rn(v.x, v.y);
    hp[1] = __floats2half2_rn(v.z, v.w);
}

// ---------------- conv GEMM: fp16 1-pass, K-chunk 64, 128B swizzled rows ----
#define TIL 8192
#define CTIL 16384
#define CBUF 32768
#define CSMEM_TOT (3 * CBUF)
#define FBUF 24576
#define FSMEM_TOT (3 * FBUF)

__global__ void __launch_bounds__(256, 2) gemm_conv_h(
    const __half* __restrict__ Ah, const __half* __restrict__ B,
    const float* __restrict__ bias, float* __restrict__ C)
{
    extern __shared__ char smem[];
    const uint32_t sb = smem_u32(smem);
    const int t = threadIdx.x;
    const int m0 = blockIdx.y * 128, n0 = blockIdx.x * 128;
    const int seg = t & 7, r0 = t >> 3;            // 8 segs x 32 rows
    const int wid = t >> 5, lane = t & 31;
    const int wy = wid >> 1, wx = wid & 1;
    const int lA_r = lane & 15, lA_k8 = (lane >> 4) & 1;
    const int lB_n = (lane & 7) + ((lane >> 4) & 1) * 8, lB_k8 = (lane >> 3) & 1;
    const int NC = KCONV >> 6;     // 108 chunks of 64

    float acc[2][8][4];
#pragma unroll
    for (int i = 0; i < 2; i++)
#pragma unroll
        for (int j = 0; j < 8; j++)
#pragma unroll
            for (int q = 0; q < 4; q++) acc[i][j][q] = 0.0f;

    auto prefetch = [&](int c) {
        const uint32_t bb = sb + (c % 3) * CBUF;
        const int kc = c * 64;
        const int tap = kc >> 8;
        const int ci0 = kc & 255;
        const int dx = tap / 9 - 1, dy = (tap / 3) % 3 - 1, dz = tap % 3 - 1;
#pragma unroll
        for (int i = 0; i < 4; i++) {
            const int r = r0 + i * 32;
            const uint32_t so = SW(r * 128 + seg * 16);
            const int m = m0 + r;
            const int x = m >> 10, y = (m >> 5) & 31, z = m & 31;
            const size_t aoff =
                (size_t)(((x + 1 + dx) * 34 + (y + 1 + dy)) * 34 + (z + 1 + dz)) * 256
                + ci0 + seg * 8;
            CP16(bb + so, Ah + aoff);
            const size_t boff = (size_t)(n0 + r) * KCONV + kc + seg * 8;
            CP16(bb + CTIL + so, B + boff);
        }
        CP_COMMIT();
    };

    prefetch(0);
    prefetch(1);
    for (int c = 0; c < NC; c++) {
        if (c + 1 < NC) CP_WAIT1(); else CP_WAIT0();
        __syncthreads();
        if (c + 2 < NC) prefetch(c + 2);
        const uint32_t bb = sb + (c % 3) * CBUF;
#pragma unroll
        for (int ks = 0; ks < 4; ks++) {
            const int chunk = ks * 32 + lA_k8 * 16;
            uint32_t ah[2][4];
#pragma unroll
            for (int mt = 0; mt < 2; mt++) {
                const uint32_t aaddr = bb + SW((wy * 32 + mt * 16 + lA_r) * 128 + chunk);
                LDSM4(ah[mt], aaddr);
            }
            const int bchunk = ks * 32 + lB_k8 * 16;
            uint32_t bf[4][4];
#pragma unroll
            for (int np = 0; np < 4; np++) {
                const uint32_t baddr = bb + CTIL + SW((wx * 64 + np * 16 + lB_n) * 128 + bchunk);
                LDSM4(bf[np], baddr);
            }
#pragma unroll
            for (int mt = 0; mt < 2; mt++)
#pragma unroll
                for (int nt = 0; nt < 8; nt++) {
                    const uint32_t* bp = &bf[nt >> 1][(nt & 1) * 2];
                    MMA16816H(acc[mt][nt], ah[mt], bp[0], bp[1]);
                }
        }
    }

    const int er = lane >> 2, ec = (lane & 3) * 2;
#pragma unroll
    for (int mt = 0; mt < 2; mt++) {
        const int row = m0 + wy * 32 + mt * 16 + er;
#pragma unroll
        for (int nt = 0; nt < 8; nt++) {
            const int col = n0 + wx * 64 + nt * 8 + ec;
            const float b0 = __ldg(&bias[col]), b1 = __ldg(&bias[col + 1]);
            float* cp0 = C + (size_t)row * 256 + col;
            float* cp1 = C + (size_t)(row + 8) * 256 + col;
            cp0[0] = acc[mt][nt][0] + b0;
            cp0[1] = acc[mt][nt][1] + b1;
            cp1[0] = acc[mt][nt][2] + b0;
            cp1[1] = acc[mt][nt][3] + b1;
        }
    }
}

// ---------------- fp32-A fp16 GEMM (npass = 1 or 2): qkv / proj ----------------
__global__ void __launch_bounds__(256, 2) gemm_fp16a(
    const float* __restrict__ A0, const float* __restrict__ A1,
    const __half* __restrict__ B,
    const float* __restrict__ bias, float* __restrict__ C, int ldc, int npass)
{
    extern __shared__ char smem[];
    const uint32_t sb = smem_u32(smem);
    const int t = threadIdx.x;
    const int m0 = blockIdx.y * 128, n0 = blockIdx.x * 128;
    const int seg = t & 3, r0 = t >> 2;
    const int wid = t >> 5, lane = t & 31;
    const int wy = wid >> 1, wx = wid & 1;
    const int lA_r = lane & 15, lA_k8 = (lane >> 4) & 1;
    const int lB_n = (lane & 7) + ((lane >> 4) & 1) * 8, lB_k8 = (lane >> 3) & 1;
    const int NC = 8;      // K = 256

    float acc[2][8][4];
#pragma unroll
    for (int i = 0; i < 2; i++)
#pragma unroll
        for (int j = 0; j < 8; j++)
#pragma unroll
            for (int q = 0; q < 4; q++) acc[i][j][q] = 0.0f;

    auto prefetch = [&](int c) {
        const uint32_t bb = sb + (c % 3) * FBUF;
        const int kc = c * 32;
#pragma unroll
        for (int i = 0; i < 2; i++) {
            const int r = r0 + i * 64;
            const uint32_t so = SW(r * 64 + seg * 16);
            const size_t boff = (size_t)(n0 + r) * 256 + kc + seg * 8;
            CP16(bb + 2 * TIL + so, B + boff);
            const size_t aoff = (size_t)(m0 + r) * 256 + kc + seg * 8;
            float4 p0 = *(const float4*)(A0 + aoff);
            float4 q0 = *(const float4*)(A0 + aoff + 4);
            float v[8] = {p0.x, p0.y, p0.z, p0.w, q0.x, q0.y, q0.z, q0.w};
            if (A1) {
                const float4 p1 = *(const float4*)(A1 + aoff);
                const float4 q1 = *(const float4*)(A1 + aoff + 4);
                v[0] += p1.x; v[1] += p1.y; v[2] += p1.z; v[3] += p1.w;
                v[4] += q1.x; v[5] += q1.y; v[6] += q1.z; v[7] += q1.w;
            }
            uint32_t hw[4];
#pragma unroll
            for (int j = 0; j < 4; j++) {
                __half2 hh = __floats2half2_rn(v[2 * j], v[2 * j + 1]);
                hw[j] = *(uint32_t*)&hh;
            }
            *(uint4*)(smem + (bb - sb) + so) = make_uint4(hw[0], hw[1], hw[2], hw[3]);
            if (npass == 2) {
                uint32_t lw[4];
#pragma unroll
                for (int j = 0; j < 4; j++) {
                    __half h0 = __float2half(v[2 * j]);
                    __half h1 = __float2half(v[2 * j + 1]);
                    __half2 ll = __halves2half2(
                        __float2half(v[2 * j] - __half2float(h0)),
                        __float2half(v[2 * j + 1] - __half2float(h1)));
                    lw[j] = *(uint32_t*)&ll;
                }
                *(uint4*)(smem + (bb - sb) + TIL + so) = make_uint4(lw[0], lw[1], lw[2], lw[3]);
            }
        }
        CP_COMMIT();
    };

    prefetch(0);
    prefetch(1);
    for (int c = 0; c < NC; c++) {
        if (c + 1 < NC) CP_WAIT1(); else CP_WAIT0();
        __syncthreads();
        if (c + 2 < NC) prefetch(c + 2);
        const uint32_t bb = sb + (c % 3) * FBUF;
#pragma unroll
        for (int ks = 0; ks < 2; ks++) {
            const int chunk = ks * 32 + lA_k8 * 16;
            uint32_t ah[2][4];
#pragma unroll
            for (int mt = 0; mt < 2; mt++) {
                const uint32_t aaddr = bb + SW((wy * 32 + mt * 16 + lA_r) * 64 + chunk);
                LDSM4(ah[mt], aaddr);
            }
            const int bchunk = ks * 32 + lB_k8 * 16;
            uint32_t bf[4][4];
#pragma unroll
            for (int np = 0; np < 4; np++) {
                const uint32_t baddr = bb + 2 * TIL + SW((wx * 64 + np * 16 + lB_n) * 64 + bchunk);
                LDSM4(bf[np], baddr);
            }
#pragma unroll
            for (int mt = 0; mt < 2; mt++)
#pragma unroll
                for (int nt = 0; nt < 8; nt++) {
                    const uint32_t* bp = &bf[nt >> 1][(nt & 1) * 2];
                    MMA16816H(acc[mt][nt], ah[mt], bp[0], bp[1]);
                }
            if (npass == 2) {
                uint32_t al[2][4];
#pragma unroll
                for (int mt = 0; mt < 2; mt++) {
                    const uint32_t aaddr = bb + SW((wy * 32 + mt * 16 + lA_r) * 64 + chunk);
                    LDSM4(al[mt], aaddr + TIL);
                }
#pragma unroll
                for (int mt = 0; mt < 2; mt++)
#pragma unroll
                    for (int nt = 0; nt < 8; nt++) {
                        const uint32_t* bp = &bf[nt >> 1][(nt & 1) * 2];
                        MMA16816H(acc[mt][nt], al[mt], bp[0], bp[1]);
                    }
            }
        }
    }

    const int er = lane >> 2, ec = (lane & 3) * 2;
#pragma unroll
    for (int mt = 0; mt < 2; mt++) {
        const int row = m0 + wy * 32 + mt * 16 + er;
#pragma unroll
        for (int nt = 0; nt < 8; nt++) {
            const int col = n0 + wx * 64 + nt * 8 + ec;
            const float b0 = __ldg(&bias[col]), b1 = __ldg(&bias[col + 1]);
            float* cp0 = C + (size_t)row * ldc + col;
            float* cp1 = C + (size_t)(row + 8) * ldc + col;
            cp0[0] = acc[mt][nt][0] + b0;
            cp0[1] = acc[mt][nt][1] + b1;
            cp1[0] = acc[mt][nt][2] + b0;
            cp1[1] = acc[mt][nt][3] + b1;
        }
    }
}

// ---------------- attention kernels ----------------
__global__ void k_pool(const float* __restrict__ lin, float* __restrict__ A) {
    const int a = blockIdx.x;
    const int c = threadIdx.x;
    const int p1 = a >> 4, p2 = (a >> 2) & 3, p3 = a & 3;
    const int csub = c >> 5;
    float s = 0.0f;
    for (int b1 = 0; b1 < 8; b1++) {
        const int f1 = p1 * 8 + b1;
        const int ch = (f1 >> 2) * 32 + (c & 31);
        const int nb1 = (f1 & 3) * 8192;
        for (int b2 = 0; b2 < 8; b2++) {
            const int nb2 = nb1 + (p2 * 8 + b2) * 256;
            for (int b3 = 0; b3 < 8; b3++) {
                const int n = nb2 + (p3 * 8 + b3) * 8 + csub;
                s += lin[(size_t)n * 768 + ch];
            }
        }
    }
    A[a * 256 + c] = s * (1.0f / 512.0f);
}

__global__ void __launch_bounds__(256) k_S(const float* __restrict__ lin,
                                           const float* __restrict__ Amat,
                                           __half* __restrict__ S) {
    const int h = blockIdx.y;
    const int n = blockIdx.x * 256 + threadIdx.x;
    __shared__ float4 As[64][8];
    for (int e = threadIdx.x; e < 512; e += 256) {
        int a = e >> 3, dq = e & 7;
        As[a][dq] = *(const float4*)&Amat[a * 256 + h * 32 + dq * 4];
    }
    __syncthreads();
    float4 kv[8];
    const float* kp = lin + (size_t)n * 768 + 256 + h * 32;
#pragma unroll
    for (int i = 0; i < 8; i++) kv[i] = *(const float4*)&kp[i * 4];
    const float scale = 0.17677669529663687f;
    __half* Sp = S + (size_t)(h * 64) * NTOK + n;
#pragma unroll 4
    for (int a = 0; a < 64; a++) {
        float s = 0.0f;
#pragma unroll
        for (int i = 0; i < 8; i++) {
            const float4 av = As[a][i];
            s += kv[i].x * av.x + kv[i].y * av.y + kv[i].z * av.z + kv[i].w * av.w;
        }
        Sp[(size_t)a * NTOK] = __float2half(fexp(s * scale));
    }
}

__global__ void __launch_bounds__(256) k_agentv(const float* __restrict__ lin,
                                                const __half* __restrict__ S,
                                                float* __restrict__ part,
                                                float* __restrict__ partl) {
    const int h = blockIdx.y;
    const int chunk = blockIdx.x;
    const int n0 = chunk * 512;
    __shared__ float Ss[64][68];
    __shared__ float vs[64][32];
    const int a = threadIdx.x >> 2, dg = threadIdx.x & 3;
    float4 acc0 = {0, 0, 0, 0}, acc1 = {0, 0, 0, 0};
    float accl = 0.0f;

    for (int sub = 0; sub < 8; sub++) {
        const int nb = n0 + sub * 64;
        for (int e = threadIdx.x; e < 512; e += 256) {
            int aa = e >> 3, tq = e & 7;
            uint4 raw = *(const uint4*)(S + (size_t)(h * 64 + aa) * NTOK + nb + tq * 8);
            const __half2* hp = (const __half2*)&raw;
            float2 f0 = __half22float2(hp[0]);
            float2 f1 = __half22float2(hp[1]);
            float2 f2 = __half22float2(hp[2]);
            float2 f3 = __half22float2(hp[3]);
            *(float4*)&Ss[aa][tq * 8]     = make_float4(f0.x, f0.y, f1.x, f1.y);
            *(float4*)&Ss[aa][tq * 8 + 4] = make_float4(f2.x, f2.y, f3.x, f3.y);
        }
        for (int e = threadIdx.x; e < 512; e += 256) {
            int tt = e >> 3, dq = e & 7;
            *(float4*)&vs[tt][dq * 4] =
                *(const float4*)&lin[(size_t)(nb + tt) * 768 + 512 + h * 32 + dq * 4];
        }
        __syncthreads();
#pragma unroll 8
        for (int tt = 0; tt < 64; tt++) {
            const float p = Ss[a][tt];
            accl += p;
            const float4 v0 = *(const float4*)&vs[tt][dg * 8];
            const float4 v1 = *(const float4*)&vs[tt][dg * 8 + 4];
            acc0.x += p * v0.x; acc0.y += p * v0.y; acc0.z += p * v0.z; acc0.w += p * v0.w;
            acc1.x += p * v1.x; acc1.y += p * v1.y; acc1.z += p * v1.z; acc1.w += p * v1.w;
        }
        __syncthreads();
    }
    float* pp = part + (size_t)((chunk * 8 + h) * 64 + a) * 32 + dg * 8;
    *(float4*)pp = acc0;
    *(float4*)(pp + 4) = acc1;
    if (dg == 0) partl[(chunk * 8 + h) * 64 + a] = accl;
}

__global__ void k_avreduce(const float* __restrict__ part, const float* __restrict__ partl,
                           float* __restrict__ av) {
    const int idx = blockIdx.x * 256 + threadIdx.x;      // 16384
    const int row = idx >> 5;                            // h*64+a
    float s = 0.0f, lsum = 0.0f;
    for (int ch = 0; ch < 64; ch++) {
        s += part[(size_t)ch * 16384 + idx];
        lsum += partl[ch * 512 + row];
    }
    av[idx] = s / lsum;
}

__global__ void __launch_bounds__(256) k_stage2(const float* __restrict__ lin,
                                                const float* __restrict__ Amat,
                                                const float* __restrict__ av,
                                                float* __restrict__ mid) {
    const int h = blockIdx.y;
    const int n = blockIdx.x * 256 + threadIdx.x;
    __shared__ float4 As[64][8];
    __shared__ float4 Vs[64][8];
    for (int e = threadIdx.x; e < 512; e += 256) {
        int a = e >> 3, dq = e & 7;
        As[a][dq] = *(const float4*)&Amat[a * 256 + h * 32 + dq * 4];
        Vs[a][dq] = *(const float4*)&av[(size_t)(h * 64 + a) * 32 + dq * 4];
    }
    __syncthreads();
    float4 qv[8];
    const float* qp = lin + (size_t)n * 768 + h * 32;
#pragma unroll
    for (int i = 0; i < 8; i++) qv[i] = *(const float4*)&qp[i * 4];
    const float scale = 0.17677669529663687f;
    float lg[64];
    float mx = -1e30f;
#pragma unroll
    for (int a = 0; a < 64; a++) {
        float s = 0.0f;
#pragma unroll
        for (int i = 0; i < 8; i++) {
            const float4 v = As[a][i];
            s += qv[i].x * v.x + qv[i].y * v.y + qv[i].z * v.z + qv[i].w * v.w;
        }
        s *= scale;
        lg[a] = s;
        mx = fmaxf(mx, s);
    }
    float sum = 0.0f;
#pragma unroll
    for (int a = 0; a < 64; a++) {
        const float p = fexp(lg[a] - mx);
        lg[a] = p;
        sum += p;
    }
    float4 o[8];
#pragma unroll
    for (int i = 0; i < 8; i++) { o[i].x = 0; o[i].y = 0; o[i].z = 0; o[i].w = 0; }
#pragma unroll
    for (int a = 0; a < 64; a++) {
        const float p = lg[a];
#pragma unroll
        for (int i = 0; i < 8; i++) {
            const float4 v = Vs[a][i];
            o[i].x += p * v.x; o[i].y += p * v.y; o[i].z += p * v.z; o[i].w += p * v.w;
        }
    }
    const float inv = 1.0f / sum;
    float* mp = mid + (size_t)h * 1048576 + n;
#pragma unroll
    for (int i = 0; i < 8; i++) {
        mp[(size_t)(i * 4 + 0) * NTOK] = o[i].x * inv;
        mp[(size_t)(i * 4 + 1) * NTOK] = o[i].y * inv;
        mp[(size_t)(i * 4 + 2) * NTOK] = o[i].z * inv;
        mp[(size_t)(i * 4 + 3) * NTOK] = o[i].w * inv;
    }
}

// ---------------- launch ----------------
extern "C" void kernel_launch(void* const* d_in, const int* in_sizes, int n_in,
                              void* d_out, int out_size) {
    const float* x      = (const float*)d_in[0];
    const float* w_qkv  = (const float*)d_in[1];
    const float* b_qkv  = (const float*)d_in[2];
    const float* w_proj = (const float*)d_in[3];
    const float* b_proj = (const float*)d_in[4];
    const float* w_dwc  = (const float*)d_in[5];
    const float* b_dwc  = (const float*)d_in[6];
    float* out = (float*)d_out;

    float *lin, *A, *avpart, *partl, *av, *mid, *convout;
    __half *S, *vph, *wc, *wq16, *wp16;
    cudaGetSymbolAddress((void**)&lin,     g_lin);
    cudaGetSymbolAddress((void**)&S,       g_S);
    cudaGetSymbolAddress((void**)&A,       g_A);
    cudaGetSymbolAddress((void**)&avpart,  g_avpart);
    cudaGetSymbolAddress((void**)&partl,   g_partl);
    cudaGetSymbolAddress((void**)&av,      g_av);
    cudaGetSymbolAddress((void**)&mid,     g_mid);
    cudaGetSymbolAddress((void**)&convout, g_conv);
    cudaGetSymbolAddress((void**)&vph,     g_vph);
    cudaGetSymbolAddress((void**)&wc,      g_wc);
    cudaGetSymbolAddress((void**)&wq16,    g_wq16);
    cudaGetSymbolAddress((void**)&wp16,    g_wp16);

    cudaFuncSetAttribute(gemm_conv_h, cudaFuncAttributeMaxDynamicSharedMemorySize, CSMEM_TOT);
    cudaFuncSetAttribute(gemm_fp16a,  cudaFuncAttributeMaxDynamicSharedMemorySize, FSMEM_TOT);

    cudaStream_t side;
    cudaStreamCreateWithFlags(&side, cudaStreamNonBlocking);
    cudaEvent_t evLin, evConv;
    cudaEventCreateWithFlags(&evLin,  cudaEventDisableTiming);
    cudaEventCreateWithFlags(&evConv, cudaEventDisableTiming);

    // ---- side stream: weight prep starts at t=0 ----
    k_f2h<<<(256 * 256 + 255) / 256, 256, 0, side>>>(w_proj, wp16, 256 * 256);
    k_wconv_h<<<(27 * 256 * 256) / 256, 256, 0, side>>>(w_dwc, wc);
    k_zero_b<<<(PVOL * CDIM / 2 + 255) / 256, 256, 0, side>>>((uint32_t*)vph, PVOL * CDIM / 2);

    // ---- main stream: w_qkv convert + qkv GEMM (fp16 1-pass) ----
    k_f2h<<<(768 * 256 + 255) / 256, 256>>>(w_qkv, wq16, 768 * 256);
    gemm_fp16a<<<dim3(6, 256), 256, FSMEM_TOT>>>(x, (const float*)nullptr,
                                                 wq16, b_qkv, lin, 768, 1);
    cudaEventRecord(evLin, 0);

    // ---- side stream: conv pipeline after lin ready ----
    cudaStreamWaitEvent(side, evLin, 0);
    k_vpadh<<<NTOK, 64, 0, side>>>(lin, vph);
    gemm_conv_h<<<dim3(2, 256), 256, CSMEM_TOT, side>>>(vph, wc, b_dwc, convout);
    cudaEventRecord(evConv, side);

    // ---- main stream: attention chain (concurrent with conv) ----
    k_pool<<<64, 256>>>(lin, A);
    k_S<<<dim3(128, 8), 256>>>(lin, A, S);
    k_agentv<<<dim3(64, 8), 256>>>(lin, S, avpart, partl);
    k_avreduce<<<64, 256>>>(avpart, partl, av);
    k_stage2<<<dim3(128, 8), 256>>>(lin, A, av, mid);

    // ---- join: proj GEMM (fp16 1-pass) reads mid + convout ----
    cudaStreamWaitEvent(0, evConv, 0);
    gemm_fp16a<<<dim3(2, 256), 256, FSMEM_TOT>>>(mid, convout, wp16, b_proj, out, 256, 1);
}